// round 2
// baseline (speedup 1.0000x reference)
#include <cuda_runtime.h>
#include <cuda_bf16.h>
#include <math.h>
#include <stdint.h>

// ---------------- problem constants ----------------
#define BATCH   128
#define OBS_H   2
#define NTOK    291            // 2*(144+1)+1
#define M_TOK   (BATCH*NTOK)   // 37248 = 291 * 128
#define D_EMB   384
#define NHEAD   6
#define HDIM    64
#define NLAYER  12
#define N_IMG   144
#define PK      192            // 8*8*3 patch features
#define M_PATCH (BATCH*OBS_H*N_IMG)   // 36864 = 288*128

// ---------------- scratch ----------------
__device__ float g_x  [M_TOK * D_EMB];
__device__ float g_y  [M_TOK * D_EMB];
__device__ float g_big[M_TOK * 1536];
__device__ float g_att[M_TOK * D_EMB];
__device__ float g_st [BATCH * OBS_H * D_EMB];

__device__ __forceinline__ float gelu_tanh(float v) {
    const float c = 0.7978845608028654f;
    float u = c * (v + 0.044715f * v * v * v);
    return 0.5f * v * (1.0f + tanhf(u));
}

// =======================================================================
// bf16 3-pass split-precision GEMM on tensor cores (mma.sync m16n8k16)
// C[M,N] = A[M,K] @ W[K,N] (+bias / +gelu / +residual)
// BM=128 BN=128 BK=16. 256 threads = 8 warps in 2(M) x 4(N) grid,
// warp tile 64x32 = 4 m16-tiles x 4 n8-tiles.
// A and B are split on load: x = hi(bf16) + lo(bf16); 3 mma passes:
// ah*bh + ah*bl + al*bh  (al*bl dropped, ~2^-18 relative).
// smem holds fragments PRE-PERMUTED so each frag = one LDS.128 / LDS.64.
// =======================================================================

__device__ __forceinline__ void mma16816(float c[4], const uint32_t a[4], const uint32_t b[2]) {
    asm volatile(
        "mma.sync.aligned.m16n8k16.row.col.f32.bf16.bf16.f32 "
        "{%0,%1,%2,%3}, {%4,%5,%6,%7}, {%8,%9}, {%0,%1,%2,%3};\n"
        : "+f"(c[0]), "+f"(c[1]), "+f"(c[2]), "+f"(c[3])
        : "r"(a[0]), "r"(a[1]), "r"(a[2]), "r"(a[3]), "r"(b[0]), "r"(b[1]));
}

__device__ __forceinline__ uint32_t pack_hi(float x0, float x1) {
    __nv_bfloat162 h;
    h.x = __float2bfloat16_rn(x0);
    h.y = __float2bfloat16_rn(x1);
    return *(uint32_t*)&h;
}
__device__ __forceinline__ uint32_t pack_lo(float x0, float x1, uint32_t hi) {
    __nv_bfloat162 h = *(__nv_bfloat162*)&hi;
    __nv_bfloat162 l;
    l.x = __float2bfloat16_rn(x0 - __bfloat162float(h.x));
    l.y = __float2bfloat16_rn(x1 - __bfloat162float(h.y));
    return *(uint32_t*)&l;
}

template <int EPI>   // 0: +bias   1: +bias,gelu   2: +bias,+residual
__global__ void __launch_bounds__(256, 2) gemm3p(
    const float* __restrict__ A, const float* __restrict__ W,
    const float* __restrict__ bias, const float* __restrict__ R,
    float* __restrict__ C, int N, int K)
{
    // fragment-order smem: A: [8 mtiles][32 lanes][4 regs], B: [16 ntiles][32 lanes][2 regs]
    __shared__ __align__(16) uint32_t As_hi[8 * 32 * 4];
    __shared__ __align__(16) uint32_t As_lo[8 * 32 * 4];
    __shared__ __align__(16) uint32_t Bs_hi[16 * 32 * 2];
    __shared__ __align__(16) uint32_t Bs_lo[16 * 32 * 2];

    const int tid  = threadIdx.x;
    const int lane = tid & 31;
    const int warp = tid >> 5;
    const int wm = warp >> 2, wn = warp & 3;
    const int bm = blockIdx.y, bn = blockIdx.x;

    float acc[4][4][4];
#pragma unroll
    for (int i = 0; i < 4; i++)
#pragma unroll
        for (int j = 0; j < 4; j++)
#pragma unroll
            for (int q = 0; q < 4; q++) acc[i][j][q] = 0.f;

    // --- writer indices (A): thread covers row r, cols c0..c0+7 of the tile
    const int ar = tid >> 1;
    const int ac0 = (tid & 1) * 8;
    const int amt = ar >> 4;
    const int arr = ar & 15;
    const int ag  = arr & 7;
    const int areg_base = (arr >= 8 ? 1 : 0) | (ac0 >= 8 ? 2 : 0);
    const float* Aptr = A + (size_t)(bm * 128 + ar) * K + ac0;

    // --- writer indices (B): thread covers k-pair (2kp,2kp+1), cols n0..n0+3
    const int bkp = tid >> 5;            // 0..7
    const int bn0 = (tid & 31) * 4;      // 0..124
    const int bnt = bn0 >> 3;
    const int breg = bkp >> 2;
    const int bt = bkp & 3;
    const float* Bptr = W + (size_t)(2 * bkp) * N + bn * 128 + bn0;

    for (int kt = 0; kt < K; kt += 16) {
        // ---- load + split A tile ----
        {
            float4 v0 = *(const float4*)(Aptr + kt);
            float4 v1 = *(const float4*)(Aptr + kt + 4);
            float xs[8] = {v0.x, v0.y, v0.z, v0.w, v1.x, v1.y, v1.z, v1.w};
#pragma unroll
            for (int p = 0; p < 4; p++) {
                uint32_t hi = pack_hi(xs[2 * p], xs[2 * p + 1]);
                uint32_t lo = pack_lo(xs[2 * p], xs[2 * p + 1], hi);
                int idx = ((amt * 32) + (ag * 4 + p)) * 4 + areg_base;
                As_hi[idx] = hi;
                As_lo[idx] = lo;
            }
        }
        // ---- load + split B tile ----
        {
            const float* bp = Bptr + (size_t)kt * N;
            float4 r0 = *(const float4*)(bp);
            float4 r1 = *(const float4*)(bp + N);
            float e0[4] = {r0.x, r0.y, r0.z, r0.w};
            float e1[4] = {r1.x, r1.y, r1.z, r1.w};
#pragma unroll
            for (int j = 0; j < 4; j++) {
                uint32_t hi = pack_hi(e0[j], e1[j]);
                uint32_t lo = pack_lo(e0[j], e1[j], hi);
                int g = ((tid & 1) * 4 + j);
                int idx = ((bnt * 32) + (g * 4 + bt)) * 2 + breg;
                Bs_hi[idx] = hi;
                Bs_lo[idx] = lo;
            }
        }
        __syncthreads();

        // ---- fragments + mma ----
        uint32_t Bh[4][2], Bl[4][2];
#pragma unroll
        for (int j = 0; j < 4; j++) {
            int nt = wn * 4 + j;
            uint2 h = ((const uint2*)Bs_hi)[nt * 32 + lane];
            uint2 l = ((const uint2*)Bs_lo)[nt * 32 + lane];
            Bh[j][0] = h.x; Bh[j][1] = h.y;
            Bl[j][0] = l.x; Bl[j][1] = l.y;
        }
#pragma unroll
        for (int i = 0; i < 4; i++) {
            int mt = wm * 4 + i;
            uint4 h4 = ((const uint4*)As_hi)[mt * 32 + lane];
            uint4 l4 = ((const uint4*)As_lo)[mt * 32 + lane];
            uint32_t Ah[4] = {h4.x, h4.y, h4.z, h4.w};
            uint32_t Al[4] = {l4.x, l4.y, l4.z, l4.w};
#pragma unroll
            for (int j = 0; j < 4; j++) {
                mma16816(acc[i][j], Ah, Bh[j]);
                mma16816(acc[i][j], Ah, Bl[j]);
                mma16816(acc[i][j], Al, Bh[j]);
            }
        }
        __syncthreads();
    }

    // ---- epilogue ----
#pragma unroll
    for (int i = 0; i < 4; i++) {
        int row0 = bm * 128 + (wm * 4 + i) * 16 + (lane >> 2);
#pragma unroll
        for (int j = 0; j < 4; j++) {
            int col = bn * 128 + (wn * 4 + j) * 8 + (lane & 3) * 2;
            float b0 = bias[col], b1 = bias[col + 1];
#pragma unroll
            for (int half = 0; half < 2; half++) {
                int row = row0 + half * 8;
                size_t off = (size_t)row * N + col;
                float v0 = acc[i][j][half * 2 + 0] + b0;
                float v1 = acc[i][j][half * 2 + 1] + b1;
                if (EPI == 1) { v0 = gelu_tanh(v0); v1 = gelu_tanh(v1); }
                if (EPI == 2) { v0 += R[off]; v1 += R[off + 1]; }
                *(float2*)(C + off) = make_float2(v0, v1);
            }
        }
    }
}

// ---------------- LayerNorm ----------------
__device__ __forceinline__ void ln_row(const float* __restrict__ xr,
                                       const float* __restrict__ w,
                                       const float* __restrict__ b,
                                       float* __restrict__ yr)
{
    int tid = threadIdx.x;
    float v0 = xr[tid], v1 = xr[tid + 128], v2 = xr[tid + 256];
    float s = v0 + v1 + v2;
    float sq = v0 * v0 + v1 * v1 + v2 * v2;
#pragma unroll
    for (int o = 16; o; o >>= 1) {
        s  += __shfl_xor_sync(~0u, s,  o);
        sq += __shfl_xor_sync(~0u, sq, o);
    }
    __shared__ float ws[4], wq[4], red[2];
    int warp = tid >> 5, lane = tid & 31;
    if (!lane) { ws[warp] = s; wq[warp] = sq; }
    __syncthreads();
    if (tid == 0) {
        float S = ws[0] + ws[1] + ws[2] + ws[3];
        float Q = wq[0] + wq[1] + wq[2] + wq[3];
        float mean = S * (1.0f / 384.0f);
        red[0] = mean;
        red[1] = rsqrtf(Q * (1.0f / 384.0f) - mean * mean + 1e-5f);
    }
    __syncthreads();
    float mean = red[0], inv = red[1];
    yr[tid]       = (v0 - mean) * inv * w[tid]       + b[tid];
    yr[tid + 128] = (v1 - mean) * inv * w[tid + 128] + b[tid + 128];
    yr[tid + 256] = (v2 - mean) * inv * w[tid + 256] + b[tid + 256];
}

__global__ void ln_kernel(const float* __restrict__ x, const float* __restrict__ w,
                          const float* __restrict__ b, float* __restrict__ y)
{
    size_t row = blockIdx.x;
    ln_row(x + row * D_EMB, w, b, y + row * D_EMB);
}

__global__ void lnf_kernel(const float* __restrict__ x, const float* __restrict__ w,
                           const float* __restrict__ b, float* __restrict__ out)
{
    size_t bi = blockIdx.x;
    ln_row(x + (bi * NTOK + (NTOK - 1)) * D_EMB, w, b, out + bi * D_EMB);
}

// ---------------- Attention (unchanged; known-good) ----------------
#define ATT_SMEM_FLOATS (291*65*2 + 8*292 + 8*64)
#define ATT_SMEM_BYTES  (ATT_SMEM_FLOATS * 4)

__global__ void __launch_bounds__(256) attn_kernel(const float* __restrict__ qkv,
                                                   float* __restrict__ out)
{
    extern __shared__ float sm[];
    float* Ks = sm;
    float* Vs = sm + 291 * 65;
    float* Ps = sm + 291 * 65 * 2;
    float* Qs = Ps + 8 * 292;

    int bh = blockIdx.x;
    int b = bh / NHEAD, h = bh % NHEAD;
    int tid = threadIdx.x, warp = tid >> 5, lane = tid & 31;
    const size_t base = (size_t)b * NTOK * 1152 + h * 64;

    for (int idx = tid; idx < NTOK * 64; idx += 256) {
        int j = idx >> 6, d = idx & 63;
        Ks[j * 65 + d] = qkv[base + (size_t)j * 1152 + 384 + d];
        Vs[j * 65 + d] = qkv[base + (size_t)j * 1152 + 768 + d];
    }
    __syncthreads();

    const float scale = rsqrtf(64.0f + 1e-8f);

    for (int t = warp; t < NTOK; t += 8) {
        __syncwarp();
        float* outr = out + ((size_t)b * NTOK + t) * D_EMB + h * 64;
        if (t == NTOK - 1) {
            outr[lane]      = Vs[(NTOK - 1) * 65 + lane];
            outr[lane + 32] = Vs[(NTOK - 1) * 65 + lane + 32];
            continue;
        }
        const float* qr = qkv + base + (size_t)t * 1152;
        Qs[warp * 64 + lane]      = qr[lane];
        Qs[warp * 64 + lane + 32] = qr[lane + 32];
        __syncwarp();

        float s[10];
#pragma unroll
        for (int jc = 0; jc < 10; jc++) {
            int j = jc * 32 + lane;
            if (j < NTOK) {
                const float* kr = Ks + j * 65;
                const float* qs = Qs + warp * 64;
                float a = 0.f;
#pragma unroll
                for (int d = 0; d < 64; d++) a = fmaf(qs[d], kr[d], a);
                s[jc] = a * scale;
            } else s[jc] = -1e30f;
        }
        float m = s[0];
#pragma unroll
        for (int jc = 1; jc < 10; jc++) m = fmaxf(m, s[jc]);
#pragma unroll
        for (int o = 16; o; o >>= 1) m = fmaxf(m, __shfl_xor_sync(~0u, m, o));
        float sum = 0.f;
#pragma unroll
        for (int jc = 0; jc < 10; jc++) { s[jc] = expf(s[jc] - m); sum += s[jc]; }
#pragma unroll
        for (int o = 16; o; o >>= 1) sum += __shfl_xor_sync(~0u, sum, o);
        float inv = 1.0f / sum;
#pragma unroll
        for (int jc = 0; jc < 10; jc++) {
            int j = jc * 32 + lane;
            if (j < NTOK) Ps[warp * 292 + j] = s[jc];
        }
        __syncwarp();

        float o0 = 0.f, o1 = 0.f;
        const float* pp = Ps + warp * 292;
        for (int j = 0; j < NTOK; j++) {
            float pv = pp[j];
            o0 = fmaf(pv, Vs[j * 65 + lane],      o0);
            o1 = fmaf(pv, Vs[j * 65 + lane + 32], o1);
        }
        outr[lane]      = o0 * inv;
        outr[lane + 32] = o1 * inv;
    }
}

// ---------------- tokenizers ----------------
__global__ void st_kernel(const float* __restrict__ as, const float* __restrict__ w1,
                          const float* __restrict__ b1, const float* __restrict__ w2,
                          const float* __restrict__ b2, float* __restrict__ st)
{
    __shared__ float h1[32];
    int bt = blockIdx.x;
    int tid = threadIdx.x;
    float s0 = as[bt * 2], s1 = as[bt * 2 + 1];
    if (tid < 32) {
        float v = b1[tid] + s0 * w1[tid] + s1 * w1[32 + tid];
        h1[tid] = v > 0.f ? v : 0.f;
    }
    __syncthreads();
    float acc = b2[tid];
#pragma unroll
    for (int k = 0; k < 32; k++) acc = fmaf(h1[k], w2[k * 384 + tid], acc);
    st[(size_t)bt * 384 + tid] = acc;
}

__global__ void im2col_kernel(const float* __restrict__ img, float* __restrict__ patch)
{
    int idx = blockIdx.x * 256 + threadIdx.x;
    int f = idx % 192;
    int rem = idx / 192;
    int pidx = rem % 144;
    int bt = rem / 144;
    int pr = f / 24, pc = (f % 24) / 3, c = f % 3;
    int hp = pidx / 12, wp = pidx % 12;
    patch[idx] = img[(((size_t)bt * 3 + c) * 96 + hp * 8 + pr) * 96 + wp * 8 + pc];
}

__global__ void assemble_kernel(const float* __restrict__ imgtok, const float* __restrict__ st,
                                const float* __restrict__ readout, const float* __restrict__ pos,
                                const float* __restrict__ img_temb, const float* __restrict__ st_temb,
                                float* __restrict__ x)
{
    int idx = blockIdx.x * 256 + threadIdx.x;
    int d = idx % 384;
    int rem = idx / 384;
    int tok = rem % NTOK;
    int b = rem / NTOK;
    float v;
    if (tok == NTOK - 1) {
        v = readout[d];
    } else {
        int t = tok / 145, r = tok % 145;
        if (r == 0) v = st[((size_t)(b * 2 + t)) * 384 + d] + st_temb[t * 384 + d];
        else        v = imgtok[((size_t)(b * 2 + t) * 144 + (r - 1)) * 384 + d] + img_temb[t * 384 + d];
    }
    x[idx] = v + pos[tok * 384 + d];
}

// ---------------- launch ----------------
extern "C" void kernel_launch(void* const* d_in, const int* in_sizes, int n_in,
                              void* d_out, int out_size)
{
    const float* images      = (const float*)d_in[0];
    const float* agent_state = (const float*)d_in[1];
    const float* img_proj_w  = (const float*)d_in[2];
    const float* img_proj_b  = (const float*)d_in[3];
    const float* img_temb    = (const float*)d_in[4];
    const float* st_w1       = (const float*)d_in[5];
    const float* st_b1       = (const float*)d_in[6];
    const float* st_w2       = (const float*)d_in[7];
    const float* st_b2       = (const float*)d_in[8];
    const float* st_temb     = (const float*)d_in[9];
    const float* readout     = (const float*)d_in[10];
    const float* pos         = (const float*)d_in[11];
    const float* ln1_w       = (const float*)d_in[12];
    const float* ln1_b       = (const float*)d_in[13];
    const float* attn_w      = (const float*)d_in[14];
    const float* attn_b      = (const float*)d_in[15];
    const float* proj_w      = (const float*)d_in[16];
    const float* proj_b      = (const float*)d_in[17];
    const float* ln2_w       = (const float*)d_in[18];
    const float* ln2_b       = (const float*)d_in[19];
    const float* fc_w        = (const float*)d_in[20];
    const float* fc_b        = (const float*)d_in[21];
    const float* fc2_w       = (const float*)d_in[22];
    const float* fc2_b       = (const float*)d_in[23];
    const float* lnf_w       = (const float*)d_in[24];
    const float* lnf_b       = (const float*)d_in[25];
    float* out = (float*)d_out;

    float *x, *y, *big, *att, *st;
    cudaGetSymbolAddress((void**)&x,   g_x);
    cudaGetSymbolAddress((void**)&y,   g_y);
    cudaGetSymbolAddress((void**)&big, g_big);
    cudaGetSymbolAddress((void**)&att, g_att);
    cudaGetSymbolAddress((void**)&st,  g_st);

    cudaFuncSetAttribute(attn_kernel, cudaFuncAttributeMaxDynamicSharedMemorySize, ATT_SMEM_BYTES);

    // ---- tokenizers ----
    st_kernel<<<BATCH * OBS_H, 384>>>(agent_state, st_w1, st_b1, st_w2, st_b2, st);
    im2col_kernel<<<(M_PATCH * PK) / 256, 256>>>(images, y);
    gemm3p<0><<<dim3(3, M_PATCH / 128), 256>>>(y, img_proj_w, img_proj_b, nullptr, att, 384, PK);
    assemble_kernel<<<(M_TOK * D_EMB) / 256, 256>>>(att, st, readout, pos, img_temb, st_temb, x);

    // ---- transformer layers ----
    for (int l = 0; l < NLAYER; l++) {
        ln_kernel<<<M_TOK, 128>>>(x, ln1_w + l * 384, ln1_b + l * 384, y);
        gemm3p<0><<<dim3(9, NTOK), 256>>>(y, attn_w + (size_t)l * 384 * 1152,
                                          attn_b + l * 1152, nullptr, big, 1152, 384);
        attn_kernel<<<BATCH * NHEAD, 256, ATT_SMEM_BYTES>>>(big, att);
        gemm3p<2><<<dim3(3, NTOK), 256>>>(att, proj_w + (size_t)l * 384 * 384,
                                          proj_b + l * 384, x, x, 384, 384);
        ln_kernel<<<M_TOK, 128>>>(x, ln2_w + l * 384, ln2_b + l * 384, y);
        gemm3p<1><<<dim3(12, NTOK), 256>>>(y, fc_w + (size_t)l * 384 * 1536,
                                           fc_b + l * 1536, nullptr, big, 1536, 384);
        gemm3p<2><<<dim3(3, NTOK), 256>>>(big, fc2_w + (size_t)l * 1536 * 384,
                                          fc2_b + l * 384, x, x, 384, 1536);
    }

    lnf_kernel<<<BATCH, 128>>>(x, lnf_w, lnf_b, out);
}

// round 4
// speedup vs baseline: 1.7478x; 1.7478x over previous
#include <cuda_runtime.h>
#include <cuda_bf16.h>
#include <math.h>
#include <stdint.h>

// ---------------- problem constants ----------------
#define BATCH   128
#define OBS_H   2
#define NTOK    291
#define M_TOK   (BATCH*NTOK)   // 37248 = 291*128
#define D_EMB   384
#define NHEAD   6
#define NLAYER  12
#define N_IMG   144
#define PK      192
#define M_PATCH (BATCH*OBS_H*N_IMG)   // 36864 = 288*128

// ---------------- scratch ----------------
__device__ float g_x  [M_TOK * D_EMB];
__device__ float g_big[M_TOK * 1536];          // qkv fp32
__device__ float g_att[M_PATCH * D_EMB];       // img tokens fp32
__device__ float g_st [BATCH * OBS_H * D_EMB];
__device__ __nv_bfloat16 g_yh[M_TOK*384],  g_yl[M_TOK*384];
__device__ __nv_bfloat16 g_ah[M_TOK*384],  g_al[M_TOK*384];
__device__ __nv_bfloat16 g_bh[M_TOK*1536], g_bl[M_TOK*1536];
__device__ __nv_bfloat16 g_ph[M_PATCH*192],g_pl[M_PATCH*192];
// transposed+split weights  [N,K] bf16 hi/lo
__device__ __nv_bfloat16 g_wqh[12*1152*384], g_wql[12*1152*384];
__device__ __nv_bfloat16 g_wph[12*384*384],  g_wpl[12*384*384];
__device__ __nv_bfloat16 g_w1h[12*1536*384], g_w1l[12*1536*384];
__device__ __nv_bfloat16 g_w2h[12*384*1536], g_w2l[12*384*1536];
__device__ __nv_bfloat16 g_wih[384*192],     g_wil[384*192];

__device__ __forceinline__ float gelu_tanh(float v) {
    const float c = 0.7978845608028654f;
    float u = c * (v + 0.044715f * v * v * v);
    return 0.5f * v * (1.0f + tanhf(u));
}

__device__ __forceinline__ uint32_t smem_u32(const void* p) {
    uint32_t a;
    asm("{ .reg .u64 t; cvta.to.shared.u64 t, %1; cvt.u32.u64 %0, t; }" : "=r"(a) : "l"(p));
    return a;
}

__device__ __forceinline__ void mma16816(float c[4], const uint32_t a[4], const uint32_t b[2]) {
    asm volatile(
        "mma.sync.aligned.m16n8k16.row.col.f32.bf16.bf16.f32 "
        "{%0,%1,%2,%3}, {%4,%5,%6,%7}, {%8,%9}, {%0,%1,%2,%3};\n"
        : "+f"(c[0]), "+f"(c[1]), "+f"(c[2]), "+f"(c[3])
        : "r"(a[0]), "r"(a[1]), "r"(a[2]), "r"(a[3]), "r"(b[0]), "r"(b[1]));
}
#define LDMX4(r0, r1, r2, r3, addr) \
    asm volatile("ldmatrix.sync.aligned.m8n8.x4.shared.b16 {%0,%1,%2,%3}, [%4];" \
        : "=r"(r0), "=r"(r1), "=r"(r2), "=r"(r3) : "r"(addr))

// =======================================================================
// HMMA GEMM: C[M,N] = A @ W^T'.  A bf16 hi/lo [M,K], B bf16 hi/lo [N,K].
// BM=BN=128, BK=32, 256 thr = 8 warps (2m x 4n), warp tile 64x32.
// 3-pass split: Ah*Bh + Ah*Bl + Al*Bh. cp.async double-buffered.
// smem stage: Ah|Al|Bh|Bl, each 128 rows x 80B (40 bf16, 32 used).
// EPI: 0 +bias->f32 | 2 +bias+res->f32 | 3 +bias,gelu->bf16 hi/lo
// =======================================================================
#define STAGE_B   40960              // 4 * 128*80
#define GSMEM     (2*STAGE_B)        // 81920

template <int EPI>
__global__ void __launch_bounds__(256, 2) gemm_mma(
    const __nv_bfloat16* __restrict__ Ah, const __nv_bfloat16* __restrict__ Al,
    const __nv_bfloat16* __restrict__ Bh, const __nv_bfloat16* __restrict__ Bl,
    const float* __restrict__ bias, const float* __restrict__ Rres,
    float* __restrict__ C, __nv_bfloat16* __restrict__ Ch, __nv_bfloat16* __restrict__ Cl,
    int N, int K)
{
    extern __shared__ __align__(16) char dyn[];
    const uint32_t sbase = smem_u32(dyn);
    const int tid = threadIdx.x, lane = tid & 31, warp = tid >> 5;
    const int wm = warp >> 2, wn = warp & 3;
    const int bn = blockIdx.x, bm = blockIdx.y;

    float acc[4][4][4];
#pragma unroll
    for (int i = 0; i < 4; i++)
#pragma unroll
        for (int j = 0; j < 4; j++)
#pragma unroll
            for (int q = 0; q < 4; q++) acc[i][j][q] = 0.f;

    const char* gsrc[4] = {
        (const char*)(Ah + (size_t)bm * 128 * K), (const char*)(Al + (size_t)bm * 128 * K),
        (const char*)(Bh + (size_t)bn * 128 * K), (const char*)(Bl + (size_t)bn * 128 * K) };
    const size_t rs = (size_t)K * 2;

#define LOADT(t_) do { \
    uint32_t db_ = sbase + ((t_) & 1) * STAGE_B; \
    size_t go_ = (size_t)(t_) * 64; \
    _Pragma("unroll") \
    for (int b_ = 0; b_ < 4; b_++) { \
        const char* g_ = gsrc[b_]; \
        uint32_t d_ = db_ + b_ * 10240; \
        _Pragma("unroll") \
        for (int i_ = 0; i_ < 2; i_++) { \
            int idx_ = i_ * 256 + tid; \
            int r_ = idx_ >> 2, c_ = (idx_ & 3) * 16; \
            asm volatile("cp.async.cg.shared.global [%0], [%1], 16;" \
                :: "r"(d_ + r_ * 80 + c_), "l"(g_ + (size_t)r_ * rs + go_ + c_) : "memory"); \
        } \
    } \
    asm volatile("cp.async.commit_group;" ::: "memory"); \
} while (0)

    const int T = K >> 5;
    LOADT(0);
    if (T > 1) LOADT(1);

    for (int t = 0; t < T; t++) {
        if (t + 1 < T) asm volatile("cp.async.wait_group 1;" ::: "memory");
        else           asm volatile("cp.async.wait_group 0;" ::: "memory");
        __syncthreads();
        const uint32_t sb = sbase + (t & 1) * STAGE_B;

#pragma unroll
        for (int ks = 0; ks < 2; ks++) {
            const int k0 = ks * 16;
            uint32_t bh[4][2], bl[4][2];
#pragma unroll
            for (int pr = 0; pr < 2; pr++) {
                int trow = wn * 32 + pr * 16 + ((lane >> 4) & 1) * 8 + (lane & 7);
                int tcol = k0 + ((lane >> 3) & 1) * 8;
                uint32_t ab = sb + 20480 + trow * 80 + tcol * 2;
                LDMX4(bh[2*pr][0], bh[2*pr][1], bh[2*pr+1][0], bh[2*pr+1][1], ab);
                LDMX4(bl[2*pr][0], bl[2*pr][1], bl[2*pr+1][0], bl[2*pr+1][1], ab + 10240);
            }
#pragma unroll
            for (int i = 0; i < 4; i++) {
                int arow = wm * 64 + i * 16 + (lane & 7) + ((lane >> 3) & 1) * 8;
                int acol = k0 + ((lane >> 4) & 1) * 8;
                uint32_t aa = sb + arow * 80 + acol * 2;
                uint32_t ah4[4], al4[4];
                LDMX4(ah4[0], ah4[1], ah4[2], ah4[3], aa);
                LDMX4(al4[0], al4[1], al4[2], al4[3], aa + 10240);
#pragma unroll
                for (int j = 0; j < 4; j++) {
                    mma16816(acc[i][j], ah4, bh[j]);
                    mma16816(acc[i][j], ah4, bl[j]);
                    mma16816(acc[i][j], al4, bh[j]);
                }
            }
        }
        __syncthreads();
        if (t + 2 < T) LOADT(t + 2);
    }

    // ---- epilogue ----
#pragma unroll
    for (int i = 0; i < 4; i++) {
        int row0 = bm * 128 + wm * 64 + i * 16 + (lane >> 2);
#pragma unroll
        for (int j = 0; j < 4; j++) {
            int col = bn * 128 + wn * 32 + j * 8 + (lane & 3) * 2;
            float b0 = bias[col], b1 = bias[col + 1];
#pragma unroll
            for (int half = 0; half < 2; half++) {
                int row = row0 + half * 8;
                size_t off = (size_t)row * N + col;
                float v0 = acc[i][j][half * 2 + 0] + b0;
                float v1 = acc[i][j][half * 2 + 1] + b1;
                if (EPI == 3) {
                    v0 = gelu_tanh(v0); v1 = gelu_tanh(v1);
                    __nv_bfloat162 h, lo;
                    h.x = __float2bfloat16_rn(v0); h.y = __float2bfloat16_rn(v1);
                    lo.x = __float2bfloat16_rn(v0 - __bfloat162float(h.x));
                    lo.y = __float2bfloat16_rn(v1 - __bfloat162float(h.y));
                    *(__nv_bfloat162*)((char*)Ch + off * 2) = h;
                    *(__nv_bfloat162*)((char*)Cl + off * 2) = lo;
                } else {
                    if (EPI == 2) {
                        float2 rr = *(const float2*)(Rres + off);
                        v0 += rr.x; v1 += rr.y;
                    }
                    *(float2*)(C + off) = make_float2(v0, v1);
                }
            }
        }
    }
}

// ---------------- weight transpose + bf16 split ([K,N] -> [N,K] hi/lo) ----
__global__ void wprep(const float* __restrict__ W, __nv_bfloat16* __restrict__ Wh,
                      __nv_bfloat16* __restrict__ Wl, int K, int N)
{
    __shared__ float t[32][33];
    const size_t lo = (size_t)blockIdx.z * K * N;
    const float* Wp = W + lo;
    const int kt = blockIdx.y * 32, nt = blockIdx.x * 32;
    const int tx = threadIdx.x, ty = threadIdx.y;
#pragma unroll
    for (int i = ty; i < 32; i += 8)
        t[i][tx] = Wp[(size_t)(kt + i) * N + nt + tx];
    __syncthreads();
#pragma unroll
    for (int i = ty; i < 32; i += 8) {
        float v = t[tx][i];
        size_t o = lo + (size_t)(nt + i) * K + kt + tx;
        __nv_bfloat16 h = __float2bfloat16_rn(v);
        Wh[o] = h;
        Wl[o] = __float2bfloat16_rn(v - __bfloat162float(h));
    }
}

// ---------------- LayerNorm -> bf16 hi/lo ----------------
__global__ void ln_split(const float* __restrict__ x, const float* __restrict__ w,
                         const float* __restrict__ b, __nv_bfloat16* __restrict__ yh,
                         __nv_bfloat16* __restrict__ yl)
{
    size_t row = blockIdx.x;
    const float* xr = x + row * D_EMB;
    int tid = threadIdx.x;
    float v0 = xr[tid], v1 = xr[tid + 128], v2 = xr[tid + 256];
    float s = v0 + v1 + v2, sq = v0*v0 + v1*v1 + v2*v2;
#pragma unroll
    for (int o = 16; o; o >>= 1) {
        s  += __shfl_xor_sync(~0u, s,  o);
        sq += __shfl_xor_sync(~0u, sq, o);
    }
    __shared__ float ws[4], wq[4], red[2];
    int warp = tid >> 5, lane = tid & 31;
    if (!lane) { ws[warp] = s; wq[warp] = sq; }
    __syncthreads();
    if (tid == 0) {
        float S = ws[0]+ws[1]+ws[2]+ws[3], Q = wq[0]+wq[1]+wq[2]+wq[3];
        float mean = S * (1.0f / 384.0f);
        red[0] = mean;
        red[1] = rsqrtf(Q * (1.0f / 384.0f) - mean * mean + 1e-5f);
    }
    __syncthreads();
    float mean = red[0], inv = red[1];
#pragma unroll
    for (int q = 0; q < 3; q++) {
        int i = tid + q * 128;
        float v = (q == 0 ? v0 : q == 1 ? v1 : v2);
        float y = (v - mean) * inv * w[i] + b[i];
        __nv_bfloat16 h = __float2bfloat16_rn(y);
        yh[row * D_EMB + i] = h;
        yl[row * D_EMB + i] = __float2bfloat16_rn(y - __bfloat162float(h));
    }
}

__global__ void lnf_kernel(const float* __restrict__ x, const float* __restrict__ w,
                           const float* __restrict__ b, float* __restrict__ out)
{
    size_t bi = blockIdx.x;
    const float* xr = x + (bi * NTOK + (NTOK - 1)) * D_EMB;
    int tid = threadIdx.x;
    float v0 = xr[tid], v1 = xr[tid + 128], v2 = xr[tid + 256];
    float s = v0 + v1 + v2, sq = v0*v0 + v1*v1 + v2*v2;
#pragma unroll
    for (int o = 16; o; o >>= 1) {
        s  += __shfl_xor_sync(~0u, s,  o);
        sq += __shfl_xor_sync(~0u, sq, o);
    }
    __shared__ float ws[4], wq[4], red[2];
    int warp = tid >> 5, lane = tid & 31;
    if (!lane) { ws[warp] = s; wq[warp] = sq; }
    __syncthreads();
    if (tid == 0) {
        float S = ws[0]+ws[1]+ws[2]+ws[3], Q = wq[0]+wq[1]+wq[2]+wq[3];
        float mean = S * (1.0f / 384.0f);
        red[0] = mean;
        red[1] = rsqrtf(Q * (1.0f / 384.0f) - mean * mean + 1e-5f);
    }
    __syncthreads();
    float mean = red[0], inv = red[1];
    out[bi * D_EMB + tid]       = (v0 - mean) * inv * w[tid]       + b[tid];
    out[bi * D_EMB + tid + 128] = (v1 - mean) * inv * w[tid + 128] + b[tid + 128];
    out[bi * D_EMB + tid + 256] = (v2 - mean) * inv * w[tid + 256] + b[tid + 256];
}

// ---------------- Attention (fp32 in, bf16 hi/lo out) ----------------
#define ATT_SMEM_FLOATS (291*65*2 + 8*292 + 8*64)
#define ATT_SMEM_BYTES  (ATT_SMEM_FLOATS * 4)

__global__ void __launch_bounds__(256) attn_kernel(const float* __restrict__ qkv,
                                                   __nv_bfloat16* __restrict__ oh,
                                                   __nv_bfloat16* __restrict__ ol)
{
    extern __shared__ float sm[];
    float* Ks = sm;
    float* Vs = sm + 291 * 65;
    float* Ps = sm + 291 * 65 * 2;
    float* Qs = Ps + 8 * 292;

    int bh = blockIdx.x;
    int b = bh / NHEAD, h = bh % NHEAD;
    int tid = threadIdx.x, warp = tid >> 5, lane = tid & 31;
    const size_t base = (size_t)b * NTOK * 1152 + h * 64;

    for (int idx = tid; idx < NTOK * 64; idx += 256) {
        int j = idx >> 6, d = idx & 63;
        Ks[j * 65 + d] = qkv[base + (size_t)j * 1152 + 384 + d];
        Vs[j * 65 + d] = qkv[base + (size_t)j * 1152 + 768 + d];
    }
    __syncthreads();

    const float scale = rsqrtf(64.0f + 1e-8f);

    for (int t = warp; t < NTOK; t += 8) {
        __syncwarp();
        size_t ob = ((size_t)b * NTOK + t) * D_EMB + h * 64;
        if (t == NTOK - 1) {
#pragma unroll
            for (int q = 0; q < 2; q++) {
                float v = Vs[(NTOK - 1) * 65 + lane + q * 32];
                __nv_bfloat16 hh = __float2bfloat16_rn(v);
                oh[ob + lane + q * 32] = hh;
                ol[ob + lane + q * 32] = __float2bfloat16_rn(v - __bfloat162float(hh));
            }
            continue;
        }
        const float* qr = qkv + base + (size_t)t * 1152;
        Qs[warp * 64 + lane]      = qr[lane];
        Qs[warp * 64 + lane + 32] = qr[lane + 32];
        __syncwarp();

        float s[10];
#pragma unroll
        for (int jc = 0; jc < 10; jc++) {
            int j = jc * 32 + lane;
            if (j < NTOK) {
                const float* kr = Ks + j * 65;
                const float* qs = Qs + warp * 64;
                float a = 0.f;
#pragma unroll
                for (int d = 0; d < 64; d++) a = fmaf(qs[d], kr[d], a);
                s[jc] = a * scale;
            } else s[jc] = -1e30f;
        }
        float m = s[0];
#pragma unroll
        for (int jc = 1; jc < 10; jc++) m = fmaxf(m, s[jc]);
#pragma unroll
        for (int o = 16; o; o >>= 1) m = fmaxf(m, __shfl_xor_sync(~0u, m, o));
        float sum = 0.f;
#pragma unroll
        for (int jc = 0; jc < 10; jc++) { s[jc] = expf(s[jc] - m); sum += s[jc]; }
#pragma unroll
        for (int o = 16; o; o >>= 1) sum += __shfl_xor_sync(~0u, sum, o);
        float inv = 1.0f / sum;
#pragma unroll
        for (int jc = 0; jc < 10; jc++) {
            int j = jc * 32 + lane;
            if (j < NTOK) Ps[warp * 292 + j] = s[jc];
        }
        __syncwarp();

        float o0 = 0.f, o1 = 0.f;
        const float* pp = Ps + warp * 292;
        for (int j = 0; j < NTOK; j++) {
            float pv = pp[j];
            o0 = fmaf(pv, Vs[j * 65 + lane],      o0);
            o1 = fmaf(pv, Vs[j * 65 + lane + 32], o1);
        }
        o0 *= inv; o1 *= inv;
        __nv_bfloat16 h0 = __float2bfloat16_rn(o0), h1 = __float2bfloat16_rn(o1);
        oh[ob + lane]      = h0;
        ol[ob + lane]      = __float2bfloat16_rn(o0 - __bfloat162float(h0));
        oh[ob + lane + 32] = h1;
        ol[ob + lane + 32] = __float2bfloat16_rn(o1 - __bfloat162float(h1));
    }
}

// ---------------- tokenizers ----------------
__global__ void st_kernel(const float* __restrict__ as, const float* __restrict__ w1,
                          const float* __restrict__ b1, const float* __restrict__ w2,
                          const float* __restrict__ b2, float* __restrict__ st)
{
    __shared__ float h1[32];
    int bt = blockIdx.x;
    int tid = threadIdx.x;
    float s0 = as[bt * 2], s1 = as[bt * 2 + 1];
    if (tid < 32) {
        float v = b1[tid] + s0 * w1[tid] + s1 * w1[32 + tid];
        h1[tid] = v > 0.f ? v : 0.f;
    }
    __syncthreads();
    float acc = b2[tid];
#pragma unroll
    for (int k = 0; k < 32; k++) acc = fmaf(h1[k], w2[k * 384 + tid], acc);
    st[(size_t)bt * 384 + tid] = acc;
}

__global__ void im2col_kernel(const float* __restrict__ img,
                              __nv_bfloat16* __restrict__ ph, __nv_bfloat16* __restrict__ pl)
{
    int idx = blockIdx.x * 256 + threadIdx.x;
    int f = idx % 192;
    int rem = idx / 192;
    int pidx = rem % 144;
    int bt = rem / 144;
    int pr = f / 24, pc = (f % 24) / 3, c = f % 3;
    int hp = pidx / 12, wp = pidx % 12;
    float v = img[(((size_t)bt * 3 + c) * 96 + hp * 8 + pr) * 96 + wp * 8 + pc];
    __nv_bfloat16 h = __float2bfloat16_rn(v);
    ph[idx] = h;
    pl[idx] = __float2bfloat16_rn(v - __bfloat162float(h));
}

__global__ void assemble_kernel(const float* __restrict__ imgtok, const float* __restrict__ st,
                                const float* __restrict__ readout, const float* __restrict__ pos,
                                const float* __restrict__ img_temb, const float* __restrict__ st_temb,
                                float* __restrict__ x)
{
    int idx = blockIdx.x * 256 + threadIdx.x;
    int d = idx % 384;
    int rem = idx / 384;
    int tok = rem % NTOK;
    int b = rem / NTOK;
    float v;
    if (tok == NTOK - 1) {
        v = readout[d];
    } else {
        int t = tok / 145, r = tok % 145;
        if (r == 0) v = st[((size_t)(b * 2 + t)) * 384 + d] + st_temb[t * 384 + d];
        else        v = imgtok[((size_t)(b * 2 + t) * 144 + (r - 1)) * 384 + d] + img_temb[t * 384 + d];
    }
    x[idx] = v + pos[tok * 384 + d];
}

// ---------------- launch ----------------
extern "C" void kernel_launch(void* const* d_in, const int* in_sizes, int n_in,
                              void* d_out, int out_size)
{
    const float* images      = (const float*)d_in[0];
    const float* agent_state = (const float*)d_in[1];
    const float* img_proj_w  = (const float*)d_in[2];
    const float* img_proj_b  = (const float*)d_in[3];
    const float* img_temb    = (const float*)d_in[4];
    const float* st_w1       = (const float*)d_in[5];
    const float* st_b1       = (const float*)d_in[6];
    const float* st_w2       = (const float*)d_in[7];
    const float* st_b2       = (const float*)d_in[8];
    const float* st_temb     = (const float*)d_in[9];
    const float* readout     = (const float*)d_in[10];
    const float* pos         = (const float*)d_in[11];
    const float* ln1_w       = (const float*)d_in[12];
    const float* ln1_b       = (const float*)d_in[13];
    const float* attn_w      = (const float*)d_in[14];
    const float* attn_b      = (const float*)d_in[15];
    const float* proj_w      = (const float*)d_in[16];
    const float* proj_b      = (const float*)d_in[17];
    const float* ln2_w       = (const float*)d_in[18];
    const float* ln2_b       = (const float*)d_in[19];
    const float* fc_w        = (const float*)d_in[20];
    const float* fc_b        = (const float*)d_in[21];
    const float* fc2_w       = (const float*)d_in[22];
    const float* fc2_b       = (const float*)d_in[23];
    const float* lnf_w       = (const float*)d_in[24];
    const float* lnf_b       = (const float*)d_in[25];
    float* out = (float*)d_out;

    float *x, *big, *att, *st;
    __nv_bfloat16 *yh, *yl, *ah, *al, *bh, *bl, *ph, *pl;
    __nv_bfloat16 *wqh, *wql, *wph, *wpl, *w1h, *w1l, *w2h, *w2l, *wih, *wil;
    cudaGetSymbolAddress((void**)&x,   g_x);
    cudaGetSymbolAddress((void**)&big, g_big);
    cudaGetSymbolAddress((void**)&att, g_att);
    cudaGetSymbolAddress((void**)&st,  g_st);
    cudaGetSymbolAddress((void**)&yh,  g_yh);  cudaGetSymbolAddress((void**)&yl, g_yl);
    cudaGetSymbolAddress((void**)&ah,  g_ah);  cudaGetSymbolAddress((void**)&al, g_al);
    cudaGetSymbolAddress((void**)&bh,  g_bh);  cudaGetSymbolAddress((void**)&bl, g_bl);
    cudaGetSymbolAddress((void**)&ph,  g_ph);  cudaGetSymbolAddress((void**)&pl, g_pl);
    cudaGetSymbolAddress((void**)&wqh, g_wqh); cudaGetSymbolAddress((void**)&wql, g_wql);
    cudaGetSymbolAddress((void**)&wph, g_wph); cudaGetSymbolAddress((void**)&wpl, g_wpl);
    cudaGetSymbolAddress((void**)&w1h, g_w1h); cudaGetSymbolAddress((void**)&w1l, g_w1l);
    cudaGetSymbolAddress((void**)&w2h, g_w2h); cudaGetSymbolAddress((void**)&w2l, g_w2l);
    cudaGetSymbolAddress((void**)&wih, g_wih); cudaGetSymbolAddress((void**)&wil, g_wil);

    cudaFuncSetAttribute(attn_kernel, cudaFuncAttributeMaxDynamicSharedMemorySize, ATT_SMEM_BYTES);
    cudaFuncSetAttribute(gemm_mma<0>, cudaFuncAttributeMaxDynamicSharedMemorySize, GSMEM);
    cudaFuncSetAttribute(gemm_mma<2>, cudaFuncAttributeMaxDynamicSharedMemorySize, GSMEM);
    cudaFuncSetAttribute(gemm_mma<3>, cudaFuncAttributeMaxDynamicSharedMemorySize, GSMEM);

    // ---- weight prep (transpose + bf16 split), once per launch ----
    wprep<<<dim3(1152/32, 384/32, 12), dim3(32, 8)>>>(attn_w, wqh, wql, 384, 1152);
    wprep<<<dim3(384/32,  384/32, 12), dim3(32, 8)>>>(proj_w, wph, wpl, 384, 384);
    wprep<<<dim3(1536/32, 384/32, 12), dim3(32, 8)>>>(fc_w,  w1h, w1l, 384, 1536);
    wprep<<<dim3(384/32, 1536/32, 12), dim3(32, 8)>>>(fc2_w, w2h, w2l, 1536, 384);
    wprep<<<dim3(384/32,  192/32, 1),  dim3(32, 8)>>>(img_proj_w, wih, wil, 192, 384);

    // ---- tokenizers ----
    st_kernel<<<BATCH * OBS_H, 384>>>(agent_state, st_w1, st_b1, st_w2, st_b2, st);
    im2col_kernel<<<(M_PATCH * PK) / 256, 256>>>(images, ph, pl);
    gemm_mma<0><<<dim3(3, M_PATCH / 128), 256, GSMEM>>>(
        ph, pl, wih, wil, img_proj_b, nullptr, att, nullptr, nullptr, 384, PK);
    assemble_kernel<<<(M_TOK * D_EMB) / 256, 256>>>(att, st, readout, pos, img_temb, st_temb, x);

    // ---- transformer layers ----
    for (int l = 0; l < NLAYER; l++) {
        ln_split<<<M_TOK, 128>>>(x, ln1_w + l * 384, ln1_b + l * 384, yh, yl);
        gemm_mma<0><<<dim3(9, NTOK), 256, GSMEM>>>(
            yh, yl, wqh + (size_t)l * 1152 * 384, wql + (size_t)l * 1152 * 384,
            attn_b + l * 1152, nullptr, big, nullptr, nullptr, 1152, 384);
        attn_kernel<<<BATCH * NHEAD, 256, ATT_SMEM_BYTES>>>(big, ah, al);
        gemm_mma<2><<<dim3(3, NTOK), 256, GSMEM>>>(
            ah, al, wph + (size_t)l * 384 * 384, wpl + (size_t)l * 384 * 384,
            proj_b + l * 384, x, x, nullptr, nullptr, 384, 384);
        ln_split<<<M_TOK, 128>>>(x, ln2_w + l * 384, ln2_b + l * 384, yh, yl);
        gemm_mma<3><<<dim3(12, NTOK), 256, GSMEM>>>(
            yh, yl, w1h + (size_t)l * 1536 * 384, w1l + (size_t)l * 1536 * 384,
            fc_b + l * 1536, nullptr, nullptr, bh, bl, 1536, 384);
        gemm_mma<2><<<dim3(3, NTOK), 256, GSMEM>>>(
            bh, bl, w2h + (size_t)l * 384 * 1536, w2l + (size_t)l * 384 * 1536,
            fc2_b + l * 384, x, x, nullptr, nullptr, 384, 1536);
    }

    lnf_kernel<<<BATCH, 128>>>(x, lnf_w, lnf_b, out);
}

// round 6
// speedup vs baseline: 3.1430x; 1.7982x over previous
#include <cuda_runtime.h>
#include <cuda_fp16.h>
#include <math.h>
#include <stdint.h>

// ---------------- problem constants ----------------
#define BATCH   128
#define OBS_H   2
#define NTOK    291
#define M_TOK   (BATCH*NTOK)   // 37248 = 291*128
#define D_EMB   384
#define NHEAD   6
#define NLAYER  12
#define N_IMG   144
#define PK      192
#define M_PATCH (BATCH*OBS_H*N_IMG)   // 36864 = 288*128

// ---------------- scratch ----------------
__device__ float g_x  [M_TOK * D_EMB];
__device__ float g_big[M_TOK * 1536];          // qkv fp32
__device__ float g_att[M_PATCH * D_EMB];       // img tokens fp32
__device__ float g_st [BATCH * OBS_H * D_EMB];
__device__ __half g_yh[M_TOK*384];             // LN out fp16
__device__ __half g_ah[M_TOK*384];             // attn out fp16
__device__ __half g_bh[M_TOK*1536];            // fc1 out fp16
__device__ __half g_ph[M_PATCH*192];           // patches fp16
// transposed weights [N,K] fp16
__device__ __half g_wq[12*1152*384];
__device__ __half g_wp[12*384*384];
__device__ __half g_w1[12*1536*384];
__device__ __half g_w2[12*384*1536];
__device__ __half g_wi[384*192];

__device__ __forceinline__ float gelu_tanh(float v) {
    const float c = 0.7978845608028654f;
    float u = c * (v + 0.044715f * v * v * v);
    return 0.5f * v * (1.0f + tanhf(u));
}

__device__ __forceinline__ uint32_t smem_u32(const void* p) {
    uint32_t a;
    asm("{ .reg .u64 t; cvta.to.shared.u64 t, %1; cvt.u32.u64 %0, t; }" : "=r"(a) : "l"(p));
    return a;
}

__device__ __forceinline__ void mma16816(float c[4], const uint32_t a[4], const uint32_t b[2]) {
    asm volatile(
        "mma.sync.aligned.m16n8k16.row.col.f32.f16.f16.f32 "
        "{%0,%1,%2,%3}, {%4,%5,%6,%7}, {%8,%9}, {%0,%1,%2,%3};\n"
        : "+f"(c[0]), "+f"(c[1]), "+f"(c[2]), "+f"(c[3])
        : "r"(a[0]), "r"(a[1]), "r"(a[2]), "r"(a[3]), "r"(b[0]), "r"(b[1]));
}
#define LDMX4(r0, r1, r2, r3, addr) \
    asm volatile("ldmatrix.sync.aligned.m8n8.x4.shared.b16 {%0,%1,%2,%3}, [%4];" \
        : "=r"(r0), "=r"(r1), "=r"(r2), "=r"(r3) : "r"(addr))

// =======================================================================
// fp16 single-pass HMMA GEMM: C[M,N] = A[M,K] @ B[N,K]^T
// BM=BN=128, BK=32, 256 thr = 8 warps (2m x 4n), warp tile 64x32.
// cp.async double-buffered; smem rows 80B (conflict-free ldmatrix).
// EPI: 0 +bias->f32 | 2 +bias+res->f32 | 3 +bias,gelu->fp16
// =======================================================================
#define STAGE_B   20480              // 2 * 128*80
#define GSMEM     (2*STAGE_B)        // 40960

template <int EPI>
__global__ void __launch_bounds__(256, 2) gemm_mma(
    const __half* __restrict__ A, const __half* __restrict__ B,
    const float* __restrict__ bias, const float* __restrict__ Rres,
    float* __restrict__ C, __half* __restrict__ Ch,
    int N, int K)
{
    extern __shared__ __align__(16) char dyn[];
    const uint32_t sbase = smem_u32(dyn);
    const int tid = threadIdx.x, lane = tid & 31, warp = tid >> 5;
    const int wm = warp >> 2, wn = warp & 3;
    const int bn = blockIdx.x, bm = blockIdx.y;

    float acc[4][4][4];
#pragma unroll
    for (int i = 0; i < 4; i++)
#pragma unroll
        for (int j = 0; j < 4; j++)
#pragma unroll
            for (int q = 0; q < 4; q++) acc[i][j][q] = 0.f;

    const char* gsrc[2] = {
        (const char*)(A + (size_t)bm * 128 * K),
        (const char*)(B + (size_t)bn * 128 * K) };
    const size_t rs = (size_t)K * 2;

#define LOADT(t_) do { \
    uint32_t db_ = sbase + ((t_) & 1) * STAGE_B; \
    size_t go_ = (size_t)(t_) * 64; \
    _Pragma("unroll") \
    for (int b_ = 0; b_ < 2; b_++) { \
        const char* g_ = gsrc[b_]; \
        uint32_t d_ = db_ + b_ * 10240; \
        _Pragma("unroll") \
        for (int i_ = 0; i_ < 2; i_++) { \
            int idx_ = i_ * 256 + tid; \
            int r_ = idx_ >> 2, c_ = (idx_ & 3) * 16; \
            asm volatile("cp.async.cg.shared.global [%0], [%1], 16;" \
                :: "r"(d_ + r_ * 80 + c_), "l"(g_ + (size_t)r_ * rs + go_ + c_) : "memory"); \
        } \
    } \
    asm volatile("cp.async.commit_group;" ::: "memory"); \
} while (0)

    const int T = K >> 5;
    LOADT(0);
    if (T > 1) LOADT(1);

    for (int t = 0; t < T; t++) {
        if (t + 1 < T) asm volatile("cp.async.wait_group 1;" ::: "memory");
        else           asm volatile("cp.async.wait_group 0;" ::: "memory");
        __syncthreads();
        const uint32_t sb = sbase + (t & 1) * STAGE_B;

#pragma unroll
        for (int ks = 0; ks < 2; ks++) {
            const int k0 = ks * 16;
            uint32_t bf[4][2];
#pragma unroll
            for (int pr = 0; pr < 2; pr++) {
                int trow = wn * 32 + pr * 16 + ((lane >> 4) & 1) * 8 + (lane & 7);
                int tcol = k0 + ((lane >> 3) & 1) * 8;
                uint32_t ab = sb + 10240 + trow * 80 + tcol * 2;
                LDMX4(bf[2*pr][0], bf[2*pr][1], bf[2*pr+1][0], bf[2*pr+1][1], ab);
            }
#pragma unroll
            for (int i = 0; i < 4; i++) {
                int arow = wm * 64 + i * 16 + (lane & 7) + ((lane >> 3) & 1) * 8;
                int acol = k0 + ((lane >> 4) & 1) * 8;
                uint32_t aa = sb + arow * 80 + acol * 2;
                uint32_t a4[4];
                LDMX4(a4[0], a4[1], a4[2], a4[3], aa);
#pragma unroll
                for (int j = 0; j < 4; j++) mma16816(acc[i][j], a4, bf[j]);
            }
        }
        __syncthreads();
        if (t + 2 < T) LOADT(t + 2);
    }

    // ---- epilogue ----
#pragma unroll
    for (int i = 0; i < 4; i++) {
        int row0 = bm * 128 + wm * 64 + i * 16 + (lane >> 2);
#pragma unroll
        for (int j = 0; j < 4; j++) {
            int col = bn * 128 + wn * 32 + j * 8 + (lane & 3) * 2;
            float b0 = bias[col], b1 = bias[col + 1];
#pragma unroll
            for (int half_ = 0; half_ < 2; half_++) {
                int row = row0 + half_ * 8;
                size_t off = (size_t)row * N + col;
                float v0 = acc[i][j][half_ * 2 + 0] + b0;
                float v1 = acc[i][j][half_ * 2 + 1] + b1;
                if (EPI == 3) {
                    v0 = gelu_tanh(v0); v1 = gelu_tanh(v1);
                    __half2 h;
                    h.x = __float2half_rn(v0); h.y = __float2half_rn(v1);
                    *(__half2*)((char*)Ch + off * 2) = h;
                } else {
                    if (EPI == 2) {
                        float2 rr = *(const float2*)(Rres + off);
                        v0 += rr.x; v1 += rr.y;
                    }
                    *(float2*)(C + off) = make_float2(v0, v1);
                }
            }
        }
    }
}

// ---------------- weight transpose + fp16 ([K,N] -> [N,K]) ----
__global__ void wprep(const float* __restrict__ W, __half* __restrict__ Wh, int K, int N)
{
    __shared__ float t[32][33];
    const size_t lo = (size_t)blockIdx.z * K * N;
    const float* Wp = W + lo;
    const int kt = blockIdx.y * 32, nt = blockIdx.x * 32;
    const int tx = threadIdx.x, ty = threadIdx.y;
#pragma unroll
    for (int i = ty; i < 32; i += 8)
        t[i][tx] = Wp[(size_t)(kt + i) * N + nt + tx];
    __syncthreads();
#pragma unroll
    for (int i = ty; i < 32; i += 8)
        Wh[lo + (size_t)(nt + i) * K + kt + tx] = __float2half_rn(t[tx][i]);
}

// ---------------- LayerNorm -> fp16 ----------------
__global__ void ln_half(const float* __restrict__ x, const float* __restrict__ w,
                        const float* __restrict__ b, __half* __restrict__ yh)
{
    size_t row = blockIdx.x;
    const float* xr = x + row * D_EMB;
    int tid = threadIdx.x;
    float v0 = xr[tid], v1 = xr[tid + 128], v2 = xr[tid + 256];
    float s = v0 + v1 + v2, sq = v0*v0 + v1*v1 + v2*v2;
#pragma unroll
    for (int o = 16; o; o >>= 1) {
        s  += __shfl_xor_sync(~0u, s,  o);
        sq += __shfl_xor_sync(~0u, sq, o);
    }
    __shared__ float ws[4], wq[4], red[2];
    int warp = tid >> 5, lane = tid & 31;
    if (!lane) { ws[warp] = s; wq[warp] = sq; }
    __syncthreads();
    if (tid == 0) {
        float S = ws[0]+ws[1]+ws[2]+ws[3], Q = wq[0]+wq[1]+wq[2]+wq[3];
        float mean = S * (1.0f / 384.0f);
        red[0] = mean;
        red[1] = rsqrtf(Q * (1.0f / 384.0f) - mean * mean + 1e-5f);
    }
    __syncthreads();
    float mean = red[0], inv = red[1];
    yh[row * D_EMB + tid]       = __float2half_rn((v0 - mean) * inv * w[tid]       + b[tid]);
    yh[row * D_EMB + tid + 128] = __float2half_rn((v1 - mean) * inv * w[tid + 128] + b[tid + 128]);
    yh[row * D_EMB + tid + 256] = __float2half_rn((v2 - mean) * inv * w[tid + 256] + b[tid + 256]);
}

__global__ void lnf_kernel(const float* __restrict__ x, const float* __restrict__ w,
                           const float* __restrict__ b, float* __restrict__ out)
{
    size_t bi = blockIdx.x;
    const float* xr = x + (bi * NTOK + (NTOK - 1)) * D_EMB;
    int tid = threadIdx.x;
    float v0 = xr[tid], v1 = xr[tid + 128], v2 = xr[tid + 256];
    float s = v0 + v1 + v2, sq = v0*v0 + v1*v1 + v2*v2;
#pragma unroll
    for (int o = 16; o; o >>= 1) {
        s  += __shfl_xor_sync(~0u, s,  o);
        sq += __shfl_xor_sync(~0u, sq, o);
    }
    __shared__ float ws[4], wq[4], red[2];
    int warp = tid >> 5, lane = tid & 31;
    if (!lane) { ws[warp] = s; wq[warp] = sq; }
    __syncthreads();
    if (tid == 0) {
        float S = ws[0]+ws[1]+ws[2]+ws[3], Q = wq[0]+wq[1]+wq[2]+wq[3];
        float mean = S * (1.0f / 384.0f);
        red[0] = mean;
        red[1] = rsqrtf(Q * (1.0f / 384.0f) - mean * mean + 1e-5f);
    }
    __syncthreads();
    float mean = red[0], inv = red[1];
    out[bi * D_EMB + tid]       = (v0 - mean) * inv * w[tid]       + b[tid];
    out[bi * D_EMB + tid + 128] = (v1 - mean) * inv * w[tid + 128] + b[tid + 128];
    out[bi * D_EMB + tid + 256] = (v2 - mean) * inv * w[tid + 256] + b[tid + 256];
}

// ---------------- Attention: 2 queries per warp-iter (halved LDS traffic) --
// smem: K[291][68] + V[291][68] + P[16][292] + Q[16][64]
#define KV_STRIDE 68
#define ATT_SMEM_FLOATS (291*KV_STRIDE*2 + 16*292 + 16*64)
#define ATT_SMEM_BYTES  (ATT_SMEM_FLOATS * 4)

__global__ void __launch_bounds__(256) attn_kernel(const float* __restrict__ qkv,
                                                   __half* __restrict__ oh)
{
    extern __shared__ float sm[];
    float* Ks = sm;
    float* Vs = sm + 291 * KV_STRIDE;
    float* Ps = sm + 291 * KV_STRIDE * 2;   // [16][292]
    float* Qs = Ps + 16 * 292;              // [16][64]

    int bh = blockIdx.x;
    int b = bh / NHEAD, h = bh % NHEAD;
    int tid = threadIdx.x, warp = tid >> 5, lane = tid & 31;
    const size_t base = (size_t)b * NTOK * 1152 + h * 64;

    for (int idx = tid; idx < NTOK * 64; idx += 256) {
        int j = idx >> 6, d = idx & 63;
        Ks[j * KV_STRIDE + d] = qkv[base + (size_t)j * 1152 + 384 + d];
        Vs[j * KV_STRIDE + d] = qkv[base + (size_t)j * 1152 + 768 + d];
    }
    __syncthreads();

    const float scale = rsqrtf(64.0f + 1e-8f);

    // 146 pairs: p -> tokens (2p, 2p+1); p=145 -> t0=290 readout (no t1)
    for (int p = warp; p < 146; p += 8) {
        __syncwarp();
        int t0 = 2 * p, t1 = 2 * p + 1;
        size_t ob0 = ((size_t)b * NTOK + t0) * D_EMB + h * 64;
        if (t0 == NTOK - 1) {
            // readout row: softmax is one-hot on itself
            oh[ob0 + lane]      = __float2half_rn(Vs[(NTOK - 1) * KV_STRIDE + lane]);
            oh[ob0 + lane + 32] = __float2half_rn(Vs[(NTOK - 1) * KV_STRIDE + lane + 32]);
            continue;
        }
        const float* q0 = qkv + base + (size_t)t0 * 1152;
        const float* q1 = qkv + base + (size_t)t1 * 1152;
        float* qs0 = Qs + warp * 128;
        float* qs1 = qs0 + 64;
        qs0[lane] = q0[lane]; qs0[lane + 32] = q0[lane + 32];
        qs1[lane] = q1[lane]; qs1[lane + 32] = q1[lane + 32];
        __syncwarp();

        float s0[10], s1[10];
#pragma unroll
        for (int jc = 0; jc < 10; jc++) {
            int j = jc * 32 + lane;
            if (j < NTOK) {
                const float4* kr = (const float4*)(Ks + j * KV_STRIDE);
                float a0 = 0.f, a1 = 0.f;
#pragma unroll
                for (int d4 = 0; d4 < 16; d4++) {
                    float4 kv = kr[d4];
                    float u0 = qs0[d4*4], u1 = qs0[d4*4+1], u2 = qs0[d4*4+2], u3 = qs0[d4*4+3];
                    float w0 = qs1[d4*4], w1 = qs1[d4*4+1], w2 = qs1[d4*4+2], w3 = qs1[d4*4+3];
                    a0 = fmaf(u0, kv.x, a0); a0 = fmaf(u1, kv.y, a0);
                    a0 = fmaf(u2, kv.z, a0); a0 = fmaf(u3, kv.w, a0);
                    a1 = fmaf(w0, kv.x, a1); a1 = fmaf(w1, kv.y, a1);
                    a1 = fmaf(w2, kv.z, a1); a1 = fmaf(w3, kv.w, a1);
                }
                s0[jc] = a0 * scale; s1[jc] = a1 * scale;
            } else { s0[jc] = -1e30f; s1[jc] = -1e30f; }
        }
        float m0 = s0[0], m1 = s1[0];
#pragma unroll
        for (int jc = 1; jc < 10; jc++) { m0 = fmaxf(m0, s0[jc]); m1 = fmaxf(m1, s1[jc]); }
#pragma unroll
        for (int o = 16; o; o >>= 1) {
            m0 = fmaxf(m0, __shfl_xor_sync(~0u, m0, o));
            m1 = fmaxf(m1, __shfl_xor_sync(~0u, m1, o));
        }
        float sum0 = 0.f, sum1 = 0.f;
#pragma unroll
        for (int jc = 0; jc < 10; jc++) {
            s0[jc] = expf(s0[jc] - m0); sum0 += s0[jc];
            s1[jc] = expf(s1[jc] - m1); sum1 += s1[jc];
        }
#pragma unroll
        for (int o = 16; o; o >>= 1) {
            sum0 += __shfl_xor_sync(~0u, sum0, o);
            sum1 += __shfl_xor_sync(~0u, sum1, o);
        }
        float inv0 = 1.0f / sum0, inv1 = 1.0f / sum1;
        float* pp0 = Ps + (warp * 2 + 0) * 292;
        float* pp1 = Ps + (warp * 2 + 1) * 292;
#pragma unroll
        for (int jc = 0; jc < 10; jc++) {
            int j = jc * 32 + lane;
            if (j < NTOK) { pp0[j] = s0[jc]; pp1[j] = s1[jc]; }
        }
        __syncwarp();

        float o00 = 0.f, o01 = 0.f, o10 = 0.f, o11 = 0.f;
        for (int j = 0; j < NTOK; j++) {
            float v0 = Vs[j * KV_STRIDE + lane];
            float v1 = Vs[j * KV_STRIDE + lane + 32];
            float pv0 = pp0[j], pv1 = pp1[j];
            o00 = fmaf(pv0, v0, o00); o01 = fmaf(pv0, v1, o01);
            o10 = fmaf(pv1, v0, o10); o11 = fmaf(pv1, v1, o11);
        }
        size_t ob1 = ob0 + D_EMB;
        oh[ob0 + lane]      = __float2half_rn(o00 * inv0);
        oh[ob0 + lane + 32] = __float2half_rn(o01 * inv0);
        oh[ob1 + lane]      = __float2half_rn(o10 * inv1);
        oh[ob1 + lane + 32] = __float2half_rn(o11 * inv1);
    }
}

// ---------------- tokenizers ----------------
__global__ void st_kernel(const float* __restrict__ as, const float* __restrict__ w1,
                          const float* __restrict__ b1, const float* __restrict__ w2,
                          const float* __restrict__ b2, float* __restrict__ st)
{
    __shared__ float h1[32];
    int bt = blockIdx.x;
    int tid = threadIdx.x;
    float s0 = as[bt * 2], s1 = as[bt * 2 + 1];
    if (tid < 32) {
        float v = b1[tid] + s0 * w1[tid] + s1 * w1[32 + tid];
        h1[tid] = v > 0.f ? v : 0.f;
    }
    __syncthreads();
    float acc = b2[tid];
#pragma unroll
    for (int k = 0; k < 32; k++) acc = fmaf(h1[k], w2[k * 384 + tid], acc);
    st[(size_t)bt * 384 + tid] = acc;
}

__global__ void im2col_kernel(const float* __restrict__ img, __half* __restrict__ ph)
{
    int idx = blockIdx.x * 256 + threadIdx.x;
    int f = idx % 192;
    int rem = idx / 192;
    int pidx = rem % 144;
    int bt = rem / 144;
    int pr = f / 24, pc = (f % 24) / 3, c = f % 3;
    int hp = pidx / 12, wp = pidx % 12;
    ph[idx] = __float2half_rn(img[(((size_t)bt * 3 + c) * 96 + hp * 8 + pr) * 96 + wp * 8 + pc]);
}

__global__ void assemble_kernel(const float* __restrict__ imgtok, const float* __restrict__ st,
                                const float* __restrict__ readout, const float* __restrict__ pos,
                                const float* __restrict__ img_temb, const float* __restrict__ st_temb,
                                float* __restrict__ x)
{
    int idx = blockIdx.x * 256 + threadIdx.x;
    int d = idx % 384;
    int rem = idx / 384;
    int tok = rem % NTOK;
    int b = rem / NTOK;
    float v;
    if (tok == NTOK - 1) {
        v = readout[d];
    } else {
        int t = tok / 145, r = tok % 145;
        if (r == 0) v = st[((size_t)(b * 2 + t)) * 384 + d] + st_temb[t * 384 + d];
        else        v = imgtok[((size_t)(b * 2 + t) * 144 + (r - 1)) * 384 + d] + img_temb[t * 384 + d];
    }
    x[idx] = v + pos[tok * 384 + d];
}

// ---------------- launch ----------------
extern "C" void kernel_launch(void* const* d_in, const int* in_sizes, int n_in,
                              void* d_out, int out_size)
{
    const float* images      = (const float*)d_in[0];
    const float* agent_state = (const float*)d_in[1];
    const float* img_proj_w  = (const float*)d_in[2];
    const float* img_proj_b  = (const float*)d_in[3];
    const float* img_temb    = (const float*)d_in[4];
    const float* st_w1       = (const float*)d_in[5];
    const float* st_b1       = (const float*)d_in[6];
    const float* st_w2       = (const float*)d_in[7];
    const float* st_b2       = (const float*)d_in[8];
    const float* st_temb     = (const float*)d_in[9];
    const float* readout     = (const float*)d_in[10];
    const float* pos         = (const float*)d_in[11];
    const float* ln1_w       = (const float*)d_in[12];
    const float* ln1_b       = (const float*)d_in[13];
    const float* attn_w      = (const float*)d_in[14];
    const float* attn_b      = (const float*)d_in[15];
    const float* proj_w      = (const float*)d_in[16];
    const float* proj_b      = (const float*)d_in[17];
    const float* ln2_w       = (const float*)d_in[18];
    const float* ln2_b       = (const float*)d_in[19];
    const float* fc_w        = (const float*)d_in[20];
    const float* fc_b        = (const float*)d_in[21];
    const float* fc2_w       = (const float*)d_in[22];
    const float* fc2_b       = (const float*)d_in[23];
    const float* lnf_w       = (const float*)d_in[24];
    const float* lnf_b       = (const float*)d_in[25];
    float* out = (float*)d_out;

    float *x, *big, *att, *st;
    __half *yh, *ah, *bh, *ph, *wq, *wp, *w1, *w2, *wi;
    cudaGetSymbolAddress((void**)&x,   g_x);
    cudaGetSymbolAddress((void**)&big, g_big);
    cudaGetSymbolAddress((void**)&att, g_att);
    cudaGetSymbolAddress((void**)&st,  g_st);
    cudaGetSymbolAddress((void**)&yh,  g_yh);
    cudaGetSymbolAddress((void**)&ah,  g_ah);
    cudaGetSymbolAddress((void**)&bh,  g_bh);
    cudaGetSymbolAddress((void**)&ph,  g_ph);
    cudaGetSymbolAddress((void**)&wq,  g_wq);
    cudaGetSymbolAddress((void**)&wp,  g_wp);
    cudaGetSymbolAddress((void**)&w1,  g_w1);
    cudaGetSymbolAddress((void**)&w2,  g_w2);
    cudaGetSymbolAddress((void**)&wi,  g_wi);

    cudaFuncSetAttribute(attn_kernel, cudaFuncAttributeMaxDynamicSharedMemorySize, ATT_SMEM_BYTES);
    cudaFuncSetAttribute(gemm_mma<0>, cudaFuncAttributeMaxDynamicSharedMemorySize, GSMEM);
    cudaFuncSetAttribute(gemm_mma<2>, cudaFuncAttributeMaxDynamicSharedMemorySize, GSMEM);
    cudaFuncSetAttribute(gemm_mma<3>, cudaFuncAttributeMaxDynamicSharedMemorySize, GSMEM);

    // ---- weight prep (transpose + fp16), once per launch ----
    wprep<<<dim3(1152/32, 384/32, 12), dim3(32, 8)>>>(attn_w, wq, 384, 1152);
    wprep<<<dim3(384/32,  384/32, 12), dim3(32, 8)>>>(proj_w, wp, 384, 384);
    wprep<<<dim3(1536/32, 384/32, 12), dim3(32, 8)>>>(fc_w,  w1, 384, 1536);
    wprep<<<dim3(384/32, 1536/32, 12), dim3(32, 8)>>>(fc2_w, w2, 1536, 384);
    wprep<<<dim3(384/32,  192/32, 1),  dim3(32, 8)>>>(img_proj_w, wi, 192, 384);

    // ---- tokenizers ----
    st_kernel<<<BATCH * OBS_H, 384>>>(agent_state, st_w1, st_b1, st_w2, st_b2, st);
    im2col_kernel<<<(M_PATCH * PK) / 256, 256>>>(images, ph);
    gemm_mma<0><<<dim3(3, M_PATCH / 128), 256, GSMEM>>>(
        ph, wi, img_proj_b, nullptr, att, nullptr, 384, PK);
    assemble_kernel<<<(M_TOK * D_EMB) / 256, 256>>>(att, st, readout, pos, img_temb, st_temb, x);

    // ---- transformer layers ----
    for (int l = 0; l < NLAYER; l++) {
        ln_half<<<M_TOK, 128>>>(x, ln1_w + l * 384, ln1_b + l * 384, yh);
        gemm_mma<0><<<dim3(9, NTOK), 256, GSMEM>>>(
            yh, wq + (size_t)l * 1152 * 384, attn_b + l * 1152, nullptr, big, nullptr, 1152, 384);
        attn_kernel<<<BATCH * NHEAD, 256, ATT_SMEM_BYTES>>>(big, ah);
        gemm_mma<2><<<dim3(3, NTOK), 256, GSMEM>>>(
            ah, wp + (size_t)l * 384 * 384, proj_b + l * 384, x, x, nullptr, 384, 384);
        ln_half<<<M_TOK, 128>>>(x, ln2_w + l * 384, ln2_b + l * 384, yh);
        gemm_mma<3><<<dim3(12, NTOK), 256, GSMEM>>>(
            yh, w1 + (size_t)l * 1536 * 384, fc_b + l * 1536, nullptr, nullptr, bh, 1536, 384);
        gemm_mma<2><<<dim3(3, NTOK), 256, GSMEM>>>(
            bh, w2 + (size_t)l * 384 * 1536, fc2_b + l * 384, x, x, nullptr, 384, 1536);
    }

    lnf_kernel<<<BATCH, 128>>>(x, lnf_w, lnf_b, out);
}

// round 7
// speedup vs baseline: 6.1031x; 1.9418x over previous
#include <cuda_runtime.h>
#include <cuda_fp16.h>
#include <math.h>
#include <stdint.h>

// ---------------- problem constants ----------------
#define BATCH   128
#define OBS_H   2
#define NTOK    291
#define M_TOK   (BATCH*NTOK)   // 37248 = 291*128
#define D_EMB   384
#define NHEAD   6
#define NLAYER  12
#define N_IMG   144
#define PK      192
#define M_PATCH (BATCH*OBS_H*N_IMG)   // 36864 = 288*128

// ---------------- scratch ----------------
__device__ float g_x  [M_TOK * D_EMB];
__device__ float g_att[M_PATCH * D_EMB];       // img tokens fp32
__device__ float g_st [BATCH * OBS_H * D_EMB];
__device__ __half g_yh[M_TOK*384];             // LN out fp16
__device__ __half g_ah[M_TOK*384];             // attn out fp16
__device__ __half g_bh[M_TOK*1536];            // fc1 out fp16
__device__ __half g_ph[M_PATCH*192];           // patches fp16
__device__ __half g_q [BATCH*NHEAD*NTOK*64];   // q (pre-scaled) fp16
__device__ __half g_k [BATCH*NHEAD*NTOK*64];
__device__ __half g_v [BATCH*NHEAD*NTOK*64];
// transposed weights [N,K] fp16
__device__ __half g_wq[12*1152*384];
__device__ __half g_wp[12*384*384];
__device__ __half g_w1[12*1536*384];
__device__ __half g_w2[12*384*1536];
__device__ __half g_wi[384*192];

__device__ __forceinline__ float gelu_tanh(float v) {
    const float c = 0.7978845608028654f;
    float u = c * (v + 0.044715f * v * v * v);
    return 0.5f * v * (1.0f + tanhf(u));
}

__device__ __forceinline__ uint32_t smem_u32(const void* p) {
    uint32_t a;
    asm("{ .reg .u64 t; cvta.to.shared.u64 t, %1; cvt.u32.u64 %0, t; }" : "=r"(a) : "l"(p));
    return a;
}

__device__ __forceinline__ void mma16816(float c[4], const uint32_t a[4], const uint32_t b[2]) {
    asm volatile(
        "mma.sync.aligned.m16n8k16.row.col.f32.f16.f16.f32 "
        "{%0,%1,%2,%3}, {%4,%5,%6,%7}, {%8,%9}, {%0,%1,%2,%3};\n"
        : "+f"(c[0]), "+f"(c[1]), "+f"(c[2]), "+f"(c[3])
        : "r"(a[0]), "r"(a[1]), "r"(a[2]), "r"(a[3]), "r"(b[0]), "r"(b[1]));
}
#define LDMX4(r0, r1, r2, r3, addr) \
    asm volatile("ldmatrix.sync.aligned.m8n8.x4.shared.b16 {%0,%1,%2,%3}, [%4];" \
        : "=r"(r0), "=r"(r1), "=r"(r2), "=r"(r3) : "r"(addr))

// =======================================================================
// fp16 HMMA GEMM: C[M,N] = A[M,K] @ B[N,K]^T
// EPI: 0 +bias->f32 | 2 +bias+res->f32 | 3 +bias,gelu->fp16
//      4 +bias -> scatter q(scaled)/k/v fp16 [b,h,t,d]
// =======================================================================
#define STAGE_B   20480
#define GSMEM     (2*STAGE_B)

template <int EPI>
__global__ void __launch_bounds__(256, 2) gemm_mma(
    const __half* __restrict__ A, const __half* __restrict__ B,
    const float* __restrict__ bias, const float* __restrict__ Rres,
    float* __restrict__ C, __half* __restrict__ Ch,
    __half* __restrict__ Qo, __half* __restrict__ Ko, __half* __restrict__ Vo,
    int N, int K)
{
    extern __shared__ __align__(16) char dyn[];
    const uint32_t sbase = smem_u32(dyn);
    const int tid = threadIdx.x, lane = tid & 31, warp = tid >> 5;
    const int wm = warp >> 2, wn = warp & 3;
    const int bn = blockIdx.x, bm = blockIdx.y;

    float acc[4][4][4];
#pragma unroll
    for (int i = 0; i < 4; i++)
#pragma unroll
        for (int j = 0; j < 4; j++)
#pragma unroll
            for (int q = 0; q < 4; q++) acc[i][j][q] = 0.f;

    const char* gsrc[2] = {
        (const char*)(A + (size_t)bm * 128 * K),
        (const char*)(B + (size_t)bn * 128 * K) };
    const size_t rs = (size_t)K * 2;

#define LOADT(t_) do { \
    uint32_t db_ = sbase + ((t_) & 1) * STAGE_B; \
    size_t go_ = (size_t)(t_) * 64; \
    _Pragma("unroll") \
    for (int b_ = 0; b_ < 2; b_++) { \
        const char* g_ = gsrc[b_]; \
        uint32_t d_ = db_ + b_ * 10240; \
        _Pragma("unroll") \
        for (int i_ = 0; i_ < 2; i_++) { \
            int idx_ = i_ * 256 + tid; \
            int r_ = idx_ >> 2, c_ = (idx_ & 3) * 16; \
            asm volatile("cp.async.cg.shared.global [%0], [%1], 16;" \
                :: "r"(d_ + r_ * 80 + c_), "l"(g_ + (size_t)r_ * rs + go_ + c_) : "memory"); \
        } \
    } \
    asm volatile("cp.async.commit_group;" ::: "memory"); \
} while (0)

    const int T = K >> 5;
    LOADT(0);
    if (T > 1) LOADT(1);

    for (int t = 0; t < T; t++) {
        if (t + 1 < T) asm volatile("cp.async.wait_group 1;" ::: "memory");
        else           asm volatile("cp.async.wait_group 0;" ::: "memory");
        __syncthreads();
        const uint32_t sb = sbase + (t & 1) * STAGE_B;

#pragma unroll
        for (int ks = 0; ks < 2; ks++) {
            const int k0 = ks * 16;
            uint32_t bf[4][2];
#pragma unroll
            for (int pr = 0; pr < 2; pr++) {
                int trow = wn * 32 + pr * 16 + ((lane >> 4) & 1) * 8 + (lane & 7);
                int tcol = k0 + ((lane >> 3) & 1) * 8;
                uint32_t ab = sb + 10240 + trow * 80 + tcol * 2;
                LDMX4(bf[2*pr][0], bf[2*pr][1], bf[2*pr+1][0], bf[2*pr+1][1], ab);
            }
#pragma unroll
            for (int i = 0; i < 4; i++) {
                int arow = wm * 64 + i * 16 + (lane & 7) + ((lane >> 3) & 1) * 8;
                int acol = k0 + ((lane >> 4) & 1) * 8;
                uint32_t aa = sb + arow * 80 + acol * 2;
                uint32_t a4[4];
                LDMX4(a4[0], a4[1], a4[2], a4[3], aa);
#pragma unroll
                for (int j = 0; j < 4; j++) mma16816(acc[i][j], a4, bf[j]);
            }
        }
        __syncthreads();
        if (t + 2 < T) LOADT(t + 2);
    }

    const float att_scale = 1.0f / sqrtf(64.0f + 1e-8f);

#pragma unroll
    for (int i = 0; i < 4; i++) {
        int row0 = bm * 128 + wm * 64 + i * 16 + (lane >> 2);
#pragma unroll
        for (int j = 0; j < 4; j++) {
            int col = bn * 128 + wn * 32 + j * 8 + (lane & 3) * 2;
            float b0 = bias[col], b1 = bias[col + 1];
#pragma unroll
            for (int half_ = 0; half_ < 2; half_++) {
                int row = row0 + half_ * 8;
                float v0 = acc[i][j][half_ * 2 + 0] + b0;
                float v1 = acc[i][j][half_ * 2 + 1] + b1;
                if (EPI == 4) {
                    int kind = col / 384;
                    int hh = (col % 384) >> 6;
                    int dd = col & 63;
                    int bb = row / NTOK, tt = row % NTOK;
                    size_t o3 = ((size_t)(bb * NHEAD + hh) * NTOK + tt) * 64 + dd;
                    __half2 hv;
                    if (kind == 0) {
                        hv = __floats2half2_rn(v0 * att_scale, v1 * att_scale);
                        *(__half2*)(Qo + o3) = hv;
                    } else if (kind == 1) {
                        hv = __floats2half2_rn(v0, v1);
                        *(__half2*)(Ko + o3) = hv;
                    } else {
                        hv = __floats2half2_rn(v0, v1);
                        *(__half2*)(Vo + o3) = hv;
                    }
                } else if (EPI == 3) {
                    size_t off = (size_t)row * N + col;
                    v0 = gelu_tanh(v0); v1 = gelu_tanh(v1);
                    *(__half2*)((char*)Ch + off * 2) = __floats2half2_rn(v0, v1);
                } else {
                    size_t off = (size_t)row * N + col;
                    if (EPI == 2) {
                        float2 rr = *(const float2*)(Rres + off);
                        v0 += rr.x; v1 += rr.y;
                    }
                    *(float2*)(C + off) = make_float2(v0, v1);
                }
            }
        }
    }
}

// ---------------- weight transpose + fp16 ([K,N] -> [N,K]) ----
__global__ void wprep(const float* __restrict__ W, __half* __restrict__ Wh, int K, int N)
{
    __shared__ float t[32][33];
    const size_t lo = (size_t)blockIdx.z * K * N;
    const float* Wp = W + lo;
    const int kt = blockIdx.y * 32, nt = blockIdx.x * 32;
    const int tx = threadIdx.x, ty = threadIdx.y;
#pragma unroll
    for (int i = ty; i < 32; i += 8)
        t[i][tx] = Wp[(size_t)(kt + i) * N + nt + tx];
    __syncthreads();
#pragma unroll
    for (int i = ty; i < 32; i += 8)
        Wh[lo + (size_t)(nt + i) * K + kt + tx] = __float2half_rn(t[tx][i]);
}

// ---------------- LayerNorm -> fp16 ----------------
__global__ void ln_half(const float* __restrict__ x, const float* __restrict__ w,
                        const float* __restrict__ b, __half* __restrict__ yh)
{
    size_t row = blockIdx.x;
    const float* xr = x + row * D_EMB;
    int tid = threadIdx.x;
    float v0 = xr[tid], v1 = xr[tid + 128], v2 = xr[tid + 256];
    float s = v0 + v1 + v2, sq = v0*v0 + v1*v1 + v2*v2;
#pragma unroll
    for (int o = 16; o; o >>= 1) {
        s  += __shfl_xor_sync(~0u, s,  o);
        sq += __shfl_xor_sync(~0u, sq, o);
    }
    __shared__ float ws[4], wq[4], red[2];
    int warp = tid >> 5, lane = tid & 31;
    if (!lane) { ws[warp] = s; wq[warp] = sq; }
    __syncthreads();
    if (tid == 0) {
        float S = ws[0]+ws[1]+ws[2]+ws[3], Q = wq[0]+wq[1]+wq[2]+wq[3];
        float mean = S * (1.0f / 384.0f);
        red[0] = mean;
        red[1] = rsqrtf(Q * (1.0f / 384.0f) - mean * mean + 1e-5f);
    }
    __syncthreads();
    float mean = red[0], inv = red[1];
    yh[row * D_EMB + tid]       = __float2half_rn((v0 - mean) * inv * w[tid]       + b[tid]);
    yh[row * D_EMB + tid + 128] = __float2half_rn((v1 - mean) * inv * w[tid + 128] + b[tid + 128]);
    yh[row * D_EMB + tid + 256] = __float2half_rn((v2 - mean) * inv * w[tid + 256] + b[tid + 256]);
}

__global__ void lnf_kernel(const float* __restrict__ x, const float* __restrict__ w,
                           const float* __restrict__ b, float* __restrict__ out)
{
    size_t bi = blockIdx.x;
    const float* xr = x + (bi * NTOK + (NTOK - 1)) * D_EMB;
    int tid = threadIdx.x;
    float v0 = xr[tid], v1 = xr[tid + 128], v2 = xr[tid + 256];
    float s = v0 + v1 + v2, sq = v0*v0 + v1*v1 + v2*v2;
#pragma unroll
    for (int o = 16; o; o >>= 1) {
        s  += __shfl_xor_sync(~0u, s,  o);
        sq += __shfl_xor_sync(~0u, sq, o);
    }
    __shared__ float ws[4], wq[4], red[2];
    int warp = tid >> 5, lane = tid & 31;
    if (!lane) { ws[warp] = s; wq[warp] = sq; }
    __syncthreads();
    if (tid == 0) {
        float S = ws[0]+ws[1]+ws[2]+ws[3], Q = wq[0]+wq[1]+wq[2]+wq[3];
        float mean = S * (1.0f / 384.0f);
        red[0] = mean;
        red[1] = rsqrtf(Q * (1.0f / 384.0f) - mean * mean + 1e-5f);
    }
    __syncthreads();
    float mean = red[0], inv = red[1];
    out[bi * D_EMB + tid]       = (v0 - mean) * inv * w[tid]       + b[tid];
    out[bi * D_EMB + tid + 128] = (v1 - mean) * inv * w[tid + 128] + b[tid + 128];
    out[bi * D_EMB + tid + 256] = (v2 - mean) * inv * w[tid + 256] + b[tid + 256];
}

// ---------------- Flash attention on HMMA (fp32 softmax) ----------------
// Per (b,h) block: Q[304][72], K[320][72], Vt[64][328] fp16 in smem.
// 8 warps; warp handles 16-query tiles (19 tiles); online softmax over
// 5 chunks of 64 keys. P repacked register-only into A fragments.
#define QPAD 304
#define KPAD 320
#define KSTR 72
#define VSTR 328
#define ATT_SMEM_HALVES (QPAD*KSTR + KPAD*KSTR + 64*VSTR)
#define ATT_SMEM_BYTES  (ATT_SMEM_HALVES * 2)

__global__ void __launch_bounds__(256) attn_mma(
    const __half* __restrict__ Qb, const __half* __restrict__ Kb,
    const __half* __restrict__ Vb, __half* __restrict__ oh)
{
    extern __shared__ __half smh[];
    __half* Qs = smh;
    __half* Ks = Qs + QPAD * KSTR;
    __half* Vt = Ks + KPAD * KSTR;

    const int bh = blockIdx.x;
    const int b = bh / NHEAD, h = bh % NHEAD;
    const int tid = threadIdx.x, warp = tid >> 5, lane = tid & 31;
    const size_t ib = (size_t)bh * NTOK * 64;

    // zero whole smem, then fill
    for (int i = tid; i < ATT_SMEM_HALVES / 8; i += 256)
        ((int4*)smh)[i] = make_int4(0, 0, 0, 0);
    __syncthreads();
    for (int idx = tid; idx < NTOK * 8; idx += 256) {
        int t = idx >> 3, s = idx & 7;
        ((int4*)(Qs + t * KSTR))[s] = ((const int4*)(Qb + ib + (size_t)t * 64))[s];
        ((int4*)(Ks + t * KSTR))[s] = ((const int4*)(Kb + ib + (size_t)t * 64))[s];
    }
    for (int idx = tid; idx < NTOK * 64; idx += 256) {
        int t = idx >> 6, d = idx & 63;
        Vt[d * VSTR + t] = Vb[ib + idx];
    }
    __syncthreads();

    const uint32_t qs0 = smem_u32(Qs), ks0 = smem_u32(Ks), vt0 = smem_u32(Vt);

    for (int tile = warp; tile < 19; tile += 8) {
        // ---- Q fragments (4 k-steps) ----
        uint32_t qf[4][4];
        {
            int ar = tile * 16 + (lane & 7) + ((lane >> 3) & 1) * 8;
#pragma unroll
            for (int ks = 0; ks < 4; ks++) {
                int ac = ks * 16 + ((lane >> 4) & 1) * 8;
                uint32_t ad = qs0 + (ar * KSTR + ac) * 2;
                LDMX4(qf[ks][0], qf[ks][1], qf[ks][2], qf[ks][3], ad);
            }
        }
        float O[8][4];
#pragma unroll
        for (int j = 0; j < 8; j++)
#pragma unroll
            for (int q = 0; q < 4; q++) O[j][q] = 0.f;
        float mr0 = -1e30f, mr1 = -1e30f, lr0 = 0.f, lr1 = 0.f;

        for (int ch = 0; ch < 5; ch++) {
            float S[8][4];
#pragma unroll
            for (int j = 0; j < 8; j++)
#pragma unroll
                for (int q = 0; q < 4; q++) S[j][q] = 0.f;

            // ---- S = Q @ K^T for this 64-key chunk ----
#pragma unroll
            for (int ks = 0; ks < 4; ks++) {
#pragma unroll
                for (int kg = 0; kg < 4; kg++) {
                    int trow = ch * 64 + kg * 16 + ((lane >> 4) & 1) * 8 + (lane & 7);
                    int tcol = ks * 16 + ((lane >> 3) & 1) * 8;
                    uint32_t ad = ks0 + (trow * KSTR + tcol) * 2;
                    uint32_t bfr[4];
                    LDMX4(bfr[0], bfr[1], bfr[2], bfr[3], ad);
                    mma16816(S[kg * 2],     qf[ks], bfr);
                    mma16816(S[kg * 2 + 1], qf[ks], bfr + 2);
                }
            }

            // ---- mask + row max ----
            float cm0 = -1e30f, cm1 = -1e30f;
#pragma unroll
            for (int j = 0; j < 8; j++) {
                int k0c = ch * 64 + j * 8 + (lane & 3) * 2;
                if (k0c >= NTOK)     { S[j][0] = -1e30f; S[j][2] = -1e30f; }
                if (k0c + 1 >= NTOK) { S[j][1] = -1e30f; S[j][3] = -1e30f; }
                cm0 = fmaxf(cm0, fmaxf(S[j][0], S[j][1]));
                cm1 = fmaxf(cm1, fmaxf(S[j][2], S[j][3]));
            }
            cm0 = fmaxf(cm0, __shfl_xor_sync(~0u, cm0, 1));
            cm0 = fmaxf(cm0, __shfl_xor_sync(~0u, cm0, 2));
            cm1 = fmaxf(cm1, __shfl_xor_sync(~0u, cm1, 1));
            cm1 = fmaxf(cm1, __shfl_xor_sync(~0u, cm1, 2));

            float mn0 = fmaxf(mr0, cm0), mn1 = fmaxf(mr1, cm1);
            float sc0 = __expf(mr0 - mn0), sc1 = __expf(mr1 - mn1);

            // ---- exp, P fragments (register repack), chunk sums ----
            float cs0 = 0.f, cs1 = 0.f;
            uint32_t pf[4][4];
#pragma unroll
            for (int j = 0; j < 8; j++) {
                float e0 = __expf(S[j][0] - mn0), e1 = __expf(S[j][1] - mn0);
                float e2 = __expf(S[j][2] - mn1), e3 = __expf(S[j][3] - mn1);
                cs0 += e0 + e1; cs1 += e2 + e3;
                __half2 p01 = __floats2half2_rn(e0, e1);
                __half2 p23 = __floats2half2_rn(e2, e3);
                int jg = j >> 1, sl = (j & 1) * 2;
                pf[jg][sl]     = reinterpret_cast<uint32_t&>(p01);
                pf[jg][sl + 1] = reinterpret_cast<uint32_t&>(p23);
            }
            cs0 += __shfl_xor_sync(~0u, cs0, 1); cs0 += __shfl_xor_sync(~0u, cs0, 2);
            cs1 += __shfl_xor_sync(~0u, cs1, 1); cs1 += __shfl_xor_sync(~0u, cs1, 2);
            lr0 = lr0 * sc0 + cs0; lr1 = lr1 * sc1 + cs1;
            mr0 = mn0; mr1 = mn1;
#pragma unroll
            for (int j = 0; j < 8; j++) {
                O[j][0] *= sc0; O[j][1] *= sc0; O[j][2] *= sc1; O[j][3] *= sc1;
            }

            // ---- O += P @ V^T ----
#pragma unroll
            for (int jg = 0; jg < 4; jg++) {
#pragma unroll
                for (int dg = 0; dg < 4; dg++) {
                    int trow = dg * 16 + ((lane >> 4) & 1) * 8 + (lane & 7);
                    int tcol = ch * 64 + jg * 16 + ((lane >> 3) & 1) * 8;
                    uint32_t ad = vt0 + (trow * VSTR + tcol) * 2;
                    uint32_t bfr[4];
                    LDMX4(bfr[0], bfr[1], bfr[2], bfr[3], ad);
                    mma16816(O[dg * 2],     pf[jg], bfr);
                    mma16816(O[dg * 2 + 1], pf[jg], bfr + 2);
                }
            }
        }

        // ---- normalize + store ----
        float inv0 = 1.0f / lr0, inv1 = 1.0f / lr1;
        int r0 = tile * 16 + (lane >> 2), r1 = r0 + 8;
#pragma unroll
        for (int j = 0; j < 8; j++) {
            int d = j * 8 + (lane & 3) * 2;
            if (r0 < NTOK) {
                __half2 hv = (r0 == NTOK - 1)
                    ? *(const __half2*)(Vb + ib + (size_t)(NTOK - 1) * 64 + d)
                    : __floats2half2_rn(O[j][0] * inv0, O[j][1] * inv0);
                *(__half2*)(oh + ((size_t)b * NTOK + r0) * D_EMB + h * 64 + d) = hv;
            }
            if (r1 < NTOK) {
                __half2 hv = (r1 == NTOK - 1)
                    ? *(const __half2*)(Vb + ib + (size_t)(NTOK - 1) * 64 + d)
                    : __floats2half2_rn(O[j][2] * inv1, O[j][3] * inv1);
                *(__half2*)(oh + ((size_t)b * NTOK + r1) * D_EMB + h * 64 + d) = hv;
            }
        }
    }
}

// ---------------- tokenizers ----------------
__global__ void st_kernel(const float* __restrict__ as, const float* __restrict__ w1,
                          const float* __restrict__ b1, const float* __restrict__ w2,
                          const float* __restrict__ b2, float* __restrict__ st)
{
    __shared__ float h1[32];
    int bt = blockIdx.x;
    int tid = threadIdx.x;
    float s0 = as[bt * 2], s1 = as[bt * 2 + 1];
    if (tid < 32) {
        float v = b1[tid] + s0 * w1[tid] + s1 * w1[32 + tid];
        h1[tid] = v > 0.f ? v : 0.f;
    }
    __syncthreads();
    float acc = b2[tid];
#pragma unroll
    for (int k = 0; k < 32; k++) acc = fmaf(h1[k], w2[k * 384 + tid], acc);
    st[(size_t)bt * 384 + tid] = acc;
}

__global__ void im2col_kernel(const float* __restrict__ img, __half* __restrict__ ph)
{
    int idx = blockIdx.x * 256 + threadIdx.x;
    int f = idx % 192;
    int rem = idx / 192;
    int pidx = rem % 144;
    int bt = rem / 144;
    int pr = f / 24, pc = (f % 24) / 3, c = f % 3;
    int hp = pidx / 12, wp = pidx % 12;
    ph[idx] = __float2half_rn(img[(((size_t)bt * 3 + c) * 96 + hp * 8 + pr) * 96 + wp * 8 + pc]);
}

__global__ void assemble_kernel(const float* __restrict__ imgtok, const float* __restrict__ st,
                                const float* __restrict__ readout, const float* __restrict__ pos,
                                const float* __restrict__ img_temb, const float* __restrict__ st_temb,
                                float* __restrict__ x)
{
    int idx = blockIdx.x * 256 + threadIdx.x;
    int d = idx % 384;
    int rem = idx / 384;
    int tok = rem % NTOK;
    int b = rem / NTOK;
    float v;
    if (tok == NTOK - 1) {
        v = readout[d];
    } else {
        int t = tok / 145, r = tok % 145;
        if (r == 0) v = st[((size_t)(b * 2 + t)) * 384 + d] + st_temb[t * 384 + d];
        else        v = imgtok[((size_t)(b * 2 + t) * 144 + (r - 1)) * 384 + d] + img_temb[t * 384 + d];
    }
    x[idx] = v + pos[tok * 384 + d];
}

// ---------------- launch ----------------
extern "C" void kernel_launch(void* const* d_in, const int* in_sizes, int n_in,
                              void* d_out, int out_size)
{
    const float* images      = (const float*)d_in[0];
    const float* agent_state = (const float*)d_in[1];
    const float* img_proj_w  = (const float*)d_in[2];
    const float* img_proj_b  = (const float*)d_in[3];
    const float* img_temb    = (const float*)d_in[4];
    const float* st_w1       = (const float*)d_in[5];
    const float* st_b1       = (const float*)d_in[6];
    const float* st_w2       = (const float*)d_in[7];
    const float* st_b2       = (const float*)d_in[8];
    const float* st_temb     = (const float*)d_in[9];
    const float* readout     = (const float*)d_in[10];
    const float* pos         = (const float*)d_in[11];
    const float* ln1_w       = (const float*)d_in[12];
    const float* ln1_b       = (const float*)d_in[13];
    const float* attn_w      = (const float*)d_in[14];
    const float* attn_b      = (const float*)d_in[15];
    const float* proj_w      = (const float*)d_in[16];
    const float* proj_b      = (const float*)d_in[17];
    const float* ln2_w       = (const float*)d_in[18];
    const float* ln2_b       = (const float*)d_in[19];
    const float* fc_w        = (const float*)d_in[20];
    const float* fc_b        = (const float*)d_in[21];
    const float* fc2_w       = (const float*)d_in[22];
    const float* fc2_b       = (const float*)d_in[23];
    const float* lnf_w       = (const float*)d_in[24];
    const float* lnf_b       = (const float*)d_in[25];
    float* out = (float*)d_out;

    float *x, *att, *st;
    __half *yh, *ah, *bhp, *ph, *qb, *kb, *vb, *wq, *wp, *w1, *w2, *wi;
    cudaGetSymbolAddress((void**)&x,   g_x);
    cudaGetSymbolAddress((void**)&att, g_att);
    cudaGetSymbolAddress((void**)&st,  g_st);
    cudaGetSymbolAddress((void**)&yh,  g_yh);
    cudaGetSymbolAddress((void**)&ah,  g_ah);
    cudaGetSymbolAddress((void**)&bhp, g_bh);
    cudaGetSymbolAddress((void**)&ph,  g_ph);
    cudaGetSymbolAddress((void**)&qb,  g_q);
    cudaGetSymbolAddress((void**)&kb,  g_k);
    cudaGetSymbolAddress((void**)&vb,  g_v);
    cudaGetSymbolAddress((void**)&wq,  g_wq);
    cudaGetSymbolAddress((void**)&wp,  g_wp);
    cudaGetSymbolAddress((void**)&w1,  g_w1);
    cudaGetSymbolAddress((void**)&w2,  g_w2);
    cudaGetSymbolAddress((void**)&wi,  g_wi);

    cudaFuncSetAttribute(attn_mma, cudaFuncAttributeMaxDynamicSharedMemorySize, ATT_SMEM_BYTES);
    cudaFuncSetAttribute(gemm_mma<0>, cudaFuncAttributeMaxDynamicSharedMemorySize, GSMEM);
    cudaFuncSetAttribute(gemm_mma<2>, cudaFuncAttributeMaxDynamicSharedMemorySize, GSMEM);
    cudaFuncSetAttribute(gemm_mma<3>, cudaFuncAttributeMaxDynamicSharedMemorySize, GSMEM);
    cudaFuncSetAttribute(gemm_mma<4>, cudaFuncAttributeMaxDynamicSharedMemorySize, GSMEM);

    // ---- weight prep ----
    wprep<<<dim3(1152/32, 384/32, 12), dim3(32, 8)>>>(attn_w, wq, 384, 1152);
    wprep<<<dim3(384/32,  384/32, 12), dim3(32, 8)>>>(proj_w, wp, 384, 384);
    wprep<<<dim3(1536/32, 384/32, 12), dim3(32, 8)>>>(fc_w,  w1, 384, 1536);
    wprep<<<dim3(384/32, 1536/32, 12), dim3(32, 8)>>>(fc2_w, w2, 1536, 384);
    wprep<<<dim3(384/32,  192/32, 1),  dim3(32, 8)>>>(img_proj_w, wi, 192, 384);

    // ---- tokenizers ----
    st_kernel<<<BATCH * OBS_H, 384>>>(agent_state, st_w1, st_b1, st_w2, st_b2, st);
    im2col_kernel<<<(M_PATCH * PK) / 256, 256>>>(images, ph);
    gemm_mma<0><<<dim3(3, M_PATCH / 128), 256, GSMEM>>>(
        ph, wi, img_proj_b, nullptr, att, nullptr, nullptr, nullptr, nullptr, 384, PK);
    assemble_kernel<<<(M_TOK * D_EMB) / 256, 256>>>(att, st, readout, pos, img_temb, st_temb, x);

    // ---- transformer layers ----
    for (int l = 0; l < NLAYER; l++) {
        ln_half<<<M_TOK, 128>>>(x, ln1_w + l * 384, ln1_b + l * 384, yh);
        gemm_mma<4><<<dim3(9, NTOK), 256, GSMEM>>>(
            yh, wq + (size_t)l * 1152 * 384, attn_b + l * 1152, nullptr,
            nullptr, nullptr, qb, kb, vb, 1152, 384);
        attn_mma<<<BATCH * NHEAD, 256, ATT_SMEM_BYTES>>>(qb, kb, vb, ah);
        gemm_mma<2><<<dim3(3, NTOK), 256, GSMEM>>>(
            ah, wp + (size_t)l * 384 * 384, proj_b + l * 384, x,
            x, nullptr, nullptr, nullptr, nullptr, 384, 384);
        ln_half<<<M_TOK, 128>>>(x, ln2_w + l * 384, ln2_b + l * 384, yh);
        gemm_mma<3><<<dim3(12, NTOK), 256, GSMEM>>>(
            yh, w1 + (size_t)l * 1536 * 384, fc_b + l * 1536, nullptr,
            nullptr, bhp, nullptr, nullptr, nullptr, 1536, 384);
        gemm_mma<2><<<dim3(3, NTOK), 256, GSMEM>>>(
            bhp, w2 + (size_t)l * 384 * 1536, fc2_b + l * 384, x,
            x, nullptr, nullptr, nullptr, nullptr, 384, 1536);
    }

    lnf_kernel<<<BATCH, 128>>>(x, lnf_w, lnf_b, out);
}

// round 8
// speedup vs baseline: 6.1635x; 1.0099x over previous
#include <cuda_runtime.h>
#include <cuda_fp16.h>
#include <math.h>
#include <stdint.h>

// ---------------- problem constants ----------------
#define BATCH   128
#define OBS_H   2
#define NTOK    291
#define M_TOK   (BATCH*NTOK)   // 37248 = 291*128
#define D_EMB   384
#define NHEAD   6
#define NLAYER  12
#define N_IMG   144
#define PK      192
#define M_PATCH (BATCH*OBS_H*N_IMG)

// ---------------- scratch ----------------
__device__ float g_x  [M_TOK * D_EMB];
__device__ float g_att[M_PATCH * D_EMB];
__device__ float g_st [BATCH * OBS_H * D_EMB];
__device__ float2 g_s0[M_TOK];                 // row stats {sum, sumsq}
__device__ float2 g_s1[M_TOK];
__device__ __half g_xh[M_TOK*384];             // fp16 copy of residual x
__device__ __half g_ah[M_TOK*384];             // attn out fp16
__device__ __half g_bh[M_TOK*1536];            // fc1 out fp16
__device__ __half g_ph[M_PATCH*192];           // patches fp16
__device__ __half g_q [BATCH*NHEAD*NTOK*64];
__device__ __half g_k [BATCH*NHEAD*NTOK*64];
__device__ __half g_v [BATCH*NHEAD*NTOK*64];
// transposed weights [N,K] fp16 (qkv/fc1 have ln-g folded in)
__device__ __half g_wq[12*1152*384];
__device__ __half g_wp[12*384*384];
__device__ __half g_w1[12*1536*384];
__device__ __half g_w2[12*384*1536];
__device__ __half g_wi[384*192];
// LN-fusion vectors: u = g@W, c = b@W + bias
__device__ float g_uq[12*1152], g_cq[12*1152];
__device__ float g_u1[12*1536], g_c1[12*1536];

__device__ __forceinline__ float gelu_tanh(float v) {
    const float c = 0.7978845608028654f;
    float u = c * (v + 0.044715f * v * v * v);
    return 0.5f * v * (1.0f + tanhf(u));
}

__device__ __forceinline__ uint32_t smem_u32(const void* p) {
    uint32_t a;
    asm("{ .reg .u64 t; cvta.to.shared.u64 t, %1; cvt.u32.u64 %0, t; }" : "=r"(a) : "l"(p));
    return a;
}

__device__ __forceinline__ void mma16816(float c[4], const uint32_t a[4], const uint32_t b[2]) {
    asm volatile(
        "mma.sync.aligned.m16n8k16.row.col.f32.f16.f16.f32 "
        "{%0,%1,%2,%3}, {%4,%5,%6,%7}, {%8,%9}, {%0,%1,%2,%3};\n"
        : "+f"(c[0]), "+f"(c[1]), "+f"(c[2]), "+f"(c[3])
        : "r"(a[0]), "r"(a[1]), "r"(a[2]), "r"(a[3]), "r"(b[0]), "r"(b[1]));
}
#define LDMX4(r0, r1, r2, r3, addr) \
    asm volatile("ldmatrix.sync.aligned.m8n8.x4.shared.b16 {%0,%1,%2,%3}, [%4];" \
        : "=r"(r0), "=r"(r1), "=r"(r2), "=r"(r3) : "r"(addr))

// =======================================================================
// fp16 HMMA GEMM: C[M,N] = A[M,K] @ B[N,K]^T
// EPI 0: +bias -> f32 C                       (img proj)
// EPI 4: LN-fused epi -> scatter q/k/v fp16   (qkv; A = raw xh)
// EPI 3: LN-fused epi + gelu -> fp16 Ch       (fc1; A = raw xh)
// EPI 5: +bias + residual -> f32 C, fp16 XH, row-stats atomics (proj/fc2)
// =======================================================================
#define STAGE_B   20480
#define GSMEM     (2*STAGE_B)

template <int EPI>
__global__ void __launch_bounds__(256, 2) gemm_mma(
    const __half* __restrict__ A, const __half* __restrict__ B,
    const float* __restrict__ bias, const float* __restrict__ Rres,
    float* __restrict__ C, __half* __restrict__ Ch,
    __half* __restrict__ Qo, __half* __restrict__ Ko, __half* __restrict__ Vo,
    const float2* __restrict__ stats_in, float2* __restrict__ stats_out,
    const float* __restrict__ uvec, __half* __restrict__ XH,
    int N, int K)
{
    extern __shared__ __align__(16) char dyn[];
    const uint32_t sbase = smem_u32(dyn);
    const int tid = threadIdx.x, lane = tid & 31, warp = tid >> 5;
    const int wm = warp >> 2, wn = warp & 3;
    const int bn = blockIdx.x, bm = blockIdx.y;

    float acc[4][4][4];
#pragma unroll
    for (int i = 0; i < 4; i++)
#pragma unroll
        for (int j = 0; j < 4; j++)
#pragma unroll
            for (int q = 0; q < 4; q++) acc[i][j][q] = 0.f;

    const char* gsrc[2] = {
        (const char*)(A + (size_t)bm * 128 * K),
        (const char*)(B + (size_t)bn * 128 * K) };
    const size_t rs = (size_t)K * 2;

#define LOADT(t_) do { \
    uint32_t db_ = sbase + ((t_) & 1) * STAGE_B; \
    size_t go_ = (size_t)(t_) * 64; \
    _Pragma("unroll") \
    for (int b_ = 0; b_ < 2; b_++) { \
        const char* g_ = gsrc[b_]; \
        uint32_t d_ = db_ + b_ * 10240; \
        _Pragma("unroll") \
        for (int i_ = 0; i_ < 2; i_++) { \
            int idx_ = i_ * 256 + tid; \
            int r_ = idx_ >> 2, c_ = (idx_ & 3) * 16; \
            asm volatile("cp.async.cg.shared.global [%0], [%1], 16;" \
                :: "r"(d_ + r_ * 80 + c_), "l"(g_ + (size_t)r_ * rs + go_ + c_) : "memory"); \
        } \
    } \
    asm volatile("cp.async.commit_group;" ::: "memory"); \
} while (0)

    const int T = K >> 5;
    LOADT(0);
    if (T > 1) LOADT(1);

    for (int t = 0; t < T; t++) {
        if (t + 1 < T) asm volatile("cp.async.wait_group 1;" ::: "memory");
        else           asm volatile("cp.async.wait_group 0;" ::: "memory");
        __syncthreads();
        const uint32_t sb = sbase + (t & 1) * STAGE_B;

#pragma unroll
        for (int ks = 0; ks < 2; ks++) {
            const int k0 = ks * 16;
            uint32_t bf[4][2];
#pragma unroll
            for (int pr = 0; pr < 2; pr++) {
                int trow = wn * 32 + pr * 16 + ((lane >> 4) & 1) * 8 + (lane & 7);
                int tcol = k0 + ((lane >> 3) & 1) * 8;
                uint32_t ab = sb + 10240 + trow * 80 + tcol * 2;
                LDMX4(bf[2*pr][0], bf[2*pr][1], bf[2*pr+1][0], bf[2*pr+1][1], ab);
            }
#pragma unroll
            for (int i = 0; i < 4; i++) {
                int arow = wm * 64 + i * 16 + (lane & 7) + ((lane >> 3) & 1) * 8;
                int acol = k0 + ((lane >> 4) & 1) * 8;
                uint32_t aa = sb + arow * 80 + acol * 2;
                uint32_t a4[4];
                LDMX4(a4[0], a4[1], a4[2], a4[3], aa);
#pragma unroll
                for (int j = 0; j < 4; j++) mma16816(acc[i][j], a4, bf[j]);
            }
        }
        __syncthreads();
        if (t + 2 < T) LOADT(t + 2);
    }

    const float att_scale = 1.0f / sqrtf(64.0f + 1e-8f);

#pragma unroll
    for (int i = 0; i < 4; i++) {
        int row0 = bm * 128 + wm * 64 + i * 16 + (lane >> 2);
#pragma unroll
        for (int half_ = 0; half_ < 2; half_++) {
            int row = row0 + half_ * 8;
            // LN-fused epilogues need per-row mean / inv-sigma
            float mu = 0.f, inv = 1.f;
            if (EPI == 3 || EPI == 4) {
                float2 st = stats_in[row];
                mu = st.x * (1.0f / 384.0f);
                inv = rsqrtf(st.y * (1.0f / 384.0f) - mu * mu + 1e-5f);
            }
            float rsum = 0.f, rsq = 0.f;
#pragma unroll
            for (int j = 0; j < 4; j++) {
                int col = bn * 128 + wn * 32 + j * 8 + (lane & 3) * 2;
                float a0 = acc[i][j][half_ * 2 + 0];
                float a1 = acc[i][j][half_ * 2 + 1];
                if (EPI == 0) {
                    size_t off = (size_t)row * N + col;
                    *(float2*)(C + off) = make_float2(a0 + bias[col], a1 + bias[col + 1]);
                } else if (EPI == 4) {
                    float v0 = inv * (a0 - mu * uvec[col])     + bias[col];
                    float v1 = inv * (a1 - mu * uvec[col + 1]) + bias[col + 1];
                    int kind = col / 384;
                    int hh = (col % 384) >> 6;
                    int dd = col & 63;
                    int bb = row / NTOK, tt = row % NTOK;
                    size_t o3 = ((size_t)(bb * NHEAD + hh) * NTOK + tt) * 64 + dd;
                    if (kind == 0)
                        *(__half2*)(Qo + o3) = __floats2half2_rn(v0 * att_scale, v1 * att_scale);
                    else if (kind == 1)
                        *(__half2*)(Ko + o3) = __floats2half2_rn(v0, v1);
                    else
                        *(__half2*)(Vo + o3) = __floats2half2_rn(v0, v1);
                } else if (EPI == 3) {
                    float v0 = gelu_tanh(inv * (a0 - mu * uvec[col])     + bias[col]);
                    float v1 = gelu_tanh(inv * (a1 - mu * uvec[col + 1]) + bias[col + 1]);
                    size_t off = (size_t)row * N + col;
                    *(__half2*)((char*)Ch + off * 2) = __floats2half2_rn(v0, v1);
                } else { // EPI == 5
                    size_t off = (size_t)row * N + col;
                    float2 rr = *(const float2*)(Rres + off);
                    float v0 = a0 + bias[col]     + rr.x;
                    float v1 = a1 + bias[col + 1] + rr.y;
                    *(float2*)(C + off) = make_float2(v0, v1);
                    *(__half2*)((char*)XH + off * 2) = __floats2half2_rn(v0, v1);
                    rsum += v0 + v1;
                    rsq  += v0 * v0 + v1 * v1;
                }
            }
            if (EPI == 5) {
                // reduce over the 4 lanes covering this row (lane&3)
                rsum += __shfl_xor_sync(~0u, rsum, 1); rsum += __shfl_xor_sync(~0u, rsum, 2);
                rsq  += __shfl_xor_sync(~0u, rsq, 1);  rsq  += __shfl_xor_sync(~0u, rsq, 2);
                if ((lane & 3) == 0) {
                    atomicAdd(&stats_out[row].x, rsum);
                    atomicAdd(&stats_out[row].y, rsq);
                }
            }
        }
    }
}

// ---------------- weight transpose + fp16, optional g-fold ----
__global__ void wprep(const float* __restrict__ W, const float* __restrict__ g,
                      __half* __restrict__ Wh, int K, int N)
{
    __shared__ float t[32][33];
    const int l = blockIdx.z;
    const size_t lo = (size_t)l * K * N;
    const float* Wp = W + lo;
    const int kt = blockIdx.y * 32, nt = blockIdx.x * 32;
    const int tx = threadIdx.x, ty = threadIdx.y;
#pragma unroll
    for (int i = ty; i < 32; i += 8)
        t[i][tx] = Wp[(size_t)(kt + i) * N + nt + tx];
    __syncthreads();
    float gk = g ? g[l * K + kt + tx] : 1.0f;
#pragma unroll
    for (int i = ty; i < 32; i += 8)
        Wh[lo + (size_t)(nt + i) * K + kt + tx] = __float2half_rn(t[tx][i] * gk);
}

// ---------------- LN-fusion u/c prep: u = g@W, c = b@W + bias ----
__global__ void prep_uc(const float* __restrict__ W, const float* __restrict__ g,
                        const float* __restrict__ b, const float* __restrict__ bias,
                        float* __restrict__ u, float* __restrict__ c, int N)
{
    const int l = blockIdx.y;
    const int n = blockIdx.x * 128 + threadIdx.x;
    const float* Wp = W + (size_t)l * 384 * N + n;
    const float* gp = g + l * 384;
    const float* bp = b + l * 384;
    float su = 0.f, sc = 0.f;
    for (int k = 0; k < 384; k++) {
        float w = Wp[(size_t)k * N];
        su = fmaf(gp[k], w, su);
        sc = fmaf(bp[k], w, sc);
    }
    u[l * N + n] = su;
    c[l * N + n] = sc + bias[l * N + n];
}

__global__ void zero_stats(float2* __restrict__ st)
{
    int i = blockIdx.x * 256 + threadIdx.x;
    if (i < M_TOK) st[i] = make_float2(0.f, 0.f);
}

__global__ void lnf_kernel(const float* __restrict__ x, const float* __restrict__ w,
                           const float* __restrict__ b, float* __restrict__ out)
{
    size_t bi = blockIdx.x;
    const float* xr = x + (bi * NTOK + (NTOK - 1)) * D_EMB;
    int tid = threadIdx.x;
    float v0 = xr[tid], v1 = xr[tid + 128], v2 = xr[tid + 256];
    float s = v0 + v1 + v2, sq = v0*v0 + v1*v1 + v2*v2;
#pragma unroll
    for (int o = 16; o; o >>= 1) {
        s  += __shfl_xor_sync(~0u, s,  o);
        sq += __shfl_xor_sync(~0u, sq, o);
    }
    __shared__ float ws[4], wq[4], red[2];
    int warp = tid >> 5, lane = tid & 31;
    if (!lane) { ws[warp] = s; wq[warp] = sq; }
    __syncthreads();
    if (tid == 0) {
        float S = ws[0]+ws[1]+ws[2]+ws[3], Q = wq[0]+wq[1]+wq[2]+wq[3];
        float mean = S * (1.0f / 384.0f);
        red[0] = mean;
        red[1] = rsqrtf(Q * (1.0f / 384.0f) - mean * mean + 1e-5f);
    }
    __syncthreads();
    float mean = red[0], inv = red[1];
    out[bi * D_EMB + tid]       = (v0 - mean) * inv * w[tid]       + b[tid];
    out[bi * D_EMB + tid + 128] = (v1 - mean) * inv * w[tid + 128] + b[tid + 128];
    out[bi * D_EMB + tid + 256] = (v2 - mean) * inv * w[tid + 256] + b[tid + 256];
}

// ---------------- Flash attention on HMMA (fp32 softmax) ----------------
#define QPAD 304
#define KPAD 320
#define KSTR 72
#define VSTR 328
#define ATT_SMEM_HALVES (QPAD*KSTR + KPAD*KSTR + 64*VSTR)
#define ATT_SMEM_BYTES  (ATT_SMEM_HALVES * 2)

__global__ void __launch_bounds__(256) attn_mma(
    const __half* __restrict__ Qb, const __half* __restrict__ Kb,
    const __half* __restrict__ Vb, __half* __restrict__ oh)
{
    extern __shared__ __half smh[];
    __half* Qs = smh;
    __half* Ks = Qs + QPAD * KSTR;
    __half* Vt = Ks + KPAD * KSTR;

    const int bh = blockIdx.x;
    const int b = bh / NHEAD, h = bh % NHEAD;
    const int tid = threadIdx.x, warp = tid >> 5, lane = tid & 31;
    const size_t ib = (size_t)bh * NTOK * 64;

    for (int i = tid; i < ATT_SMEM_HALVES / 8; i += 256)
        ((int4*)smh)[i] = make_int4(0, 0, 0, 0);
    __syncthreads();
    for (int idx = tid; idx < NTOK * 8; idx += 256) {
        int t = idx >> 3, s = idx & 7;
        ((int4*)(Qs + t * KSTR))[s] = ((const int4*)(Qb + ib + (size_t)t * 64))[s];
        ((int4*)(Ks + t * KSTR))[s] = ((const int4*)(Kb + ib + (size_t)t * 64))[s];
    }
    for (int idx = tid; idx < NTOK * 64; idx += 256) {
        int t = idx >> 6, d = idx & 63;
        Vt[d * VSTR + t] = Vb[ib + idx];
    }
    __syncthreads();

    const uint32_t qs0 = smem_u32(Qs), ks0 = smem_u32(Ks), vt0 = smem_u32(Vt);

    for (int tile = warp; tile < 19; tile += 8) {
        uint32_t qf[4][4];
        {
            int ar = tile * 16 + (lane & 7) + ((lane >> 3) & 1) * 8;
#pragma unroll
            for (int ks = 0; ks < 4; ks++) {
                int ac = ks * 16 + ((lane >> 4) & 1) * 8;
                uint32_t ad = qs0 + (ar * KSTR + ac) * 2;
                LDMX4(qf[ks][0], qf[ks][1], qf[ks][2], qf[ks][3], ad);
            }
        }
        float O[8][4];
#pragma unroll
        for (int j = 0; j < 8; j++)
#pragma unroll
            for (int q = 0; q < 4; q++) O[j][q] = 0.f;
        float mr0 = -1e30f, mr1 = -1e30f, lr0 = 0.f, lr1 = 0.f;

        for (int ch = 0; ch < 5; ch++) {
            float S[8][4];
#pragma unroll
            for (int j = 0; j < 8; j++)
#pragma unroll
                for (int q = 0; q < 4; q++) S[j][q] = 0.f;

#pragma unroll
            for (int ks = 0; ks < 4; ks++) {
#pragma unroll
                for (int kg = 0; kg < 4; kg++) {
                    int trow = ch * 64 + kg * 16 + ((lane >> 4) & 1) * 8 + (lane & 7);
                    int tcol = ks * 16 + ((lane >> 3) & 1) * 8;
                    uint32_t ad = ks0 + (trow * KSTR + tcol) * 2;
                    uint32_t bfr[4];
                    LDMX4(bfr[0], bfr[1], bfr[2], bfr[3], ad);
                    mma16816(S[kg * 2],     qf[ks], bfr);
                    mma16816(S[kg * 2 + 1], qf[ks], bfr + 2);
                }
            }

            float cm0 = -1e30f, cm1 = -1e30f;
#pragma unroll
            for (int j = 0; j < 8; j++) {
                int k0c = ch * 64 + j * 8 + (lane & 3) * 2;
                if (k0c >= NTOK)     { S[j][0] = -1e30f; S[j][2] = -1e30f; }
                if (k0c + 1 >= NTOK) { S[j][1] = -1e30f; S[j][3] = -1e30f; }
                cm0 = fmaxf(cm0, fmaxf(S[j][0], S[j][1]));
                cm1 = fmaxf(cm1, fmaxf(S[j][2], S[j][3]));
            }
            cm0 = fmaxf(cm0, __shfl_xor_sync(~0u, cm0, 1));
            cm0 = fmaxf(cm0, __shfl_xor_sync(~0u, cm0, 2));
            cm1 = fmaxf(cm1, __shfl_xor_sync(~0u, cm1, 1));
            cm1 = fmaxf(cm1, __shfl_xor_sync(~0u, cm1, 2));

            float mn0 = fmaxf(mr0, cm0), mn1 = fmaxf(mr1, cm1);
            float sc0 = __expf(mr0 - mn0), sc1 = __expf(mr1 - mn1);

            float cs0 = 0.f, cs1 = 0.f;
            uint32_t pf[4][4];
#pragma unroll
            for (int j = 0; j < 8; j++) {
                float e0 = __expf(S[j][0] - mn0), e1 = __expf(S[j][1] - mn0);
                float e2 = __expf(S[j][2] - mn1), e3 = __expf(S[j][3] - mn1);
                cs0 += e0 + e1; cs1 += e2 + e3;
                __half2 p01 = __floats2half2_rn(e0, e1);
                __half2 p23 = __floats2half2_rn(e2, e3);
                int jg = j >> 1, sl = (j & 1) * 2;
                pf[jg][sl]     = reinterpret_cast<uint32_t&>(p01);
                pf[jg][sl + 1] = reinterpret_cast<uint32_t&>(p23);
            }
            cs0 += __shfl_xor_sync(~0u, cs0, 1); cs0 += __shfl_xor_sync(~0u, cs0, 2);
            cs1 += __shfl_xor_sync(~0u, cs1, 1); cs1 += __shfl_xor_sync(~0u, cs1, 2);
            lr0 = lr0 * sc0 + cs0; lr1 = lr1 * sc1 + cs1;
            mr0 = mn0; mr1 = mn1;
#pragma unroll
            for (int j = 0; j < 8; j++) {
                O[j][0] *= sc0; O[j][1] *= sc0; O[j][2] *= sc1; O[j][3] *= sc1;
            }

#pragma unroll
            for (int jg = 0; jg < 4; jg++) {
#pragma unroll
                for (int dg = 0; dg < 4; dg++) {
                    int trow = dg * 16 + ((lane >> 4) & 1) * 8 + (lane & 7);
                    int tcol = ch * 64 + jg * 16 + ((lane >> 3) & 1) * 8;
                    uint32_t ad = vt0 + (trow * VSTR + tcol) * 2;
                    uint32_t bfr[4];
                    LDMX4(bfr[0], bfr[1], bfr[2], bfr[3], ad);
                    mma16816(O[dg * 2],     pf[jg], bfr);
                    mma16816(O[dg * 2 + 1], pf[jg], bfr + 2);
                }
            }
        }

        float inv0 = 1.0f / lr0, inv1 = 1.0f / lr1;
        int r0 = tile * 16 + (lane >> 2), r1 = r0 + 8;
#pragma unroll
        for (int j = 0; j < 8; j++) {
            int d = j * 8 + (lane & 3) * 2;
            if (r0 < NTOK) {
                __half2 hv = (r0 == NTOK - 1)
                    ? *(const __half2*)(Vb + ib + (size_t)(NTOK - 1) * 64 + d)
                    : __floats2half2_rn(O[j][0] * inv0, O[j][1] * inv0);
                *(__half2*)(oh + ((size_t)b * NTOK + r0) * D_EMB + h * 64 + d) = hv;
            }
            if (r1 < NTOK) {
                __half2 hv = (r1 == NTOK - 1)
                    ? *(const __half2*)(Vb + ib + (size_t)(NTOK - 1) * 64 + d)
                    : __floats2half2_rn(O[j][2] * inv1, O[j][3] * inv1);
                *(__half2*)(oh + ((size_t)b * NTOK + r1) * D_EMB + h * 64 + d) = hv;
            }
        }
    }
}

// ---------------- tokenizers ----------------
__global__ void st_kernel(const float* __restrict__ as, const float* __restrict__ w1,
                          const float* __restrict__ b1, const float* __restrict__ w2,
                          const float* __restrict__ b2, float* __restrict__ st)
{
    __shared__ float h1[32];
    int bt = blockIdx.x;
    int tid = threadIdx.x;
    float s0 = as[bt * 2], s1 = as[bt * 2 + 1];
    if (tid < 32) {
        float v = b1[tid] + s0 * w1[tid] + s1 * w1[32 + tid];
        h1[tid] = v > 0.f ? v : 0.f;
    }
    __syncthreads();
    float acc = b2[tid];
#pragma unroll
    for (int k = 0; k < 32; k++) acc = fmaf(h1[k], w2[k * 384 + tid], acc);
    st[(size_t)bt * 384 + tid] = acc;
}

__global__ void im2col_kernel(const float* __restrict__ img, __half* __restrict__ ph)
{
    int idx = blockIdx.x * 256 + threadIdx.x;
    int f = idx % 192;
    int rem = idx / 192;
    int pidx = rem % 144;
    int bt = rem / 144;
    int pr = f / 24, pc = (f % 24) / 3, c = f % 3;
    int hp = pidx / 12, wp = pidx % 12;
    ph[idx] = __float2half_rn(img[(((size_t)bt * 3 + c) * 96 + hp * 8 + pr) * 96 + wp * 8 + pc]);
}

// assemble residual stream + xh + row stats (block per row, 128 thr)
__global__ void assemble_ln(const float* __restrict__ imgtok, const float* __restrict__ st,
                            const float* __restrict__ readout, const float* __restrict__ pos,
                            const float* __restrict__ img_temb, const float* __restrict__ st_temb,
                            float* __restrict__ x, __half* __restrict__ xh,
                            float2* __restrict__ stats)
{
    size_t row = blockIdx.x;
    int tok = (int)(row % NTOK);
    int b = (int)(row / NTOK);
    int tid = threadIdx.x;
    float v[3];
#pragma unroll
    for (int q = 0; q < 3; q++) {
        int d = tid + q * 128;
        float vv;
        if (tok == NTOK - 1) {
            vv = readout[d];
        } else {
            int t = tok / 145, r = tok % 145;
            if (r == 0) vv = st[((size_t)(b * 2 + t)) * 384 + d] + st_temb[t * 384 + d];
            else        vv = imgtok[((size_t)(b * 2 + t) * 144 + (r - 1)) * 384 + d] + img_temb[t * 384 + d];
        }
        vv += pos[tok * 384 + d];
        v[q] = vv;
        x[row * D_EMB + d] = vv;
        xh[row * D_EMB + d] = __float2half_rn(vv);
    }
    float s = v[0] + v[1] + v[2], sq = v[0]*v[0] + v[1]*v[1] + v[2]*v[2];
#pragma unroll
    for (int o = 16; o; o >>= 1) {
        s  += __shfl_xor_sync(~0u, s,  o);
        sq += __shfl_xor_sync(~0u, sq, o);
    }
    __shared__ float ws[4], wq[4];
    int warp = tid >> 5, lane = tid & 31;
    if (!lane) { ws[warp] = s; wq[warp] = sq; }
    __syncthreads();
    if (tid == 0)
        stats[row] = make_float2(ws[0]+ws[1]+ws[2]+ws[3], wq[0]+wq[1]+wq[2]+wq[3]);
}

// ---------------- launch ----------------
extern "C" void kernel_launch(void* const* d_in, const int* in_sizes, int n_in,
                              void* d_out, int out_size)
{
    const float* images      = (const float*)d_in[0];
    const float* agent_state = (const float*)d_in[1];
    const float* img_proj_w  = (const float*)d_in[2];
    const float* img_proj_b  = (const float*)d_in[3];
    const float* img_temb    = (const float*)d_in[4];
    const float* st_w1       = (const float*)d_in[5];
    const float* st_b1       = (const float*)d_in[6];
    const float* st_w2       = (const float*)d_in[7];
    const float* st_b2       = (const float*)d_in[8];
    const float* st_temb     = (const float*)d_in[9];
    const float* readout     = (const float*)d_in[10];
    const float* pos         = (const float*)d_in[11];
    const float* ln1_w       = (const float*)d_in[12];
    const float* ln1_b       = (const float*)d_in[13];
    const float* attn_w      = (const float*)d_in[14];
    const float* attn_b      = (const float*)d_in[15];
    const float* proj_w      = (const float*)d_in[16];
    const float* proj_b      = (const float*)d_in[17];
    const float* ln2_w       = (const float*)d_in[18];
    const float* ln2_b       = (const float*)d_in[19];
    const float* fc_w        = (const float*)d_in[20];
    const float* fc_b        = (const float*)d_in[21];
    const float* fc2_w       = (const float*)d_in[22];
    const float* fc2_b       = (const float*)d_in[23];
    const float* lnf_w       = (const float*)d_in[24];
    const float* lnf_b       = (const float*)d_in[25];
    float* out = (float*)d_out;

    float *x, *att, *st, *uq, *cq, *u1, *c1;
    float2 *s0, *s1;
    __half *xh, *ah, *bhp, *ph, *qb, *kb, *vb, *wq, *wp, *w1, *w2, *wi;
    cudaGetSymbolAddress((void**)&x,   g_x);
    cudaGetSymbolAddress((void**)&att, g_att);
    cudaGetSymbolAddress((void**)&st,  g_st);
    cudaGetSymbolAddress((void**)&s0,  g_s0);
    cudaGetSymbolAddress((void**)&s1,  g_s1);
    cudaGetSymbolAddress((void**)&xh,  g_xh);
    cudaGetSymbolAddress((void**)&ah,  g_ah);
    cudaGetSymbolAddress((void**)&bhp, g_bh);
    cudaGetSymbolAddress((void**)&ph,  g_ph);
    cudaGetSymbolAddress((void**)&qb,  g_q);
    cudaGetSymbolAddress((void**)&kb,  g_k);
    cudaGetSymbolAddress((void**)&vb,  g_v);
    cudaGetSymbolAddress((void**)&wq,  g_wq);
    cudaGetSymbolAddress((void**)&wp,  g_wp);
    cudaGetSymbolAddress((void**)&w1,  g_w1);
    cudaGetSymbolAddress((void**)&w2,  g_w2);
    cudaGetSymbolAddress((void**)&wi,  g_wi);
    cudaGetSymbolAddress((void**)&uq,  g_uq);
    cudaGetSymbolAddress((void**)&cq,  g_cq);
    cudaGetSymbolAddress((void**)&u1,  g_u1);
    cudaGetSymbolAddress((void**)&c1,  g_c1);

    cudaFuncSetAttribute(attn_mma, cudaFuncAttributeMaxDynamicSharedMemorySize, ATT_SMEM_BYTES);
    cudaFuncSetAttribute(gemm_mma<0>, cudaFuncAttributeMaxDynamicSharedMemorySize, GSMEM);
    cudaFuncSetAttribute(gemm_mma<3>, cudaFuncAttributeMaxDynamicSharedMemorySize, GSMEM);
    cudaFuncSetAttribute(gemm_mma<4>, cudaFuncAttributeMaxDynamicSharedMemorySize, GSMEM);
    cudaFuncSetAttribute(gemm_mma<5>, cudaFuncAttributeMaxDynamicSharedMemorySize, GSMEM);

    // ---- weight prep (g folded into qkv/fc1 weights) + u/c vectors ----
    wprep<<<dim3(1152/32, 384/32, 12), dim3(32, 8)>>>(attn_w, ln1_w, wq, 384, 1152);
    wprep<<<dim3(384/32,  384/32, 12), dim3(32, 8)>>>(proj_w, nullptr, wp, 384, 384);
    wprep<<<dim3(1536/32, 384/32, 12), dim3(32, 8)>>>(fc_w,  ln2_w, w1, 384, 1536);
    wprep<<<dim3(384/32, 1536/32, 12), dim3(32, 8)>>>(fc2_w, nullptr, w2, 1536, 384);
    wprep<<<dim3(384/32,  192/32, 1),  dim3(32, 8)>>>(img_proj_w, nullptr, wi, 192, 384);
    prep_uc<<<dim3(1152/128, 12), 128>>>(attn_w, ln1_w, ln1_b, attn_b, uq, cq, 1152);
    prep_uc<<<dim3(1536/128, 12), 128>>>(fc_w,  ln2_w, ln2_b, fc_b,  u1, c1, 1536);

    // ---- tokenizers ----
    st_kernel<<<BATCH * OBS_H, 384>>>(agent_state, st_w1, st_b1, st_w2, st_b2, st);
    im2col_kernel<<<(M_PATCH * PK) / 256, 256>>>(images, ph);
    gemm_mma<0><<<dim3(3, M_PATCH / 128), 256, GSMEM>>>(
        ph, wi, img_proj_b, nullptr, att, nullptr, nullptr, nullptr, nullptr,
        nullptr, nullptr, nullptr, nullptr, 384, PK);
    assemble_ln<<<M_TOK, 128>>>(att, st, readout, pos, img_temb, st_temb, x, xh, s0);

    // ---- transformer layers ----
    const int ZB = (M_TOK + 255) / 256;
    for (int l = 0; l < NLAYER; l++) {
        gemm_mma<4><<<dim3(9, NTOK), 256, GSMEM>>>(
            xh, wq + (size_t)l * 1152 * 384, cq + l * 1152, nullptr,
            nullptr, nullptr, qb, kb, vb, s0, nullptr, uq + l * 1152, nullptr, 1152, 384);
        zero_stats<<<ZB, 256>>>(s1);
        attn_mma<<<BATCH * NHEAD, 256, ATT_SMEM_BYTES>>>(qb, kb, vb, ah);
        gemm_mma<5><<<dim3(3, NTOK), 256, GSMEM>>>(
            ah, wp + (size_t)l * 384 * 384, proj_b + l * 384, x,
            x, nullptr, nullptr, nullptr, nullptr, nullptr, s1, nullptr, xh, 384, 384);
        zero_stats<<<ZB, 256>>>(s0);
        gemm_mma<3><<<dim3(12, NTOK), 256, GSMEM>>>(
            xh, w1 + (size_t)l * 1536 * 384, c1 + l * 1536, nullptr,
            nullptr, bhp, nullptr, nullptr, nullptr, s1, nullptr, u1 + l * 1536, nullptr, 1536, 384);
        gemm_mma<5><<<dim3(3, NTOK), 256, GSMEM>>>(
            bhp, w2 + (size_t)l * 384 * 1536, fc2_b + l * 384, x,
            x, nullptr, nullptr, nullptr, nullptr, nullptr, s0, nullptr, xh, 384, 1536);
    }

    lnf_kernel<<<BATCH, 128>>>(x, lnf_w, lnf_b, out);
}

// round 10
// speedup vs baseline: 6.8747x; 1.1154x over previous
#include <cuda_runtime.h>
#include <cuda_fp16.h>
#include <math.h>
#include <stdint.h>

// ---------------- problem constants ----------------
#define BATCH   128
#define OBS_H   2
#define NTOK    291
#define M_TOK   (BATCH*NTOK)   // 37248 = 291*128
#define D_EMB   384
#define NHEAD   6
#define NLAYER  12
#define N_IMG   144
#define PK      192
#define M_PATCH (BATCH*OBS_H*N_IMG)

// ---------------- scratch ----------------
__device__ float g_x  [M_TOK * D_EMB];
__device__ float g_att[M_PATCH * D_EMB];
__device__ float g_st [BATCH * OBS_H * D_EMB];
__device__ float2 g_sA[3 * M_TOK];             // row-stat partials (x)
__device__ float2 g_sB[3 * M_TOK];             // row-stat partials (after proj)
__device__ __half g_xh[M_TOK*384];
__device__ __half g_ah[M_TOK*384];
__device__ __half g_bh[M_TOK*1536];
__device__ __half g_ph[M_PATCH*192];
__device__ __half g_q [BATCH*NHEAD*NTOK*64];
__device__ __half g_k [BATCH*NHEAD*NTOK*64];
__device__ __half g_v [BATCH*NHEAD*NTOK*64];
// transposed weights [N,K] fp16 (qkv/fc1 have ln-g folded in)
__device__ __half g_wq[12*1152*384];
__device__ __half g_wp[12*384*384];
__device__ __half g_w1[12*1536*384];
__device__ __half g_w2[12*384*1536];
__device__ __half g_wi[384*192];
// LN-fusion vectors: u = g@W, c = b@W + bias
__device__ float g_uq[12*1152], g_cq[12*1152];
__device__ float g_u1[12*1536], g_c1[12*1536];

__device__ __forceinline__ float gelu_tanh(float v) {
    const float c = 0.7978845608028654f;
    float u = c * (v + 0.044715f * v * v * v);
    return 0.5f * v * (1.0f + tanhf(u));
}

__device__ __forceinline__ uint32_t smem_u32(const void* p) {
    uint32_t a;
    asm("{ .reg .u64 t; cvta.to.shared.u64 t, %1; cvt.u32.u64 %0, t; }" : "=r"(a) : "l"(p));
    return a;
}

__device__ __forceinline__ void mma16816(float c[4], const uint32_t a[4], const uint32_t b[2]) {
    asm volatile(
        "mma.sync.aligned.m16n8k16.row.col.f32.f16.f16.f32 "
        "{%0,%1,%2,%3}, {%4,%5,%6,%7}, {%8,%9}, {%0,%1,%2,%3};\n"
        : "+f"(c[0]), "+f"(c[1]), "+f"(c[2]), "+f"(c[3])
        : "r"(a[0]), "r"(a[1]), "r"(a[2]), "r"(a[3]), "r"(b[0]), "r"(b[1]));
}
#define LDMX4(r0, r1, r2, r3, addr) \
    asm volatile("ldmatrix.sync.aligned.m8n8.x4.shared.b16 {%0,%1,%2,%3}, [%4];" \
        : "=r"(r0), "=r"(r1), "=r"(r2), "=r"(r3) : "r"(addr))

// =======================================================================
// fp16 HMMA GEMM, 3-stage cp.async pipeline, single sync per k-tile.
// EPI 0: +bias -> f32 C
// EPI 4: LN-fused -> scatter q/k/v fp16           (reads 3 stat partials)
// EPI 3: LN-fused + gelu -> fp16 Ch               (reads 3 stat partials)
// EPI 5: +bias+res -> f32 C, fp16 XH, stat partial (smem-reduced across warps)
// =======================================================================
#define STAGE_B   20480
#define GSMEM     (3*STAGE_B)

template <int EPI>
__global__ void __launch_bounds__(256, 2) gemm_mma(
    const __half* __restrict__ A, const __half* __restrict__ B,
    const float* __restrict__ bias, const float* __restrict__ Rres,
    float* __restrict__ C, __half* __restrict__ Ch,
    __half* __restrict__ Qo, __half* __restrict__ Ko, __half* __restrict__ Vo,
    const float2* __restrict__ stats_in, float2* __restrict__ stats_out,
    const float* __restrict__ uvec, __half* __restrict__ XH,
    int N, int K)
{
    extern __shared__ __align__(16) char dyn[];
    const uint32_t sbase = smem_u32(dyn);
    const int tid = threadIdx.x, lane = tid & 31, warp = tid >> 5;
    const int wm = warp >> 2, wn = warp & 3;
    const int bn = blockIdx.x, bm = blockIdx.y;

    float acc[4][4][4];
#pragma unroll
    for (int i = 0; i < 4; i++)
#pragma unroll
        for (int j = 0; j < 4; j++)
#pragma unroll
            for (int q = 0; q < 4; q++) acc[i][j][q] = 0.f;

    const char* gsrc[2] = {
        (const char*)(A + (size_t)bm * 128 * K),
        (const char*)(B + (size_t)bn * 128 * K) };
    const size_t rs = (size_t)K * 2;

#define LOADT(t_) do { \
    uint32_t db_ = sbase + ((t_) % 3) * STAGE_B; \
    size_t go_ = (size_t)(t_) * 64; \
    _Pragma("unroll") \
    for (int b_ = 0; b_ < 2; b_++) { \
        const char* g_ = gsrc[b_]; \
        uint32_t d_ = db_ + b_ * 10240; \
        _Pragma("unroll") \
        for (int i_ = 0; i_ < 2; i_++) { \
            int idx_ = i_ * 256 + tid; \
            int r_ = idx_ >> 2, c_ = (idx_ & 3) * 16; \
            asm volatile("cp.async.cg.shared.global [%0], [%1], 16;" \
                :: "r"(d_ + r_ * 80 + c_), "l"(g_ + (size_t)r_ * rs + go_ + c_) : "memory"); \
        } \
    } \
    asm volatile("cp.async.commit_group;" ::: "memory"); \
} while (0)

    const int T = K >> 5;
    LOADT(0);
    if (T > 1) LOADT(1);

    for (int t = 0; t < T; t++) {
        if (t + 1 < T) asm volatile("cp.async.wait_group 1;" ::: "memory");
        else           asm volatile("cp.async.wait_group 0;" ::: "memory");
        __syncthreads();
        const uint32_t sb = sbase + (t % 3) * STAGE_B;

#pragma unroll
        for (int ks = 0; ks < 2; ks++) {
            const int k0 = ks * 16;
            uint32_t bf[4][2];
#pragma unroll
            for (int pr = 0; pr < 2; pr++) {
                int trow = wn * 32 + pr * 16 + ((lane >> 4) & 1) * 8 + (lane & 7);
                int tcol = k0 + ((lane >> 3) & 1) * 8;
                uint32_t ab = sb + 10240 + trow * 80 + tcol * 2;
                LDMX4(bf[2*pr][0], bf[2*pr][1], bf[2*pr+1][0], bf[2*pr+1][1], ab);
            }
#pragma unroll
            for (int i = 0; i < 4; i++) {
                int arow = wm * 64 + i * 16 + (lane & 7) + ((lane >> 3) & 1) * 8;
                int acol = k0 + ((lane >> 4) & 1) * 8;
                uint32_t aa = sb + arow * 80 + acol * 2;
                uint32_t a4[4];
                LDMX4(a4[0], a4[1], a4[2], a4[3], aa);
#pragma unroll
                for (int j = 0; j < 4; j++) mma16816(acc[i][j], a4, bf[j]);
            }
        }
        if (t + 2 < T) LOADT(t + 2);
    }

    // EPI==5: per-row stat reduction buffer in (now-free) pipeline smem
    float2* sstat = (float2*)dyn;
    if (EPI == 5) {
        __syncthreads();                 // everyone done reading stage smem
        if (tid < 128) sstat[tid] = make_float2(0.f, 0.f);
        __syncthreads();
    }

    const float att_scale = 1.0f / sqrtf(64.0f + 1e-8f);

#pragma unroll
    for (int i = 0; i < 4; i++) {
        int row0 = bm * 128 + wm * 64 + i * 16 + (lane >> 2);
#pragma unroll
        for (int half_ = 0; half_ < 2; half_++) {
            int row = row0 + half_ * 8;
            float mu = 0.f, inv = 1.f;
            if (EPI == 3 || EPI == 4) {
                float2 p0 = stats_in[row];
                float2 p1 = stats_in[M_TOK + row];
                float2 p2 = stats_in[2 * M_TOK + row];
                float sx = p0.x + p1.x + p2.x;
                float sq = p0.y + p1.y + p2.y;
                mu = sx * (1.0f / 384.0f);
                inv = rsqrtf(sq * (1.0f / 384.0f) - mu * mu + 1e-5f);
            }
            float rsum = 0.f, rsq = 0.f;
#pragma unroll
            for (int j = 0; j < 4; j++) {
                int col = bn * 128 + wn * 32 + j * 8 + (lane & 3) * 2;
                float a0 = acc[i][j][half_ * 2 + 0];
                float a1 = acc[i][j][half_ * 2 + 1];
                if (EPI == 0) {
                    size_t off = (size_t)row * N + col;
                    *(float2*)(C + off) = make_float2(a0 + bias[col], a1 + bias[col + 1]);
                } else if (EPI == 4) {
                    float v0 = inv * (a0 - mu * uvec[col])     + bias[col];
                    float v1 = inv * (a1 - mu * uvec[col + 1]) + bias[col + 1];
                    int kind = col / 384;
                    int hh = (col % 384) >> 6;
                    int dd = col & 63;
                    int bb = row / NTOK, tt = row % NTOK;
                    size_t o3 = ((size_t)(bb * NHEAD + hh) * NTOK + tt) * 64 + dd;
                    if (kind == 0)
                        *(__half2*)(Qo + o3) = __floats2half2_rn(v0 * att_scale, v1 * att_scale);
                    else if (kind == 1)
                        *(__half2*)(Ko + o3) = __floats2half2_rn(v0, v1);
                    else
                        *(__half2*)(Vo + o3) = __floats2half2_rn(v0, v1);
                } else if (EPI == 3) {
                    float v0 = gelu_tanh(inv * (a0 - mu * uvec[col])     + bias[col]);
                    float v1 = gelu_tanh(inv * (a1 - mu * uvec[col + 1]) + bias[col + 1]);
                    size_t off = (size_t)row * N + col;
                    *(__half2*)((char*)Ch + off * 2) = __floats2half2_rn(v0, v1);
                } else { // EPI == 5
                    size_t off = (size_t)row * N + col;
                    float2 rr = *(const float2*)(Rres + off);
                    float v0 = a0 + bias[col]     + rr.x;
                    float v1 = a1 + bias[col + 1] + rr.y;
                    *(float2*)(C + off) = make_float2(v0, v1);
                    *(__half2*)((char*)XH + off * 2) = __floats2half2_rn(v0, v1);
                    rsum += v0 + v1;
                    rsq  += v0 * v0 + v1 * v1;
                }
            }
            if (EPI == 5) {
                // reduce over the 4 lanes of this row, then combine across
                // the 4 wn-warps via smem atomics (fix for R9's race)
                rsum += __shfl_xor_sync(~0u, rsum, 1); rsum += __shfl_xor_sync(~0u, rsum, 2);
                rsq  += __shfl_xor_sync(~0u, rsq, 1);  rsq  += __shfl_xor_sync(~0u, rsq, 2);
                if ((lane & 3) == 0) {
                    int rl = row - bm * 128;       // 0..127
                    atomicAdd(&sstat[rl].x, rsum);
                    atomicAdd(&sstat[rl].y, rsq);
                }
            }
        }
    }
    if (EPI == 5) {
        __syncthreads();
        if (tid < 128)
            stats_out[bn * M_TOK + bm * 128 + tid] = sstat[tid];
    }
}

// ---------------- weight transpose + fp16, optional g-fold ----
__global__ void wprep(const float* __restrict__ W, const float* __restrict__ g,
                      __half* __restrict__ Wh, int K, int N)
{
    __shared__ float t[32][33];
    const int l = blockIdx.z;
    const size_t lo = (size_t)l * K * N;
    const float* Wp = W + lo;
    const int kt = blockIdx.y * 32, nt = blockIdx.x * 32;
    const int tx = threadIdx.x, ty = threadIdx.y;
#pragma unroll
    for (int i = ty; i < 32; i += 8)
        t[i][tx] = Wp[(size_t)(kt + i) * N + nt + tx];
    __syncthreads();
    float gk = g ? g[l * K + kt + tx] : 1.0f;
#pragma unroll
    for (int i = ty; i < 32; i += 8)
        Wh[lo + (size_t)(nt + i) * K + kt + tx] = __float2half_rn(t[tx][i] * gk);
}

// ---------------- LN-fusion u/c prep ----
__global__ void prep_uc(const float* __restrict__ W, const float* __restrict__ g,
                        const float* __restrict__ b, const float* __restrict__ bias,
                        float* __restrict__ u, float* __restrict__ c, int N)
{
    const int l = blockIdx.y;
    const int n = blockIdx.x * 128 + threadIdx.x;
    const float* Wp = W + (size_t)l * 384 * N + n;
    const float* gp = g + l * 384;
    const float* bp = b + l * 384;
    float su = 0.f, sc = 0.f;
    for (int k = 0; k < 384; k++) {
        float w = Wp[(size_t)k * N];
        su = fmaf(gp[k], w, su);
        sc = fmaf(bp[k], w, sc);
    }
    u[l * N + n] = su;
    c[l * N + n] = sc + bias[l * N + n];
}

__global__ void lnf_kernel(const float* __restrict__ x, const float* __restrict__ w,
                           const float* __restrict__ b, float* __restrict__ out)
{
    size_t bi = blockIdx.x;
    const float* xr = x + (bi * NTOK + (NTOK - 1)) * D_EMB;
    int tid = threadIdx.x;
    float v0 = xr[tid], v1 = xr[tid + 128], v2 = xr[tid + 256];
    float s = v0 + v1 + v2, sq = v0*v0 + v1*v1 + v2*v2;
#pragma unroll
    for (int o = 16; o; o >>= 1) {
        s  += __shfl_xor_sync(~0u, s,  o);
        sq += __shfl_xor_sync(~0u, sq, o);
    }
    __shared__ float ws[4], wq[4], red[2];
    int warp = tid >> 5, lane = tid & 31;
    if (!lane) { ws[warp] = s; wq[warp] = sq; }
    __syncthreads();
    if (tid == 0) {
        float S = ws[0]+ws[1]+ws[2]+ws[3], Q = wq[0]+wq[1]+wq[2]+wq[3];
        float mean = S * (1.0f / 384.0f);
        red[0] = mean;
        red[1] = rsqrtf(Q * (1.0f / 384.0f) - mean * mean + 1e-5f);
    }
    __syncthreads();
    float mean = red[0], inv = red[1];
    out[bi * D_EMB + tid]       = (v0 - mean) * inv * w[tid]       + b[tid];
    out[bi * D_EMB + tid + 128] = (v1 - mean) * inv * w[tid + 128] + b[tid + 128];
    out[bi * D_EMB + tid + 256] = (v2 - mean) * inv * w[tid + 256] + b[tid + 256];
}

// ---------------- Flash attention on HMMA (fp32 softmax) ----------------
// No Q smem (direct gmem A-fragments) -> 88KB smem -> 2 CTAs/SM.
#define KPAD 320
#define KSTR 72
#define VSTR 328
#define ATT_SMEM_HALVES (KPAD*KSTR + 64*VSTR)
#define ATT_SMEM_BYTES  (ATT_SMEM_HALVES * 2)

__global__ void __launch_bounds__(256, 2) attn_mma(
    const __half* __restrict__ Qb, const __half* __restrict__ Kb,
    const __half* __restrict__ Vb, __half* __restrict__ oh)
{
    extern __shared__ __half smh[];
    __half* Ks = smh;
    __half* Vt = smh + KPAD * KSTR;

    const int bh = blockIdx.x;
    const int b = bh / NHEAD, h = bh % NHEAD;
    const int tid = threadIdx.x, warp = tid >> 5, lane = tid & 31;
    const size_t ib = (size_t)bh * NTOK * 64;

    // zero V^T (padding cols must be 0), then fill K and V^T
    for (int i = tid; i < (64 * VSTR) / 8; i += 256)
        ((int4*)Vt)[i] = make_int4(0, 0, 0, 0);
    __syncthreads();
    for (int idx = tid; idx < NTOK * 8; idx += 256) {
        int t = idx >> 3, s = idx & 7;
        ((int4*)(Ks + t * KSTR))[s] = ((const int4*)(Kb + ib + (size_t)t * 64))[s];
    }
    for (int idx = tid; idx < NTOK * 64; idx += 256) {
        int t = idx >> 6, d = idx & 63;
        Vt[d * VSTR + t] = Vb[ib + idx];
    }
    __syncthreads();

    const uint32_t ks0 = smem_u32(Ks), vt0 = smem_u32(Vt);

    for (int tile = warp; tile < 19; tile += 8) {
        // ---- Q fragments straight from gmem (canonical m16n8k16 A layout) ----
        uint32_t qf[4][4];
        {
            int r0g = tile * 16 + (lane >> 2);
            int r1g = r0g + 8;
            if (r0g >= NTOK) r0g = NTOK - 1;
            if (r1g >= NTOK) r1g = NTOK - 1;
            const __half* Q0 = Qb + ib + (size_t)r0g * 64;
            const __half* Q1 = Qb + ib + (size_t)r1g * 64;
            int c0 = (lane & 3) * 2;
#pragma unroll
            for (int ks = 0; ks < 4; ks++) {
                qf[ks][0] = *(const uint32_t*)(Q0 + ks * 16 + c0);
                qf[ks][1] = *(const uint32_t*)(Q1 + ks * 16 + c0);
                qf[ks][2] = *(const uint32_t*)(Q0 + ks * 16 + c0 + 8);
                qf[ks][3] = *(const uint32_t*)(Q1 + ks * 16 + c0 + 8);
            }
        }
        float O[8][4];
#pragma unroll
        for (int j = 0; j < 8; j++)
#pragma unroll
            for (int q = 0; q < 4; q++) O[j][q] = 0.f;
        float mr0 = -1e30f, mr1 = -1e30f, lr0 = 0.f, lr1 = 0.f;

        for (int ch = 0; ch < 5; ch++) {
            float S[8][4];
#pragma unroll
            for (int j = 0; j < 8; j++)
#pragma unroll
                for (int q = 0; q < 4; q++) S[j][q] = 0.f;

#pragma unroll
            for (int ks = 0; ks < 4; ks++) {
#pragma unroll
                for (int kg = 0; kg < 4; kg++) {
                    int trow = ch * 64 + kg * 16 + ((lane >> 4) & 1) * 8 + (lane & 7);
                    int tcol = ks * 16 + ((lane >> 3) & 1) * 8;
                    uint32_t ad = ks0 + (trow * KSTR + tcol) * 2;
                    uint32_t bfr[4];
                    LDMX4(bfr[0], bfr[1], bfr[2], bfr[3], ad);
                    mma16816(S[kg * 2],     qf[ks], bfr);
                    mma16816(S[kg * 2 + 1], qf[ks], bfr + 2);
                }
            }

            float cm0 = -1e30f, cm1 = -1e30f;
#pragma unroll
            for (int j = 0; j < 8; j++) {
                int k0c = ch * 64 + j * 8 + (lane & 3) * 2;
                if (k0c >= NTOK)     { S[j][0] = -1e30f; S[j][2] = -1e30f; }
                if (k0c + 1 >= NTOK) { S[j][1] = -1e30f; S[j][3] = -1e30f; }
                cm0 = fmaxf(cm0, fmaxf(S[j][0], S[j][1]));
                cm1 = fmaxf(cm1, fmaxf(S[j][2], S[j][3]));
            }
            cm0 = fmaxf(cm0, __shfl_xor_sync(~0u, cm0, 1));
            cm0 = fmaxf(cm0, __shfl_xor_sync(~0u, cm0, 2));
            cm1 = fmaxf(cm1, __shfl_xor_sync(~0u, cm1, 1));
            cm1 = fmaxf(cm1, __shfl_xor_sync(~0u, cm1, 2));

            float mn0 = fmaxf(mr0, cm0), mn1 = fmaxf(mr1, cm1);
            float sc0 = __expf(mr0 - mn0), sc1 = __expf(mr1 - mn1);

            float cs0 = 0.f, cs1 = 0.f;
            uint32_t pf[4][4];
#pragma unroll
            for (int j = 0; j < 8; j++) {
                float e0 = __expf(S[j][0] - mn0), e1 = __expf(S[j][1] - mn0);
                float e2 = __expf(S[j][2] - mn1), e3 = __expf(S[j][3] - mn1);
                cs0 += e0 + e1; cs1 += e2 + e3;
                __half2 p01 = __floats2half2_rn(e0, e1);
                __half2 p23 = __floats2half2_rn(e2, e3);
                int jg = j >> 1, sl = (j & 1) * 2;
                pf[jg][sl]     = reinterpret_cast<uint32_t&>(p01);
                pf[jg][sl + 1] = reinterpret_cast<uint32_t&>(p23);
            }
            cs0 += __shfl_xor_sync(~0u, cs0, 1); cs0 += __shfl_xor_sync(~0u, cs0, 2);
            cs1 += __shfl_xor_sync(~0u, cs1, 1); cs1 += __shfl_xor_sync(~0u, cs1, 2);
            lr0 = lr0 * sc0 + cs0; lr1 = lr1 * sc1 + cs1;
            mr0 = mn0; mr1 = mn1;
#pragma unroll
            for (int j = 0; j < 8; j++) {
                O[j][0] *= sc0; O[j][1] *= sc0; O[j][2] *= sc1; O[j][3] *= sc1;
            }

#pragma unroll
            for (int jg = 0; jg < 4; jg++) {
#pragma unroll
                for (int dg = 0; dg < 4; dg++) {
                    int trow = dg * 16 + ((lane >> 4) & 1) * 8 + (lane & 7);
                    int tcol = ch * 64 + jg * 16 + ((lane >> 3) & 1) * 8;
                    uint32_t ad = vt0 + (trow * VSTR + tcol) * 2;
                    uint32_t bfr[4];
                    LDMX4(bfr[0], bfr[1], bfr[2], bfr[3], ad);
                    mma16816(O[dg * 2],     pf[jg], bfr);
                    mma16816(O[dg * 2 + 1], pf[jg], bfr + 2);
                }
            }
        }

        float inv0 = 1.0f / lr0, inv1 = 1.0f / lr1;
        int r0 = tile * 16 + (lane >> 2), r1 = r0 + 8;
#pragma unroll
        for (int j = 0; j < 8; j++) {
            int d = j * 8 + (lane & 3) * 2;
            if (r0 < NTOK) {
                __half2 hv = (r0 == NTOK - 1)
                    ? *(const __half2*)(Vb + ib + (size_t)(NTOK - 1) * 64 + d)
                    : __floats2half2_rn(O[j][0] * inv0, O[j][1] * inv0);
                *(__half2*)(oh + ((size_t)b * NTOK + r0) * D_EMB + h * 64 + d) = hv;
            }
            if (r1 < NTOK) {
                __half2 hv = (r1 == NTOK - 1)
                    ? *(const __half2*)(Vb + ib + (size_t)(NTOK - 1) * 64 + d)
                    : __floats2half2_rn(O[j][2] * inv1, O[j][3] * inv1);
                *(__half2*)(oh + ((size_t)b * NTOK + r1) * D_EMB + h * 64 + d) = hv;
            }
        }
    }
}

// ---------------- tokenizers ----------------
__global__ void st_kernel(const float* __restrict__ as, const float* __restrict__ w1,
                          const float* __restrict__ b1, const float* __restrict__ w2,
                          const float* __restrict__ b2, float* __restrict__ st)
{
    __shared__ float h1[32];
    int bt = blockIdx.x;
    int tid = threadIdx.x;
    float s0 = as[bt * 2], s1 = as[bt * 2 + 1];
    if (tid < 32) {
        float v = b1[tid] + s0 * w1[tid] + s1 * w1[32 + tid];
        h1[tid] = v > 0.f ? v : 0.f;
    }
    __syncthreads();
    float acc = b2[tid];
#pragma unroll
    for (int k = 0; k < 32; k++) acc = fmaf(h1[k], w2[k * 384 + tid], acc);
    st[(size_t)bt * 384 + tid] = acc;
}

__global__ void im2col_kernel(const float* __restrict__ img, __half* __restrict__ ph)
{
    int idx = blockIdx.x * 256 + threadIdx.x;
    int f = idx % 192;
    int rem = idx / 192;
    int pidx = rem % 144;
    int bt = rem / 144;
    int pr = f / 24, pc = (f % 24) / 3, c = f % 3;
    int hp = pidx / 12, wp = pidx % 12;
    ph[idx] = __float2half_rn(img[(((size_t)bt * 3 + c) * 96 + hp * 8 + pr) * 96 + wp * 8 + pc]);
}

// assemble residual stream + xh + stat partials (block per row, 128 thr)
__global__ void assemble_ln(const float* __restrict__ imgtok, const float* __restrict__ st,
                            const float* __restrict__ readout, const float* __restrict__ pos,
                            const float* __restrict__ img_temb, const float* __restrict__ st_temb,
                            float* __restrict__ x, __half* __restrict__ xh,
                            float2* __restrict__ stats)
{
    size_t row = blockIdx.x;
    int tok = (int)(row % NTOK);
    int b = (int)(row / NTOK);
    int tid = threadIdx.x;
    float v[3];
#pragma unroll
    for (int q = 0; q < 3; q++) {
        int d = tid + q * 128;
        float vv;
        if (tok == NTOK - 1) {
            vv = readout[d];
        } else {
            int t = tok / 145, r = tok % 145;
            if (r == 0) vv = st[((size_t)(b * 2 + t)) * 384 + d] + st_temb[t * 384 + d];
            else        vv = imgtok[((size_t)(b * 2 + t) * 144 + (r - 1)) * 384 + d] + img_temb[t * 384 + d];
        }
        vv += pos[tok * 384 + d];
        v[q] = vv;
        x[row * D_EMB + d] = vv;
        xh[row * D_EMB + d] = __float2half_rn(vv);
    }
    float s = v[0] + v[1] + v[2], sq = v[0]*v[0] + v[1]*v[1] + v[2]*v[2];
#pragma unroll
    for (int o = 16; o; o >>= 1) {
        s  += __shfl_xor_sync(~0u, s,  o);
        sq += __shfl_xor_sync(~0u, sq, o);
    }
    __shared__ float ws[4], wq[4];
    int warp = tid >> 5, lane = tid & 31;
    if (!lane) { ws[warp] = s; wq[warp] = sq; }
    __syncthreads();
    if (tid == 0) {
        stats[row] = make_float2(ws[0]+ws[1]+ws[2]+ws[3], wq[0]+wq[1]+wq[2]+wq[3]);
        stats[M_TOK + row] = make_float2(0.f, 0.f);
        stats[2 * M_TOK + row] = make_float2(0.f, 0.f);
    }
}

// ---------------- launch ----------------
extern "C" void kernel_launch(void* const* d_in, const int* in_sizes, int n_in,
                              void* d_out, int out_size)
{
    const float* images      = (const float*)d_in[0];
    const float* agent_state = (const float*)d_in[1];
    const float* img_proj_w  = (const float*)d_in[2];
    const float* img_proj_b  = (const float*)d_in[3];
    const float* img_temb    = (const float*)d_in[4];
    const float* st_w1       = (const float*)d_in[5];
    const float* st_b1       = (const float*)d_in[6];
    const float* st_w2       = (const float*)d_in[7];
    const float* st_b2       = (const float*)d_in[8];
    const float* st_temb     = (const float*)d_in[9];
    const float* readout     = (const float*)d_in[10];
    const float* pos         = (const float*)d_in[11];
    const float* ln1_w       = (const float*)d_in[12];
    const float* ln1_b       = (const float*)d_in[13];
    const float* attn_w      = (const float*)d_in[14];
    const float* attn_b      = (const float*)d_in[15];
    const float* proj_w      = (const float*)d_in[16];
    const float* proj_b      = (const float*)d_in[17];
    const float* ln2_w       = (const float*)d_in[18];
    const float* ln2_b       = (const float*)d_in[19];
    const float* fc_w        = (const float*)d_in[20];
    const float* fc_b        = (const float*)d_in[21];
    const float* fc2_w       = (const float*)d_in[22];
    const float* fc2_b       = (const float*)d_in[23];
    const float* lnf_w       = (const float*)d_in[24];
    const float* lnf_b       = (const float*)d_in[25];
    float* out = (float*)d_out;

    float *x, *att, *st, *uq, *cq, *u1, *c1;
    float2 *sA, *sB;
    __half *xh, *ah, *bhp, *ph, *qb, *kb, *vb, *wq, *wp, *w1, *w2, *wi;
    cudaGetSymbolAddress((void**)&x,   g_x);
    cudaGetSymbolAddress((void**)&att, g_att);
    cudaGetSymbolAddress((void**)&st,  g_st);
    cudaGetSymbolAddress((void**)&sA,  g_sA);
    cudaGetSymbolAddress((void**)&sB,  g_sB);
    cudaGetSymbolAddress((void**)&xh,  g_xh);
    cudaGetSymbolAddress((void**)&ah,  g_ah);
    cudaGetSymbolAddress((void**)&bhp, g_bh);
    cudaGetSymbolAddress((void**)&ph,  g_ph);
    cudaGetSymbolAddress((void**)&qb,  g_q);
    cudaGetSymbolAddress((void**)&kb,  g_k);
    cudaGetSymbolAddress((void**)&vb,  g_v);
    cudaGetSymbolAddress((void**)&wq,  g_wq);
    cudaGetSymbolAddress((void**)&wp,  g_wp);
    cudaGetSymbolAddress((void**)&w1,  g_w1);
    cudaGetSymbolAddress((void**)&w2,  g_w2);
    cudaGetSymbolAddress((void**)&wi,  g_wi);
    cudaGetSymbolAddress((void**)&uq,  g_uq);
    cudaGetSymbolAddress((void**)&cq,  g_cq);
    cudaGetSymbolAddress((void**)&u1,  g_u1);
    cudaGetSymbolAddress((void**)&c1,  g_c1);

    cudaFuncSetAttribute(attn_mma, cudaFuncAttributeMaxDynamicSharedMemorySize, ATT_SMEM_BYTES);
    cudaFuncSetAttribute(gemm_mma<0>, cudaFuncAttributeMaxDynamicSharedMemorySize, GSMEM);
    cudaFuncSetAttribute(gemm_mma<3>, cudaFuncAttributeMaxDynamicSharedMemorySize, GSMEM);
    cudaFuncSetAttribute(gemm_mma<4>, cudaFuncAttributeMaxDynamicSharedMemorySize, GSMEM);
    cudaFuncSetAttribute(gemm_mma<5>, cudaFuncAttributeMaxDynamicSharedMemorySize, GSMEM);

    // ---- weight prep + LN fusion vectors ----
    wprep<<<dim3(1152/32, 384/32, 12), dim3(32, 8)>>>(attn_w, ln1_w, wq, 384, 1152);
    wprep<<<dim3(384/32,  384/32, 12), dim3(32, 8)>>>(proj_w, nullptr, wp, 384, 384);
    wprep<<<dim3(1536/32, 384/32, 12), dim3(32, 8)>>>(fc_w,  ln2_w, w1, 384, 1536);
    wprep<<<dim3(384/32, 1536/32, 12), dim3(32, 8)>>>(fc2_w, nullptr, w2, 1536, 384);
    wprep<<<dim3(384/32,  192/32, 1),  dim3(32, 8)>>>(img_proj_w, nullptr, wi, 192, 384);
    prep_uc<<<dim3(1152/128, 12), 128>>>(attn_w, ln1_w, ln1_b, attn_b, uq, cq, 1152);
    prep_uc<<<dim3(1536/128, 12), 128>>>(fc_w,  ln2_w, ln2_b, fc_b,  u1, c1, 1536);

    // ---- tokenizers ----
    st_kernel<<<BATCH * OBS_H, 384>>>(agent_state, st_w1, st_b1, st_w2, st_b2, st);
    im2col_kernel<<<(M_PATCH * PK) / 256, 256>>>(images, ph);
    gemm_mma<0><<<dim3(3, M_PATCH / 128), 256, GSMEM>>>(
        ph, wi, img_proj_b, nullptr, att, nullptr, nullptr, nullptr, nullptr,
        nullptr, nullptr, nullptr, nullptr, 384, PK);
    assemble_ln<<<M_TOK, 128>>>(att, st, readout, pos, img_temb, st_temb, x, xh, sA);

    // ---- transformer layers ----
    for (int l = 0; l < NLAYER; l++) {
        gemm_mma<4><<<dim3(9, NTOK), 256, GSMEM>>>(
            xh, wq + (size_t)l * 1152 * 384, cq + l * 1152, nullptr,
            nullptr, nullptr, qb, kb, vb, sA, nullptr, uq + l * 1152, nullptr, 1152, 384);
        attn_mma<<<BATCH * NHEAD, 256, ATT_SMEM_BYTES>>>(qb, kb, vb, ah);
        gemm_mma<5><<<dim3(3, NTOK), 256, GSMEM>>>(
            ah, wp + (size_t)l * 384 * 384, proj_b + l * 384, x,
            x, nullptr, nullptr, nullptr, nullptr, nullptr, sB, nullptr, xh, 384, 384);
        gemm_mma<3><<<dim3(12, NTOK), 256, GSMEM>>>(
            xh, w1 + (size_t)l * 1536 * 384, c1 + l * 1536, nullptr,
            nullptr, bhp, nullptr, nullptr, nullptr, sB, nullptr, u1 + l * 1536, nullptr, 1536, 384);
        gemm_mma<5><<<dim3(3, NTOK), 256, GSMEM>>>(
            bhp, w2 + (size_t)l * 384 * 1536, fc2_b + l * 384, x,
            x, nullptr, nullptr, nullptr, nullptr, nullptr, sA, nullptr, xh, 384, 1536);
    }

    lnf_kernel<<<BATCH, 128>>>(x, lnf_w, lnf_b, out);
}

// round 11
// speedup vs baseline: 7.3255x; 1.0656x over previous
#include <cuda_runtime.h>
#include <cuda_fp16.h>
#include <math.h>
#include <stdint.h>

// ---------------- problem constants ----------------
#define BATCH   128
#define OBS_H   2
#define NTOK    291
#define M_TOK   (BATCH*NTOK)   // 37248 = 291*128
#define D_EMB   384
#define NHEAD   6
#define NLAYER  12
#define N_IMG   144
#define PK      192
#define M_PATCH (BATCH*OBS_H*N_IMG)

// ---------------- scratch ----------------
__device__ float g_x  [M_TOK * D_EMB];
__device__ float g_att[M_PATCH * D_EMB];
__device__ float g_st [BATCH * OBS_H * D_EMB];
__device__ float2 g_sA[3 * M_TOK];             // row-stat partials (x)
__device__ float2 g_sB[3 * M_TOK];             // row-stat partials (after proj)
__device__ __half g_xh[M_TOK*384];
__device__ __half g_ah[M_TOK*384];
__device__ __half g_bh[M_TOK*1536];
__device__ __half g_ph[M_PATCH*192];
__device__ __half g_q [BATCH*NHEAD*NTOK*64];
__device__ __half g_k [BATCH*NHEAD*NTOK*64];
__device__ __half g_v [BATCH*NHEAD*NTOK*64];
// transposed weights [N,K] fp16 (qkv/fc1 have ln-g folded in)
__device__ __half g_wq[12*1152*384];
__device__ __half g_wp[12*384*384];
__device__ __half g_w1[12*1536*384];
__device__ __half g_w2[12*384*1536];
__device__ __half g_wi[384*192];
// LN-fusion vectors: u = g@W, c = b@W + bias
__device__ float g_uq[12*1152], g_cq[12*1152];
__device__ float g_u1[12*1536], g_c1[12*1536];

__device__ __forceinline__ float gelu_tanh(float v) {
    const float c = 0.7978845608028654f;
    float u = c * (v + 0.044715f * v * v * v);
    return 0.5f * v * (1.0f + tanhf(u));
}

__device__ __forceinline__ uint32_t smem_u32(const void* p) {
    uint32_t a;
    asm("{ .reg .u64 t; cvta.to.shared.u64 t, %1; cvt.u32.u64 %0, t; }" : "=r"(a) : "l"(p));
    return a;
}

__device__ __forceinline__ void mma16816(float c[4], const uint32_t a[4], const uint32_t b[2]) {
    asm volatile(
        "mma.sync.aligned.m16n8k16.row.col.f32.f16.f16.f32 "
        "{%0,%1,%2,%3}, {%4,%5,%6,%7}, {%8,%9}, {%0,%1,%2,%3};\n"
        : "+f"(c[0]), "+f"(c[1]), "+f"(c[2]), "+f"(c[3])
        : "r"(a[0]), "r"(a[1]), "r"(a[2]), "r"(a[3]), "r"(b[0]), "r"(b[1]));
}
#define LDMX4(r0, r1, r2, r3, addr) \
    asm volatile("ldmatrix.sync.aligned.m8n8.x4.shared.b16 {%0,%1,%2,%3}, [%4];" \
        : "=r"(r0), "=r"(r1), "=r"(r2), "=r"(r3) : "r"(addr))

// =======================================================================
// fp16 HMMA GEMM. BK=64, 3-stage cp.async pipeline, ONE sync per 64-k-tile.
// smem stage: A[128][72h] + B[128][72h], 144B rows (conflict-free), 36.9KB.
// EPI 0: +bias -> f32 C
// EPI 4: LN-fused -> scatter q/k/v fp16           (reads 3 stat partials)
// EPI 3: LN-fused + gelu -> fp16 Ch               (reads 3 stat partials)
// EPI 5: +bias+res -> f32 C, fp16 XH, stat partial (smem-reduced across warps)
// =======================================================================
#define ROWB      144
#define STAGE_B   (2*128*ROWB)        // 36864
#define GSMEM     (3*STAGE_B)         // 110592

template <int EPI>
__global__ void __launch_bounds__(256, 2) gemm_mma(
    const __half* __restrict__ A, const __half* __restrict__ B,
    const float* __restrict__ bias, const float* __restrict__ Rres,
    float* __restrict__ C, __half* __restrict__ Ch,
    __half* __restrict__ Qo, __half* __restrict__ Ko, __half* __restrict__ Vo,
    const float2* __restrict__ stats_in, float2* __restrict__ stats_out,
    const float* __restrict__ uvec, __half* __restrict__ XH,
    int N, int K)
{
    extern __shared__ __align__(16) char dyn[];
    const uint32_t sbase = smem_u32(dyn);
    const int tid = threadIdx.x, lane = tid & 31, warp = tid >> 5;
    const int wm = warp >> 2, wn = warp & 3;
    const int bn = blockIdx.x, bm = blockIdx.y;

    float acc[4][4][4];
#pragma unroll
    for (int i = 0; i < 4; i++)
#pragma unroll
        for (int j = 0; j < 4; j++)
#pragma unroll
            for (int q = 0; q < 4; q++) acc[i][j][q] = 0.f;

    const char* gsrc[2] = {
        (const char*)(A + (size_t)bm * 128 * K),
        (const char*)(B + (size_t)bn * 128 * K) };
    const size_t rs = (size_t)K * 2;

// 64-k tile: per operand 128 rows x 128B (8 chunks of 16B) = 1024 chunks
#define LOADT(t_) do { \
    uint32_t db_ = sbase + ((t_) % 3) * STAGE_B; \
    size_t go_ = (size_t)(t_) * 128; \
    _Pragma("unroll") \
    for (int b_ = 0; b_ < 2; b_++) { \
        const char* g_ = gsrc[b_]; \
        uint32_t d_ = db_ + b_ * (128 * ROWB); \
        _Pragma("unroll") \
        for (int i_ = 0; i_ < 4; i_++) { \
            int idx_ = i_ * 256 + tid; \
            int r_ = idx_ >> 3, c_ = (idx_ & 7) * 16; \
            asm volatile("cp.async.cg.shared.global [%0], [%1], 16;" \
                :: "r"(d_ + r_ * ROWB + c_), "l"(g_ + (size_t)r_ * rs + go_ + c_) : "memory"); \
        } \
    } \
    asm volatile("cp.async.commit_group;" ::: "memory"); \
} while (0)

    const int T = K >> 6;
    LOADT(0);
    if (T > 1) LOADT(1);

    for (int t = 0; t < T; t++) {
        if (t + 1 < T) asm volatile("cp.async.wait_group 1;" ::: "memory");
        else           asm volatile("cp.async.wait_group 0;" ::: "memory");
        __syncthreads();
        const uint32_t sb = sbase + (t % 3) * STAGE_B;

#pragma unroll
        for (int ks = 0; ks < 4; ks++) {
            const int k0 = ks * 16;
            uint32_t bf[4][2];
#pragma unroll
            for (int pr = 0; pr < 2; pr++) {
                int trow = wn * 32 + pr * 16 + ((lane >> 4) & 1) * 8 + (lane & 7);
                int tcol = k0 + ((lane >> 3) & 1) * 8;
                uint32_t ab = sb + 128 * ROWB + trow * ROWB + tcol * 2;
                LDMX4(bf[2*pr][0], bf[2*pr][1], bf[2*pr+1][0], bf[2*pr+1][1], ab);
            }
#pragma unroll
            for (int i = 0; i < 4; i++) {
                int arow = wm * 64 + i * 16 + (lane & 7) + ((lane >> 3) & 1) * 8;
                int acol = k0 + ((lane >> 4) & 1) * 8;
                uint32_t aa = sb + arow * ROWB + acol * 2;
                uint32_t a4[4];
                LDMX4(a4[0], a4[1], a4[2], a4[3], aa);
#pragma unroll
                for (int j = 0; j < 4; j++) mma16816(acc[i][j], a4, bf[j]);
            }
        }
        if (t + 2 < T) LOADT(t + 2);
    }

    // EPI==5: per-row stat reduction buffer in (now-free) pipeline smem
    float2* sstat = (float2*)dyn;
    if (EPI == 5) {
        __syncthreads();                 // everyone done reading stage smem
        if (tid < 128) sstat[tid] = make_float2(0.f, 0.f);
        __syncthreads();
    }

    const float att_scale = 1.0f / sqrtf(64.0f + 1e-8f);

#pragma unroll
    for (int i = 0; i < 4; i++) {
        int row0 = bm * 128 + wm * 64 + i * 16 + (lane >> 2);
#pragma unroll
        for (int half_ = 0; half_ < 2; half_++) {
            int row = row0 + half_ * 8;
            float mu = 0.f, inv = 1.f;
            if (EPI == 3 || EPI == 4) {
                float2 p0 = stats_in[row];
                float2 p1 = stats_in[M_TOK + row];
                float2 p2 = stats_in[2 * M_TOK + row];
                float sx = p0.x + p1.x + p2.x;
                float sq = p0.y + p1.y + p2.y;
                mu = sx * (1.0f / 384.0f);
                inv = rsqrtf(sq * (1.0f / 384.0f) - mu * mu + 1e-5f);
            }
            float rsum = 0.f, rsq = 0.f;
#pragma unroll
            for (int j = 0; j < 4; j++) {
                int col = bn * 128 + wn * 32 + j * 8 + (lane & 3) * 2;
                float a0 = acc[i][j][half_ * 2 + 0];
                float a1 = acc[i][j][half_ * 2 + 1];
                if (EPI == 0) {
                    size_t off = (size_t)row * N + col;
                    *(float2*)(C + off) = make_float2(a0 + bias[col], a1 + bias[col + 1]);
                } else if (EPI == 4) {
                    float v0 = inv * (a0 - mu * uvec[col])     + bias[col];
                    float v1 = inv * (a1 - mu * uvec[col + 1]) + bias[col + 1];
                    int kind = col / 384;
                    int hh = (col % 384) >> 6;
                    int dd = col & 63;
                    int bb = row / NTOK, tt = row % NTOK;
                    size_t o3 = ((size_t)(bb * NHEAD + hh) * NTOK + tt) * 64 + dd;
                    if (kind == 0)
                        *(__half2*)(Qo + o3) = __floats2half2_rn(v0 * att_scale, v1 * att_scale);
                    else if (kind == 1)
                        *(__half2*)(Ko + o3) = __floats2half2_rn(v0, v1);
                    else
                        *(__half2*)(Vo + o3) = __floats2half2_rn(v0, v1);
                } else if (EPI == 3) {
                    float v0 = gelu_tanh(inv * (a0 - mu * uvec[col])     + bias[col]);
                    float v1 = gelu_tanh(inv * (a1 - mu * uvec[col + 1]) + bias[col + 1]);
                    size_t off = (size_t)row * N + col;
                    *(__half2*)((char*)Ch + off * 2) = __floats2half2_rn(v0, v1);
                } else { // EPI == 5
                    size_t off = (size_t)row * N + col;
                    float2 rr = *(const float2*)(Rres + off);
                    float v0 = a0 + bias[col]     + rr.x;
                    float v1 = a1 + bias[col + 1] + rr.y;
                    *(float2*)(C + off) = make_float2(v0, v1);
                    *(__half2*)((char*)XH + off * 2) = __floats2half2_rn(v0, v1);
                    rsum += v0 + v1;
                    rsq  += v0 * v0 + v1 * v1;
                }
            }
            if (EPI == 5) {
                rsum += __shfl_xor_sync(~0u, rsum, 1); rsum += __shfl_xor_sync(~0u, rsum, 2);
                rsq  += __shfl_xor_sync(~0u, rsq, 1);  rsq  += __shfl_xor_sync(~0u, rsq, 2);
                if ((lane & 3) == 0) {
                    int rl = row - bm * 128;       // 0..127
                    atomicAdd(&sstat[rl].x, rsum);
                    atomicAdd(&sstat[rl].y, rsq);
                }
            }
        }
    }
    if (EPI == 5) {
        __syncthreads();
        if (tid < 128)
            stats_out[bn * M_TOK + bm * 128 + tid] = sstat[tid];
    }
}

// ---------------- weight transpose + fp16, optional g-fold ----
__global__ void wprep(const float* __restrict__ W, const float* __restrict__ g,
                      __half* __restrict__ Wh, int K, int N)
{
    __shared__ float t[32][33];
    const int l = blockIdx.z;
    const size_t lo = (size_t)l * K * N;
    const float* Wp = W + lo;
    const int kt = blockIdx.y * 32, nt = blockIdx.x * 32;
    const int tx = threadIdx.x, ty = threadIdx.y;
#pragma unroll
    for (int i = ty; i < 32; i += 8)
        t[i][tx] = Wp[(size_t)(kt + i) * N + nt + tx];
    __syncthreads();
    float gk = g ? g[l * K + kt + tx] : 1.0f;
#pragma unroll
    for (int i = ty; i < 32; i += 8)
        Wh[lo + (size_t)(nt + i) * K + kt + tx] = __float2half_rn(t[tx][i] * gk);
}

// ---------------- LN-fusion u/c prep ----
__global__ void prep_uc(const float* __restrict__ W, const float* __restrict__ g,
                        const float* __restrict__ b, const float* __restrict__ bias,
                        float* __restrict__ u, float* __restrict__ c, int N)
{
    const int l = blockIdx.y;
    const int n = blockIdx.x * 128 + threadIdx.x;
    const float* Wp = W + (size_t)l * 384 * N + n;
    const float* gp = g + l * 384;
    const float* bp = b + l * 384;
    float su = 0.f, sc = 0.f;
    for (int k = 0; k < 384; k++) {
        float w = Wp[(size_t)k * N];
        su = fmaf(gp[k], w, su);
        sc = fmaf(bp[k], w, sc);
    }
    u[l * N + n] = su;
    c[l * N + n] = sc + bias[l * N + n];
}

__global__ void lnf_kernel(const float* __restrict__ x, const float* __restrict__ w,
                           const float* __restrict__ b, float* __restrict__ out)
{
    size_t bi = blockIdx.x;
    const float* xr = x + (bi * NTOK + (NTOK - 1)) * D_EMB;
    int tid = threadIdx.x;
    float v0 = xr[tid], v1 = xr[tid + 128], v2 = xr[tid + 256];
    float s = v0 + v1 + v2, sq = v0*v0 + v1*v1 + v2*v2;
#pragma unroll
    for (int o = 16; o; o >>= 1) {
        s  += __shfl_xor_sync(~0u, s,  o);
        sq += __shfl_xor_sync(~0u, sq, o);
    }
    __shared__ float ws[4], wq[4], red[2];
    int warp = tid >> 5, lane = tid & 31;
    if (!lane) { ws[warp] = s; wq[warp] = sq; }
    __syncthreads();
    if (tid == 0) {
        float S = ws[0]+ws[1]+ws[2]+ws[3], Q = wq[0]+wq[1]+wq[2]+wq[3];
        float mean = S * (1.0f / 384.0f);
        red[0] = mean;
        red[1] = rsqrtf(Q * (1.0f / 384.0f) - mean * mean + 1e-5f);
    }
    __syncthreads();
    float mean = red[0], inv = red[1];
    out[bi * D_EMB + tid]       = (v0 - mean) * inv * w[tid]       + b[tid];
    out[bi * D_EMB + tid + 128] = (v1 - mean) * inv * w[tid + 128] + b[tid + 128];
    out[bi * D_EMB + tid + 256] = (v2 - mean) * inv * w[tid + 256] + b[tid + 256];
}

// ---------------- Flash attention on HMMA (fp32 softmax) ----------------
// No Q smem (direct gmem A-fragments) -> 88KB smem -> 2 CTAs/SM.
#define KPAD 320
#define KSTR 72
#define VSTR 328
#define ATT_SMEM_HALVES (KPAD*KSTR + 64*VSTR)
#define ATT_SMEM_BYTES  (ATT_SMEM_HALVES * 2)

__global__ void __launch_bounds__(256, 2) attn_mma(
    const __half* __restrict__ Qb, const __half* __restrict__ Kb,
    const __half* __restrict__ Vb, __half* __restrict__ oh)
{
    extern __shared__ __half smh[];
    __half* Ks = smh;
    __half* Vt = smh + KPAD * KSTR;

    const int bh = blockIdx.x;
    const int b = bh / NHEAD, h = bh % NHEAD;
    const int tid = threadIdx.x, warp = tid >> 5, lane = tid & 31;
    const size_t ib = (size_t)bh * NTOK * 64;

    // zero V^T (padding cols must be 0), then fill K and V^T
    for (int i = tid; i < (64 * VSTR) / 8; i += 256)
        ((int4*)Vt)[i] = make_int4(0, 0, 0, 0);
    __syncthreads();
    for (int idx = tid; idx < NTOK * 8; idx += 256) {
        int t = idx >> 3, s = idx & 7;
        ((int4*)(Ks + t * KSTR))[s] = ((const int4*)(Kb + ib + (size_t)t * 64))[s];
    }
    for (int idx = tid; idx < NTOK * 64; idx += 256) {
        int t = idx >> 6, d = idx & 63;
        Vt[d * VSTR + t] = Vb[ib + idx];
    }
    __syncthreads();

    const uint32_t ks0 = smem_u32(Ks), vt0 = smem_u32(Vt);

    for (int tile = warp; tile < 19; tile += 8) {
        // ---- Q fragments straight from gmem (canonical m16n8k16 A layout) ----
        uint32_t qf[4][4];
        {
            int r0g = tile * 16 + (lane >> 2);
            int r1g = r0g + 8;
            if (r0g >= NTOK) r0g = NTOK - 1;
            if (r1g >= NTOK) r1g = NTOK - 1;
            const __half* Q0 = Qb + ib + (size_t)r0g * 64;
            const __half* Q1 = Qb + ib + (size_t)r1g * 64;
            int c0 = (lane & 3) * 2;
#pragma unroll
            for (int ks = 0; ks < 4; ks++) {
                qf[ks][0] = *(const uint32_t*)(Q0 + ks * 16 + c0);
                qf[ks][1] = *(const uint32_t*)(Q1 + ks * 16 + c0);
                qf[ks][2] = *(const uint32_t*)(Q0 + ks * 16 + c0 + 8);
                qf[ks][3] = *(const uint32_t*)(Q1 + ks * 16 + c0 + 8);
            }
        }
        float O[8][4];
#pragma unroll
        for (int j = 0; j < 8; j++)
#pragma unroll
            for (int q = 0; q < 4; q++) O[j][q] = 0.f;
        float mr0 = -1e30f, mr1 = -1e30f, lr0 = 0.f, lr1 = 0.f;

        for (int ch = 0; ch < 5; ch++) {
            float S[8][4];
#pragma unroll
            for (int j = 0; j < 8; j++)
#pragma unroll
                for (int q = 0; q < 4; q++) S[j][q] = 0.f;

#pragma unroll
            for (int ks = 0; ks < 4; ks++) {
#pragma unroll
                for (int kg = 0; kg < 4; kg++) {
                    int trow = ch * 64 + kg * 16 + ((lane >> 4) & 1) * 8 + (lane & 7);
                    int tcol = ks * 16 + ((lane >> 3) & 1) * 8;
                    uint32_t ad = ks0 + (trow * KSTR + tcol) * 2;
                    uint32_t bfr[4];
                    LDMX4(bfr[0], bfr[1], bfr[2], bfr[3], ad);
                    mma16816(S[kg * 2],     qf[ks], bfr);
                    mma16816(S[kg * 2 + 1], qf[ks], bfr + 2);
                }
            }

            float cm0 = -1e30f, cm1 = -1e30f;
#pragma unroll
            for (int j = 0; j < 8; j++) {
                int k0c = ch * 64 + j * 8 + (lane & 3) * 2;
                if (k0c >= NTOK)     { S[j][0] = -1e30f; S[j][2] = -1e30f; }
                if (k0c + 1 >= NTOK) { S[j][1] = -1e30f; S[j][3] = -1e30f; }
                cm0 = fmaxf(cm0, fmaxf(S[j][0], S[j][1]));
                cm1 = fmaxf(cm1, fmaxf(S[j][2], S[j][3]));
            }
            cm0 = fmaxf(cm0, __shfl_xor_sync(~0u, cm0, 1));
            cm0 = fmaxf(cm0, __shfl_xor_sync(~0u, cm0, 2));
            cm1 = fmaxf(cm1, __shfl_xor_sync(~0u, cm1, 1));
            cm1 = fmaxf(cm1, __shfl_xor_sync(~0u, cm1, 2));

            float mn0 = fmaxf(mr0, cm0), mn1 = fmaxf(mr1, cm1);
            float sc0 = __expf(mr0 - mn0), sc1 = __expf(mr1 - mn1);

            float cs0 = 0.f, cs1 = 0.f;
            uint32_t pf[4][4];
#pragma unroll
            for (int j = 0; j < 8; j++) {
                float e0 = __expf(S[j][0] - mn0), e1 = __expf(S[j][1] - mn0);
                float e2 = __expf(S[j][2] - mn1), e3 = __expf(S[j][3] - mn1);
                cs0 += e0 + e1; cs1 += e2 + e3;
                __half2 p01 = __floats2half2_rn(e0, e1);
                __half2 p23 = __floats2half2_rn(e2, e3);
                int jg = j >> 1, sl = (j & 1) * 2;
                pf[jg][sl]     = reinterpret_cast<uint32_t&>(p01);
                pf[jg][sl + 1] = reinterpret_cast<uint32_t&>(p23);
            }
            cs0 += __shfl_xor_sync(~0u, cs0, 1); cs0 += __shfl_xor_sync(~0u, cs0, 2);
            cs1 += __shfl_xor_sync(~0u, cs1, 1); cs1 += __shfl_xor_sync(~0u, cs1, 2);
            lr0 = lr0 * sc0 + cs0; lr1 = lr1 * sc1 + cs1;
            mr0 = mn0; mr1 = mn1;
#pragma unroll
            for (int j = 0; j < 8; j++) {
                O[j][0] *= sc0; O[j][1] *= sc0; O[j][2] *= sc1; O[j][3] *= sc1;
            }

#pragma unroll
            for (int jg = 0; jg < 4; jg++) {
#pragma unroll
                for (int dg = 0; dg < 4; dg++) {
                    int trow = dg * 16 + ((lane >> 4) & 1) * 8 + (lane & 7);
                    int tcol = ch * 64 + jg * 16 + ((lane >> 3) & 1) * 8;
                    uint32_t ad = vt0 + (trow * VSTR + tcol) * 2;
                    uint32_t bfr[4];
                    LDMX4(bfr[0], bfr[1], bfr[2], bfr[3], ad);
                    mma16816(O[dg * 2],     pf[jg], bfr);
                    mma16816(O[dg * 2 + 1], pf[jg], bfr + 2);
                }
            }
        }

        float inv0 = 1.0f / lr0, inv1 = 1.0f / lr1;
        int r0 = tile * 16 + (lane >> 2), r1 = r0 + 8;
#pragma unroll
        for (int j = 0; j < 8; j++) {
            int d = j * 8 + (lane & 3) * 2;
            if (r0 < NTOK) {
                __half2 hv = (r0 == NTOK - 1)
                    ? *(const __half2*)(Vb + ib + (size_t)(NTOK - 1) * 64 + d)
                    : __floats2half2_rn(O[j][0] * inv0, O[j][1] * inv0);
                *(__half2*)(oh + ((size_t)b * NTOK + r0) * D_EMB + h * 64 + d) = hv;
            }
            if (r1 < NTOK) {
                __half2 hv = (r1 == NTOK - 1)
                    ? *(const __half2*)(Vb + ib + (size_t)(NTOK - 1) * 64 + d)
                    : __floats2half2_rn(O[j][2] * inv1, O[j][3] * inv1);
                *(__half2*)(oh + ((size_t)b * NTOK + r1) * D_EMB + h * 64 + d) = hv;
            }
        }
    }
}

// ---------------- tokenizers ----------------
__global__ void st_kernel(const float* __restrict__ as, const float* __restrict__ w1,
                          const float* __restrict__ b1, const float* __restrict__ w2,
                          const float* __restrict__ b2, float* __restrict__ st)
{
    __shared__ float h1[32];
    int bt = blockIdx.x;
    int tid = threadIdx.x;
    float s0 = as[bt * 2], s1 = as[bt * 2 + 1];
    if (tid < 32) {
        float v = b1[tid] + s0 * w1[tid] + s1 * w1[32 + tid];
        h1[tid] = v > 0.f ? v : 0.f;
    }
    __syncthreads();
    float acc = b2[tid];
#pragma unroll
    for (int k = 0; k < 32; k++) acc = fmaf(h1[k], w2[k * 384 + tid], acc);
    st[(size_t)bt * 384 + tid] = acc;
}

__global__ void im2col_kernel(const float* __restrict__ img, __half* __restrict__ ph)
{
    int idx = blockIdx.x * 256 + threadIdx.x;
    int f = idx % 192;
    int rem = idx / 192;
    int pidx = rem % 144;
    int bt = rem / 144;
    int pr = f / 24, pc = (f % 24) / 3, c = f % 3;
    int hp = pidx / 12, wp = pidx % 12;
    ph[idx] = __float2half_rn(img[(((size_t)bt * 3 + c) * 96 + hp * 8 + pr) * 96 + wp * 8 + pc]);
}

// assemble residual stream + xh + stat partials (block per row, 128 thr)
__global__ void assemble_ln(const float* __restrict__ imgtok, const float* __restrict__ st,
                            const float* __restrict__ readout, const float* __restrict__ pos,
                            const float* __restrict__ img_temb, const float* __restrict__ st_temb,
                            float* __restrict__ x, __half* __restrict__ xh,
                            float2* __restrict__ stats)
{
    size_t row = blockIdx.x;
    int tok = (int)(row % NTOK);
    int b = (int)(row / NTOK);
    int tid = threadIdx.x;
    float v[3];
#pragma unroll
    for (int q = 0; q < 3; q++) {
        int d = tid + q * 128;
        float vv;
        if (tok == NTOK - 1) {
            vv = readout[d];
        } else {
            int t = tok / 145, r = tok % 145;
            if (r == 0) vv = st[((size_t)(b * 2 + t)) * 384 + d] + st_temb[t * 384 + d];
            else        vv = imgtok[((size_t)(b * 2 + t) * 144 + (r - 1)) * 384 + d] + img_temb[t * 384 + d];
        }
        vv += pos[tok * 384 + d];
        v[q] = vv;
        x[row * D_EMB + d] = vv;
        xh[row * D_EMB + d] = __float2half_rn(vv);
    }
    float s = v[0] + v[1] + v[2], sq = v[0]*v[0] + v[1]*v[1] + v[2]*v[2];
#pragma unroll
    for (int o = 16; o; o >>= 1) {
        s  += __shfl_xor_sync(~0u, s,  o);
        sq += __shfl_xor_sync(~0u, sq, o);
    }
    __shared__ float ws[4], wq[4];
    int warp = tid >> 5, lane = tid & 31;
    if (!lane) { ws[warp] = s; wq[warp] = sq; }
    __syncthreads();
    if (tid == 0) {
        stats[row] = make_float2(ws[0]+ws[1]+ws[2]+ws[3], wq[0]+wq[1]+wq[2]+wq[3]);
        stats[M_TOK + row] = make_float2(0.f, 0.f);
        stats[2 * M_TOK + row] = make_float2(0.f, 0.f);
    }
}

// ---------------- launch ----------------
extern "C" void kernel_launch(void* const* d_in, const int* in_sizes, int n_in,
                              void* d_out, int out_size)
{
    const float* images      = (const float*)d_in[0];
    const float* agent_state = (const float*)d_in[1];
    const float* img_proj_w  = (const float*)d_in[2];
    const float* img_proj_b  = (const float*)d_in[3];
    const float* img_temb    = (const float*)d_in[4];
    const float* st_w1       = (const float*)d_in[5];
    const float* st_b1       = (const float*)d_in[6];
    const float* st_w2       = (const float*)d_in[7];
    const float* st_b2       = (const float*)d_in[8];
    const float* st_temb     = (const float*)d_in[9];
    const float* readout     = (const float*)d_in[10];
    const float* pos         = (const float*)d_in[11];
    const float* ln1_w       = (const float*)d_in[12];
    const float* ln1_b       = (const float*)d_in[13];
    const float* attn_w      = (const float*)d_in[14];
    const float* attn_b      = (const float*)d_in[15];
    const float* proj_w      = (const float*)d_in[16];
    const float* proj_b      = (const float*)d_in[17];
    const float* ln2_w       = (const float*)d_in[18];
    const float* ln2_b       = (const float*)d_in[19];
    const float* fc_w        = (const float*)d_in[20];
    const float* fc_b        = (const float*)d_in[21];
    const float* fc2_w       = (const float*)d_in[22];
    const float* fc2_b       = (const float*)d_in[23];
    const float* lnf_w       = (const float*)d_in[24];
    const float* lnf_b       = (const float*)d_in[25];
    float* out = (float*)d_out;

    float *x, *att, *st, *uq, *cq, *u1, *c1;
    float2 *sA, *sB;
    __half *xh, *ah, *bhp, *ph, *qb, *kb, *vb, *wq, *wp, *w1, *w2, *wi;
    cudaGetSymbolAddress((void**)&x,   g_x);
    cudaGetSymbolAddress((void**)&att, g_att);
    cudaGetSymbolAddress((void**)&st,  g_st);
    cudaGetSymbolAddress((void**)&sA,  g_sA);
    cudaGetSymbolAddress((void**)&sB,  g_sB);
    cudaGetSymbolAddress((void**)&xh,  g_xh);
    cudaGetSymbolAddress((void**)&ah,  g_ah);
    cudaGetSymbolAddress((void**)&bhp, g_bh);
    cudaGetSymbolAddress((void**)&ph,  g_ph);
    cudaGetSymbolAddress((void**)&qb,  g_q);
    cudaGetSymbolAddress((void**)&kb,  g_k);
    cudaGetSymbolAddress((void**)&vb,  g_v);
    cudaGetSymbolAddress((void**)&wq,  g_wq);
    cudaGetSymbolAddress((void**)&wp,  g_wp);
    cudaGetSymbolAddress((void**)&w1,  g_w1);
    cudaGetSymbolAddress((void**)&w2,  g_w2);
    cudaGetSymbolAddress((void**)&wi,  g_wi);
    cudaGetSymbolAddress((void**)&uq,  g_uq);
    cudaGetSymbolAddress((void**)&cq,  g_cq);
    cudaGetSymbolAddress((void**)&u1,  g_u1);
    cudaGetSymbolAddress((void**)&c1,  g_c1);

    cudaFuncSetAttribute(attn_mma, cudaFuncAttributeMaxDynamicSharedMemorySize, ATT_SMEM_BYTES);
    cudaFuncSetAttribute(gemm_mma<0>, cudaFuncAttributeMaxDynamicSharedMemorySize, GSMEM);
    cudaFuncSetAttribute(gemm_mma<3>, cudaFuncAttributeMaxDynamicSharedMemorySize, GSMEM);
    cudaFuncSetAttribute(gemm_mma<4>, cudaFuncAttributeMaxDynamicSharedMemorySize, GSMEM);
    cudaFuncSetAttribute(gemm_mma<5>, cudaFuncAttributeMaxDynamicSharedMemorySize, GSMEM);

    // ---- weight prep + LN fusion vectors ----
    wprep<<<dim3(1152/32, 384/32, 12), dim3(32, 8)>>>(attn_w, ln1_w, wq, 384, 1152);
    wprep<<<dim3(384/32,  384/32, 12), dim3(32, 8)>>>(proj_w, nullptr, wp, 384, 384);
    wprep<<<dim3(1536/32, 384/32, 12), dim3(32, 8)>>>(fc_w,  ln2_w, w1, 384, 1536);
    wprep<<<dim3(384/32, 1536/32, 12), dim3(32, 8)>>>(fc2_w, nullptr, w2, 1536, 384);
    wprep<<<dim3(384/32,  192/32, 1),  dim3(32, 8)>>>(img_proj_w, nullptr, wi, 192, 384);
    prep_uc<<<dim3(1152/128, 12), 128>>>(attn_w, ln1_w, ln1_b, attn_b, uq, cq, 1152);
    prep_uc<<<dim3(1536/128, 12), 128>>>(fc_w,  ln2_w, ln2_b, fc_b,  u1, c1, 1536);

    // ---- tokenizers ----
    st_kernel<<<BATCH * OBS_H, 384>>>(agent_state, st_w1, st_b1, st_w2, st_b2, st);
    im2col_kernel<<<(M_PATCH * PK) / 256, 256>>>(images, ph);
    gemm_mma<0><<<dim3(3, M_PATCH / 128), 256, GSMEM>>>(
        ph, wi, img_proj_b, nullptr, att, nullptr, nullptr, nullptr, nullptr,
        nullptr, nullptr, nullptr, nullptr, 384, PK);
    assemble_ln<<<M_TOK, 128>>>(att, st, readout, pos, img_temb, st_temb, x, xh, sA);

    // ---- transformer layers ----
    for (int l = 0; l < NLAYER; l++) {
        gemm_mma<4><<<dim3(9, NTOK), 256, GSMEM>>>(
            xh, wq + (size_t)l * 1152 * 384, cq + l * 1152, nullptr,
            nullptr, nullptr, qb, kb, vb, sA, nullptr, uq + l * 1152, nullptr, 1152, 384);
        attn_mma<<<BATCH * NHEAD, 256, ATT_SMEM_BYTES>>>(qb, kb, vb, ah);
        gemm_mma<5><<<dim3(3, NTOK), 256, GSMEM>>>(
            ah, wp + (size_t)l * 384 * 384, proj_b + l * 384, x,
            x, nullptr, nullptr, nullptr, nullptr, nullptr, sB, nullptr, xh, 384, 384);
        gemm_mma<3><<<dim3(12, NTOK), 256, GSMEM>>>(
            xh, w1 + (size_t)l * 1536 * 384, c1 + l * 1536, nullptr,
            nullptr, bhp, nullptr, nullptr, nullptr, sB, nullptr, u1 + l * 1536, nullptr, 1536, 384);
        gemm_mma<5><<<dim3(3, NTOK), 256, GSMEM>>>(
            bhp, w2 + (size_t)l * 384 * 1536, fc2_b + l * 384, x,
            x, nullptr, nullptr, nullptr, nullptr, nullptr, sA, nullptr, xh, 384, 1536);
    }

    lnf_kernel<<<BATCH, 128>>>(x, lnf_w, lnf_b, out);
}

// round 12
// speedup vs baseline: 7.4360x; 1.0151x over previous
#include <cuda_runtime.h>
#include <cuda_fp16.h>
#include <math.h>
#include <stdint.h>

// ---------------- problem constants ----------------
#define BATCH   128
#define OBS_H   2
#define NTOK    291
#define M_TOK   (BATCH*NTOK)   // 37248 = 291*128
#define D_EMB   384
#define NHEAD   6
#define NLAYER  12
#define N_IMG   144
#define PK      192
#define M_PATCH (BATCH*OBS_H*N_IMG)

// ---------------- scratch ----------------
__device__ float g_x  [M_TOK * D_EMB];
__device__ float g_att[M_PATCH * D_EMB];
__device__ float g_st [BATCH * OBS_H * D_EMB];
__device__ float2 g_sA[3 * M_TOK];             // row-stat partials (x)
__device__ float2 g_sB[3 * M_TOK];             // row-stat partials (after proj)
__device__ __half g_xh[M_TOK*384];
__device__ __half g_ah[M_TOK*384];
__device__ __half g_bh[M_TOK*1536];
__device__ __half g_ph[M_PATCH*192];
__device__ __half g_q [BATCH*NHEAD*NTOK*64];
__device__ __half g_k [BATCH*NHEAD*NTOK*64];
__device__ __half g_v [BATCH*NHEAD*NTOK*64];
// transposed weights [N,K] fp16 (qkv/fc1 have ln-g folded in)
__device__ __half g_wq[12*1152*384];
__device__ __half g_wp[12*384*384];
__device__ __half g_w1[12*1536*384];
__device__ __half g_w2[12*384*1536];
__device__ __half g_wi[384*192];
// LN-fusion vectors: u = g@W, c = b@W + bias
__device__ float g_uq[12*1152], g_cq[12*1152];
__device__ float g_u1[12*1536], g_c1[12*1536];

__device__ __forceinline__ float gelu_tanh(float v) {
    const float c = 0.7978845608028654f;
    float u = c * (v + 0.044715f * v * v * v);
    return 0.5f * v * (1.0f + tanhf(u));
}

__device__ __forceinline__ uint32_t smem_u32(const void* p) {
    uint32_t a;
    asm("{ .reg .u64 t; cvta.to.shared.u64 t, %1; cvt.u32.u64 %0, t; }" : "=r"(a) : "l"(p));
    return a;
}

__device__ __forceinline__ void mma16816(float c[4], const uint32_t a[4], const uint32_t b[2]) {
    asm volatile(
        "mma.sync.aligned.m16n8k16.row.col.f32.f16.f16.f32 "
        "{%0,%1,%2,%3}, {%4,%5,%6,%7}, {%8,%9}, {%0,%1,%2,%3};\n"
        : "+f"(c[0]), "+f"(c[1]), "+f"(c[2]), "+f"(c[3])
        : "r"(a[0]), "r"(a[1]), "r"(a[2]), "r"(a[3]), "r"(b[0]), "r"(b[1]));
}
#define LDMX4(r0, r1, r2, r3, addr) \
    asm volatile("ldmatrix.sync.aligned.m8n8.x4.shared.b16 {%0,%1,%2,%3}, [%4];" \
        : "=r"(r0), "=r"(r1), "=r"(r2), "=r"(r3) : "r"(addr))
#define LDMX4T(r0, r1, r2, r3, addr) \
    asm volatile("ldmatrix.sync.aligned.m8n8.x4.trans.shared.b16 {%0,%1,%2,%3}, [%4];" \
        : "=r"(r0), "=r"(r1), "=r"(r2), "=r"(r3) : "r"(addr))

// =======================================================================
// fp16 HMMA GEMM. BK=64, 3-stage cp.async pipeline, ONE sync per 64-k-tile.
// smem stage: A[128][72h] + B[128][72h], 144B rows (conflict-free), 36.9KB.
// EPI 0: +bias -> f32 C
// EPI 4: LN-fused -> scatter q/k/v fp16           (reads 3 stat partials)
// EPI 3: LN-fused + gelu -> fp16 Ch               (reads 3 stat partials)
// EPI 5: +bias+res -> f32 C, fp16 XH, stat partial (smem-reduced across warps)
// =======================================================================
#define ROWB      144
#define STAGE_B   (2*128*ROWB)        // 36864
#define GSMEM     (3*STAGE_B)         // 110592

template <int EPI>
__global__ void __launch_bounds__(256, 2) gemm_mma(
    const __half* __restrict__ A, const __half* __restrict__ B,
    const float* __restrict__ bias, const float* __restrict__ Rres,
    float* __restrict__ C, __half* __restrict__ Ch,
    __half* __restrict__ Qo, __half* __restrict__ Ko, __half* __restrict__ Vo,
    const float2* __restrict__ stats_in, float2* __restrict__ stats_out,
    const float* __restrict__ uvec, __half* __restrict__ XH,
    int N, int K)
{
    extern __shared__ __align__(16) char dyn[];
    const uint32_t sbase = smem_u32(dyn);
    const int tid = threadIdx.x, lane = tid & 31, warp = tid >> 5;
    const int wm = warp >> 2, wn = warp & 3;
    const int bn = blockIdx.x, bm = blockIdx.y;

    float acc[4][4][4];
#pragma unroll
    for (int i = 0; i < 4; i++)
#pragma unroll
        for (int j = 0; j < 4; j++)
#pragma unroll
            for (int q = 0; q < 4; q++) acc[i][j][q] = 0.f;

    const char* gsrc[2] = {
        (const char*)(A + (size_t)bm * 128 * K),
        (const char*)(B + (size_t)bn * 128 * K) };
    const size_t rs = (size_t)K * 2;

// 64-k tile: per operand 128 rows x 128B (8 chunks of 16B) = 1024 chunks
#define LOADT(t_) do { \
    uint32_t db_ = sbase + ((t_) % 3) * STAGE_B; \
    size_t go_ = (size_t)(t_) * 128; \
    _Pragma("unroll") \
    for (int b_ = 0; b_ < 2; b_++) { \
        const char* g_ = gsrc[b_]; \
        uint32_t d_ = db_ + b_ * (128 * ROWB); \
        _Pragma("unroll") \
        for (int i_ = 0; i_ < 4; i_++) { \
            int idx_ = i_ * 256 + tid; \
            int r_ = idx_ >> 3, c_ = (idx_ & 7) * 16; \
            asm volatile("cp.async.cg.shared.global [%0], [%1], 16;" \
                :: "r"(d_ + r_ * ROWB + c_), "l"(g_ + (size_t)r_ * rs + go_ + c_) : "memory"); \
        } \
    } \
    asm volatile("cp.async.commit_group;" ::: "memory"); \
} while (0)

    const int T = K >> 6;
    LOADT(0);
    if (T > 1) LOADT(1);

    for (int t = 0; t < T; t++) {
        if (t + 1 < T) asm volatile("cp.async.wait_group 1;" ::: "memory");
        else           asm volatile("cp.async.wait_group 0;" ::: "memory");
        __syncthreads();
        // issue next-next tile loads FIRST so cp.async overlaps the mma burst
        if (t + 2 < T) LOADT(t + 2);
        const uint32_t sb = sbase + (t % 3) * STAGE_B;

#pragma unroll
        for (int ks = 0; ks < 4; ks++) {
            const int k0 = ks * 16;
            uint32_t bf[4][2];
#pragma unroll
            for (int pr = 0; pr < 2; pr++) {
                int trow = wn * 32 + pr * 16 + ((lane >> 4) & 1) * 8 + (lane & 7);
                int tcol = k0 + ((lane >> 3) & 1) * 8;
                uint32_t ab = sb + 128 * ROWB + trow * ROWB + tcol * 2;
                LDMX4(bf[2*pr][0], bf[2*pr][1], bf[2*pr+1][0], bf[2*pr+1][1], ab);
            }
#pragma unroll
            for (int i = 0; i < 4; i++) {
                int arow = wm * 64 + i * 16 + (lane & 7) + ((lane >> 3) & 1) * 8;
                int acol = k0 + ((lane >> 4) & 1) * 8;
                uint32_t aa = sb + arow * ROWB + acol * 2;
                uint32_t a4[4];
                LDMX4(a4[0], a4[1], a4[2], a4[3], aa);
#pragma unroll
                for (int j = 0; j < 4; j++) mma16816(acc[i][j], a4, bf[j]);
            }
        }
    }

    // EPI==5: per-row stat reduction buffer in (now-free) pipeline smem
    float2* sstat = (float2*)dyn;
    if (EPI == 5) {
        __syncthreads();                 // everyone done reading stage smem
        if (tid < 128) sstat[tid] = make_float2(0.f, 0.f);
        __syncthreads();
    }

    const float att_scale = 1.0f / sqrtf(64.0f + 1e-8f);

#pragma unroll
    for (int i = 0; i < 4; i++) {
        int row0 = bm * 128 + wm * 64 + i * 16 + (lane >> 2);
#pragma unroll
        for (int half_ = 0; half_ < 2; half_++) {
            int row = row0 + half_ * 8;
            float mu = 0.f, inv = 1.f;
            if (EPI == 3 || EPI == 4) {
                float2 p0 = stats_in[row];
                float2 p1 = stats_in[M_TOK + row];
                float2 p2 = stats_in[2 * M_TOK + row];
                float sx = p0.x + p1.x + p2.x;
                float sq = p0.y + p1.y + p2.y;
                mu = sx * (1.0f / 384.0f);
                inv = rsqrtf(sq * (1.0f / 384.0f) - mu * mu + 1e-5f);
            }
            float rsum = 0.f, rsq = 0.f;
#pragma unroll
            for (int j = 0; j < 4; j++) {
                int col = bn * 128 + wn * 32 + j * 8 + (lane & 3) * 2;
                float a0 = acc[i][j][half_ * 2 + 0];
                float a1 = acc[i][j][half_ * 2 + 1];
                if (EPI == 0) {
                    size_t off = (size_t)row * N + col;
                    *(float2*)(C + off) = make_float2(a0 + bias[col], a1 + bias[col + 1]);
                } else if (EPI == 4) {
                    float v0 = inv * (a0 - mu * uvec[col])     + bias[col];
                    float v1 = inv * (a1 - mu * uvec[col + 1]) + bias[col + 1];
                    int kind = col / 384;
                    int hh = (col % 384) >> 6;
                    int dd = col & 63;
                    int bb = row / NTOK, tt = row % NTOK;
                    size_t o3 = ((size_t)(bb * NHEAD + hh) * NTOK + tt) * 64 + dd;
                    if (kind == 0)
                        *(__half2*)(Qo + o3) = __floats2half2_rn(v0 * att_scale, v1 * att_scale);
                    else if (kind == 1)
                        *(__half2*)(Ko + o3) = __floats2half2_rn(v0, v1);
                    else
                        *(__half2*)(Vo + o3) = __floats2half2_rn(v0, v1);
                } else if (EPI == 3) {
                    float v0 = gelu_tanh(inv * (a0 - mu * uvec[col])     + bias[col]);
                    float v1 = gelu_tanh(inv * (a1 - mu * uvec[col + 1]) + bias[col + 1]);
                    size_t off = (size_t)row * N + col;
                    *(__half2*)((char*)Ch + off * 2) = __floats2half2_rn(v0, v1);
                } else { // EPI == 5
                    size_t off = (size_t)row * N + col;
                    float2 rr = *(const float2*)(Rres + off);
                    float v0 = a0 + bias[col]     + rr.x;
                    float v1 = a1 + bias[col + 1] + rr.y;
                    *(float2*)(C + off) = make_float2(v0, v1);
                    *(__half2*)((char*)XH + off * 2) = __floats2half2_rn(v0, v1);
                    rsum += v0 + v1;
                    rsq  += v0 * v0 + v1 * v1;
                }
            }
            if (EPI == 5) {
                rsum += __shfl_xor_sync(~0u, rsum, 1); rsum += __shfl_xor_sync(~0u, rsum, 2);
                rsq  += __shfl_xor_sync(~0u, rsq, 1);  rsq  += __shfl_xor_sync(~0u, rsq, 2);
                if ((lane & 3) == 0) {
                    int rl = row - bm * 128;       // 0..127
                    atomicAdd(&sstat[rl].x, rsum);
                    atomicAdd(&sstat[rl].y, rsq);
                }
            }
        }
    }
    if (EPI == 5) {
        __syncthreads();
        if (tid < 128)
            stats_out[bn * M_TOK + bm * 128 + tid] = sstat[tid];
    }
}

// ---------------- weight transpose + fp16, optional g-fold ----
__global__ void wprep(const float* __restrict__ W, const float* __restrict__ g,
                      __half* __restrict__ Wh, int K, int N)
{
    __shared__ float t[32][33];
    const int l = blockIdx.z;
    const size_t lo = (size_t)l * K * N;
    const float* Wp = W + lo;
    const int kt = blockIdx.y * 32, nt = blockIdx.x * 32;
    const int tx = threadIdx.x, ty = threadIdx.y;
#pragma unroll
    for (int i = ty; i < 32; i += 8)
        t[i][tx] = Wp[(size_t)(kt + i) * N + nt + tx];
    __syncthreads();
    float gk = g ? g[l * K + kt + tx] : 1.0f;
#pragma unroll
    for (int i = ty; i < 32; i += 8)
        Wh[lo + (size_t)(nt + i) * K + kt + tx] = __float2half_rn(t[tx][i] * gk);
}

// ---------------- LN-fusion u/c prep ----
__global__ void prep_uc(const float* __restrict__ W, const float* __restrict__ g,
                        const float* __restrict__ b, const float* __restrict__ bias,
                        float* __restrict__ u, float* __restrict__ c, int N)
{
    const int l = blockIdx.y;
    const int n = blockIdx.x * 128 + threadIdx.x;
    const float* Wp = W + (size_t)l * 384 * N + n;
    const float* gp = g + l * 384;
    const float* bp = b + l * 384;
    float su = 0.f, sc = 0.f;
    for (int k = 0; k < 384; k++) {
        float w = Wp[(size_t)k * N];
        su = fmaf(gp[k], w, su);
        sc = fmaf(bp[k], w, sc);
    }
    u[l * N + n] = su;
    c[l * N + n] = sc + bias[l * N + n];
}

__global__ void lnf_kernel(const float* __restrict__ x, const float* __restrict__ w,
                           const float* __restrict__ b, float* __restrict__ out)
{
    size_t bi = blockIdx.x;
    const float* xr = x + (bi * NTOK + (NTOK - 1)) * D_EMB;
    int tid = threadIdx.x;
    float v0 = xr[tid], v1 = xr[tid + 128], v2 = xr[tid + 256];
    float s = v0 + v1 + v2, sq = v0*v0 + v1*v1 + v2*v2;
#pragma unroll
    for (int o = 16; o; o >>= 1) {
        s  += __shfl_xor_sync(~0u, s,  o);
        sq += __shfl_xor_sync(~0u, sq, o);
    }
    __shared__ float ws[4], wq[4], red[2];
    int warp = tid >> 5, lane = tid & 31;
    if (!lane) { ws[warp] = s; wq[warp] = sq; }
    __syncthreads();
    if (tid == 0) {
        float S = ws[0]+ws[1]+ws[2]+ws[3], Q = wq[0]+wq[1]+wq[2]+wq[3];
        float mean = S * (1.0f / 384.0f);
        red[0] = mean;
        red[1] = rsqrtf(Q * (1.0f / 384.0f) - mean * mean + 1e-5f);
    }
    __syncthreads();
    float mean = red[0], inv = red[1];
    out[bi * D_EMB + tid]       = (v0 - mean) * inv * w[tid]       + b[tid];
    out[bi * D_EMB + tid + 128] = (v1 - mean) * inv * w[tid + 128] + b[tid + 128];
    out[bi * D_EMB + tid + 256] = (v2 - mean) * inv * w[tid + 256] + b[tid + 256];
}

// ---------------- Flash attention on HMMA (fp32 softmax) ----------------
// No Q smem (gmem A-fragments). K and V both row-major [320][72h];
// V fragments fetched via ldmatrix.trans (no smem transpose pass).
#define KPAD 320
#define KSTR 72
#define ATT_SMEM_HALVES (2*KPAD*KSTR)
#define ATT_SMEM_BYTES  (ATT_SMEM_HALVES * 2)    // 92160

__global__ void __launch_bounds__(256, 2) attn_mma(
    const __half* __restrict__ Qb, const __half* __restrict__ Kb,
    const __half* __restrict__ Vb, __half* __restrict__ oh)
{
    extern __shared__ __half smh[];
    __half* Ks = smh;
    __half* Vs = smh + KPAD * KSTR;

    const int bh = blockIdx.x;
    const int b = bh / NHEAD, h = bh % NHEAD;
    const int tid = threadIdx.x, warp = tid >> 5, lane = tid & 31;
    const size_t ib = (size_t)bh * NTOK * 64;

    // fill K and V rows 0..290; zero V pad rows 291..319 (NaN*0 hazard in P@V)
    for (int idx = tid; idx < NTOK * 8; idx += 256) {
        int t = idx >> 3, s = idx & 7;
        ((int4*)(Ks + t * KSTR))[s] = ((const int4*)(Kb + ib + (size_t)t * 64))[s];
        ((int4*)(Vs + t * KSTR))[s] = ((const int4*)(Vb + ib + (size_t)t * 64))[s];
    }
    for (int idx = tid; idx < (KPAD - NTOK) * 8; idx += 256) {
        int t = NTOK + (idx >> 3), s = idx & 7;
        ((int4*)(Vs + t * KSTR))[s] = make_int4(0, 0, 0, 0);
    }
    __syncthreads();

    const uint32_t ks0 = smem_u32(Ks), vs0 = smem_u32(Vs);

    for (int tile = warp; tile < 19; tile += 8) {
        // ---- Q fragments straight from gmem (canonical m16n8k16 A layout) ----
        uint32_t qf[4][4];
        {
            int r0g = tile * 16 + (lane >> 2);
            int r1g = r0g + 8;
            if (r0g >= NTOK) r0g = NTOK - 1;
            if (r1g >= NTOK) r1g = NTOK - 1;
            const __half* Q0 = Qb + ib + (size_t)r0g * 64;
            const __half* Q1 = Qb + ib + (size_t)r1g * 64;
            int c0 = (lane & 3) * 2;
#pragma unroll
            for (int ks = 0; ks < 4; ks++) {
                qf[ks][0] = *(const uint32_t*)(Q0 + ks * 16 + c0);
                qf[ks][1] = *(const uint32_t*)(Q1 + ks * 16 + c0);
                qf[ks][2] = *(const uint32_t*)(Q0 + ks * 16 + c0 + 8);
                qf[ks][3] = *(const uint32_t*)(Q1 + ks * 16 + c0 + 8);
            }
        }
        float O[8][4];
#pragma unroll
        for (int j = 0; j < 8; j++)
#pragma unroll
            for (int q = 0; q < 4; q++) O[j][q] = 0.f;
        float mr0 = -1e30f, mr1 = -1e30f, lr0 = 0.f, lr1 = 0.f;

        for (int ch = 0; ch < 5; ch++) {
            float S[8][4];
#pragma unroll
            for (int j = 0; j < 8; j++)
#pragma unroll
                for (int q = 0; q < 4; q++) S[j][q] = 0.f;

#pragma unroll
            for (int ks = 0; ks < 4; ks++) {
#pragma unroll
                for (int kg = 0; kg < 4; kg++) {
                    int trow = ch * 64 + kg * 16 + ((lane >> 4) & 1) * 8 + (lane & 7);
                    int tcol = ks * 16 + ((lane >> 3) & 1) * 8;
                    uint32_t ad = ks0 + (trow * KSTR + tcol) * 2;
                    uint32_t bfr[4];
                    LDMX4(bfr[0], bfr[1], bfr[2], bfr[3], ad);
                    mma16816(S[kg * 2],     qf[ks], bfr);
                    mma16816(S[kg * 2 + 1], qf[ks], bfr + 2);
                }
            }

            float cm0 = -1e30f, cm1 = -1e30f;
#pragma unroll
            for (int j = 0; j < 8; j++) {
                int k0c = ch * 64 + j * 8 + (lane & 3) * 2;
                if (k0c >= NTOK)     { S[j][0] = -1e30f; S[j][2] = -1e30f; }
                if (k0c + 1 >= NTOK) { S[j][1] = -1e30f; S[j][3] = -1e30f; }
                cm0 = fmaxf(cm0, fmaxf(S[j][0], S[j][1]));
                cm1 = fmaxf(cm1, fmaxf(S[j][2], S[j][3]));
            }
            cm0 = fmaxf(cm0, __shfl_xor_sync(~0u, cm0, 1));
            cm0 = fmaxf(cm0, __shfl_xor_sync(~0u, cm0, 2));
            cm1 = fmaxf(cm1, __shfl_xor_sync(~0u, cm1, 1));
            cm1 = fmaxf(cm1, __shfl_xor_sync(~0u, cm1, 2));

            float mn0 = fmaxf(mr0, cm0), mn1 = fmaxf(mr1, cm1);
            float sc0 = __expf(mr0 - mn0), sc1 = __expf(mr1 - mn1);

            float cs0 = 0.f, cs1 = 0.f;
            uint32_t pf[4][4];
#pragma unroll
            for (int j = 0; j < 8; j++) {
                float e0 = __expf(S[j][0] - mn0), e1 = __expf(S[j][1] - mn0);
                float e2 = __expf(S[j][2] - mn1), e3 = __expf(S[j][3] - mn1);
                cs0 += e0 + e1; cs1 += e2 + e3;
                __half2 p01 = __floats2half2_rn(e0, e1);
                __half2 p23 = __floats2half2_rn(e2, e3);
                int jg = j >> 1, sl = (j & 1) * 2;
                pf[jg][sl]     = reinterpret_cast<uint32_t&>(p01);
                pf[jg][sl + 1] = reinterpret_cast<uint32_t&>(p23);
            }
            cs0 += __shfl_xor_sync(~0u, cs0, 1); cs0 += __shfl_xor_sync(~0u, cs0, 2);
            cs1 += __shfl_xor_sync(~0u, cs1, 1); cs1 += __shfl_xor_sync(~0u, cs1, 2);
            lr0 = lr0 * sc0 + cs0; lr1 = lr1 * sc1 + cs1;
            mr0 = mn0; mr1 = mn1;
#pragma unroll
            for (int j = 0; j < 8; j++) {
                O[j][0] *= sc0; O[j][1] *= sc0; O[j][2] *= sc1; O[j][3] *= sc1;
            }

            // ---- O += P @ V : V row-major, B-fragments via ldmatrix.trans ----
#pragma unroll
            for (int jg = 0; jg < 4; jg++) {
#pragma unroll
                for (int dg = 0; dg < 4; dg++) {
                    int trow = ch * 64 + jg * 16 + ((lane >> 3) & 1) * 8 + (lane & 7);
                    int tcol = dg * 16 + ((lane >> 4) & 1) * 8;
                    uint32_t ad = vs0 + (trow * KSTR + tcol) * 2;
                    uint32_t bfr[4];
                    LDMX4T(bfr[0], bfr[1], bfr[2], bfr[3], ad);
                    mma16816(O[dg * 2],     pf[jg], bfr);
                    mma16816(O[dg * 2 + 1], pf[jg], bfr + 2);
                }
            }
        }

        float inv0 = 1.0f / lr0, inv1 = 1.0f / lr1;
        int r0 = tile * 16 + (lane >> 2), r1 = r0 + 8;
#pragma unroll
        for (int j = 0; j < 8; j++) {
            int d = j * 8 + (lane & 3) * 2;
            if (r0 < NTOK) {
                __half2 hv = (r0 == NTOK - 1)
                    ? *(const __half2*)(Vb + ib + (size_t)(NTOK - 1) * 64 + d)
                    : __floats2half2_rn(O[j][0] * inv0, O[j][1] * inv0);
                *(__half2*)(oh + ((size_t)b * NTOK + r0) * D_EMB + h * 64 + d) = hv;
            }
            if (r1 < NTOK) {
                __half2 hv = (r1 == NTOK - 1)
                    ? *(const __half2*)(Vb + ib + (size_t)(NTOK - 1) * 64 + d)
                    : __floats2half2_rn(O[j][2] * inv1, O[j][3] * inv1);
                *(__half2*)(oh + ((size_t)b * NTOK + r1) * D_EMB + h * 64 + d) = hv;
            }
        }
    }
}

// ---------------- tokenizers ----------------
__global__ void st_kernel(const float* __restrict__ as, const float* __restrict__ w1,
                          const float* __restrict__ b1, const float* __restrict__ w2,
                          const float* __restrict__ b2, float* __restrict__ st)
{
    __shared__ float h1[32];
    int bt = blockIdx.x;
    int tid = threadIdx.x;
    float s0 = as[bt * 2], s1 = as[bt * 2 + 1];
    if (tid < 32) {
        float v = b1[tid] + s0 * w1[tid] + s1 * w1[32 + tid];
        h1[tid] = v > 0.f ? v : 0.f;
    }
    __syncthreads();
    float acc = b2[tid];
#pragma unroll
    for (int k = 0; k < 32; k++) acc = fmaf(h1[k], w2[k * 384 + tid], acc);
    st[(size_t)bt * 384 + tid] = acc;
}

__global__ void im2col_kernel(const float* __restrict__ img, __half* __restrict__ ph)
{
    int idx = blockIdx.x * 256 + threadIdx.x;
    int f = idx % 192;
    int rem = idx / 192;
    int pidx = rem % 144;
    int bt = rem / 144;
    int pr = f / 24, pc = (f % 24) / 3, c = f % 3;
    int hp = pidx / 12, wp = pidx % 12;
    ph[idx] = __float2half_rn(img[(((size_t)bt * 3 + c) * 96 + hp * 8 + pr) * 96 + wp * 8 + pc]);
}

// assemble residual stream + xh + stat partials (block per row, 128 thr)
__global__ void assemble_ln(const float* __restrict__ imgtok, const float* __restrict__ st,
                            const float* __restrict__ readout, const float* __restrict__ pos,
                            const float* __restrict__ img_temb, const float* __restrict__ st_temb,
                            float* __restrict__ x, __half* __restrict__ xh,
                            float2* __restrict__ stats)
{
    size_t row = blockIdx.x;
    int tok = (int)(row % NTOK);
    int b = (int)(row / NTOK);
    int tid = threadIdx.x;
    float v[3];
#pragma unroll
    for (int q = 0; q < 3; q++) {
        int d = tid + q * 128;
        float vv;
        if (tok == NTOK - 1) {
            vv = readout[d];
        } else {
            int t = tok / 145, r = tok % 145;
            if (r == 0) vv = st[((size_t)(b * 2 + t)) * 384 + d] + st_temb[t * 384 + d];
            else        vv = imgtok[((size_t)(b * 2 + t) * 144 + (r - 1)) * 384 + d] + img_temb[t * 384 + d];
        }
        vv += pos[tok * 384 + d];
        v[q] = vv;
        x[row * D_EMB + d] = vv;
        xh[row * D_EMB + d] = __float2half_rn(vv);
    }
    float s = v[0] + v[1] + v[2], sq = v[0]*v[0] + v[1]*v[1] + v[2]*v[2];
#pragma unroll
    for (int o = 16; o; o >>= 1) {
        s  += __shfl_xor_sync(~0u, s,  o);
        sq += __shfl_xor_sync(~0u, sq, o);
    }
    __shared__ float ws[4], wq[4];
    int warp = tid >> 5, lane = tid & 31;
    if (!lane) { ws[warp] = s; wq[warp] = sq; }
    __syncthreads();
    if (tid == 0) {
        stats[row] = make_float2(ws[0]+ws[1]+ws[2]+ws[3], wq[0]+wq[1]+wq[2]+wq[3]);
        stats[M_TOK + row] = make_float2(0.f, 0.f);
        stats[2 * M_TOK + row] = make_float2(0.f, 0.f);
    }
}

// ---------------- launch ----------------
extern "C" void kernel_launch(void* const* d_in, const int* in_sizes, int n_in,
                              void* d_out, int out_size)
{
    const float* images      = (const float*)d_in[0];
    const float* agent_state = (const float*)d_in[1];
    const float* img_proj_w  = (const float*)d_in[2];
    const float* img_proj_b  = (const float*)d_in[3];
    const float* img_temb    = (const float*)d_in[4];
    const float* st_w1       = (const float*)d_in[5];
    const float* st_b1       = (const float*)d_in[6];
    const float* st_w2       = (const float*)d_in[7];
    const float* st_b2       = (const float*)d_in[8];
    const float* st_temb     = (const float*)d_in[9];
    const float* readout     = (const float*)d_in[10];
    const float* pos         = (const float*)d_in[11];
    const float* ln1_w       = (const float*)d_in[12];
    const float* ln1_b       = (const float*)d_in[13];
    const float* attn_w      = (const float*)d_in[14];
    const float* attn_b      = (const float*)d_in[15];
    const float* proj_w      = (const float*)d_in[16];
    const float* proj_b      = (const float*)d_in[17];
    const float* ln2_w       = (const float*)d_in[18];
    const float* ln2_b       = (const float*)d_in[19];
    const float* fc_w        = (const float*)d_in[20];
    const float* fc_b        = (const float*)d_in[21];
    const float* fc2_w       = (const float*)d_in[22];
    const float* fc2_b       = (const float*)d_in[23];
    const float* lnf_w       = (const float*)d_in[24];
    const float* lnf_b       = (const float*)d_in[25];
    float* out = (float*)d_out;

    float *x, *att, *st, *uq, *cq, *u1, *c1;
    float2 *sA, *sB;
    __half *xh, *ah, *bhp, *ph, *qb, *kb, *vb, *wq, *wp, *w1, *w2, *wi;
    cudaGetSymbolAddress((void**)&x,   g_x);
    cudaGetSymbolAddress((void**)&att, g_att);
    cudaGetSymbolAddress((void**)&st,  g_st);
    cudaGetSymbolAddress((void**)&sA,  g_sA);
    cudaGetSymbolAddress((void**)&sB,  g_sB);
    cudaGetSymbolAddress((void**)&xh,  g_xh);
    cudaGetSymbolAddress((void**)&ah,  g_ah);
    cudaGetSymbolAddress((void**)&bhp, g_bh);
    cudaGetSymbolAddress((void**)&ph,  g_ph);
    cudaGetSymbolAddress((void**)&qb,  g_q);
    cudaGetSymbolAddress((void**)&kb,  g_k);
    cudaGetSymbolAddress((void**)&vb,  g_v);
    cudaGetSymbolAddress((void**)&wq,  g_wq);
    cudaGetSymbolAddress((void**)&wp,  g_wp);
    cudaGetSymbolAddress((void**)&w1,  g_w1);
    cudaGetSymbolAddress((void**)&w2,  g_w2);
    cudaGetSymbolAddress((void**)&wi,  g_wi);
    cudaGetSymbolAddress((void**)&uq,  g_uq);
    cudaGetSymbolAddress((void**)&cq,  g_cq);
    cudaGetSymbolAddress((void**)&u1,  g_u1);
    cudaGetSymbolAddress((void**)&c1,  g_c1);

    cudaFuncSetAttribute(attn_mma, cudaFuncAttributeMaxDynamicSharedMemorySize, ATT_SMEM_BYTES);
    cudaFuncSetAttribute(gemm_mma<0>, cudaFuncAttributeMaxDynamicSharedMemorySize, GSMEM);
    cudaFuncSetAttribute(gemm_mma<3>, cudaFuncAttributeMaxDynamicSharedMemorySize, GSMEM);
    cudaFuncSetAttribute(gemm_mma<4>, cudaFuncAttributeMaxDynamicSharedMemorySize, GSMEM);
    cudaFuncSetAttribute(gemm_mma<5>, cudaFuncAttributeMaxDynamicSharedMemorySize, GSMEM);

    // ---- weight prep + LN fusion vectors ----
    wprep<<<dim3(1152/32, 384/32, 12), dim3(32, 8)>>>(attn_w, ln1_w, wq, 384, 1152);
    wprep<<<dim3(384/32,  384/32, 12), dim3(32, 8)>>>(proj_w, nullptr, wp, 384, 384);
    wprep<<<dim3(1536/32, 384/32, 12), dim3(32, 8)>>>(fc_w,  ln2_w, w1, 384, 1536);
    wprep<<<dim3(384/32, 1536/32, 12), dim3(32, 8)>>>(fc2_w, nullptr, w2, 1536, 384);
    wprep<<<dim3(384/32,  192/32, 1),  dim3(32, 8)>>>(img_proj_w, nullptr, wi, 192, 384);
    prep_uc<<<dim3(1152/128, 12), 128>>>(attn_w, ln1_w, ln1_b, attn_b, uq, cq, 1152);
    prep_uc<<<dim3(1536/128, 12), 128>>>(fc_w,  ln2_w, ln2_b, fc_b,  u1, c1, 1536);

    // ---- tokenizers ----
    st_kernel<<<BATCH * OBS_H, 384>>>(agent_state, st_w1, st_b1, st_w2, st_b2, st);
    im2col_kernel<<<(M_PATCH * PK) / 256, 256>>>(images, ph);
    gemm_mma<0><<<dim3(3, M_PATCH / 128), 256, GSMEM>>>(
        ph, wi, img_proj_b, nullptr, att, nullptr, nullptr, nullptr, nullptr,
        nullptr, nullptr, nullptr, nullptr, 384, PK);
    assemble_ln<<<M_TOK, 128>>>(att, st, readout, pos, img_temb, st_temb, x, xh, sA);

    // ---- transformer layers ----
    for (int l = 0; l < NLAYER; l++) {
        gemm_mma<4><<<dim3(9, NTOK), 256, GSMEM>>>(
            xh, wq + (size_t)l * 1152 * 384, cq + l * 1152, nullptr,
            nullptr, nullptr, qb, kb, vb, sA, nullptr, uq + l * 1152, nullptr, 1152, 384);
        attn_mma<<<BATCH * NHEAD, 256, ATT_SMEM_BYTES>>>(qb, kb, vb, ah);
        gemm_mma<5><<<dim3(3, NTOK), 256, GSMEM>>>(
            ah, wp + (size_t)l * 384 * 384, proj_b + l * 384, x,
            x, nullptr, nullptr, nullptr, nullptr, nullptr, sB, nullptr, xh, 384, 384);
        gemm_mma<3><<<dim3(12, NTOK), 256, GSMEM>>>(
            xh, w1 + (size_t)l * 1536 * 384, c1 + l * 1536, nullptr,
            nullptr, bhp, nullptr, nullptr, nullptr, sB, nullptr, u1 + l * 1536, nullptr, 1536, 384);
        gemm_mma<5><<<dim3(3, NTOK), 256, GSMEM>>>(
            bhp, w2 + (size_t)l * 384 * 1536, fc2_b + l * 384, x,
            x, nullptr, nullptr, nullptr, nullptr, nullptr, sA, nullptr, xh, 384, 1536);
    }

    lnf_kernel<<<BATCH, 128>>>(x, lnf_w, lnf_b, out);
}